// round 2
// baseline (speedup 1.0000x reference)
#include <cuda_runtime.h>
#include <cuda_bf16.h>

// Problem constants
#define BB 4
#define NN 2048
#define EE 1024
#define HH 16
#define DD 64

// Scratch (allocation-free rule: __device__ globals)
__device__ float g_q[BB * HH * NN * DD];     // [B,H,N,D]
__device__ float g_k[BB * HH * NN * DD];
__device__ float g_v[BB * HH * NN * DD];
__device__ float g_att[BB * NN * EE];        // [B,N,E]

typedef unsigned long long u64;

__device__ __forceinline__ float fast_exp2(float x) {
    float y;
    asm("ex2.approx.ftz.f32 %0, %1;" : "=f"(y) : "f"(x));
    return y;
}
__device__ __forceinline__ u64 pack2(float lo, float hi) {
    u64 r; asm("mov.b64 %0, {%1, %2};" : "=l"(r) : "f"(lo), "f"(hi)); return r;
}
__device__ __forceinline__ float2 unpack2(u64 v) {
    float2 f; asm("mov.b64 {%0, %1}, %2;" : "=f"(f.x), "=f"(f.y) : "l"(v)); return f;
}
__device__ __forceinline__ u64 fma2(u64 a, u64 b, u64 c) {
    u64 d; asm("fma.rn.f32x2 %0, %1, %2, %3;" : "=l"(d) : "l"(a), "l"(b), "l"(c)); return d;
}
__device__ __forceinline__ u64 mul2(u64 a, u64 b) {
    u64 d; asm("mul.rn.f32x2 %0, %1, %2;" : "=l"(d) : "l"(a), "l"(b)); return d;
}
__device__ __forceinline__ u64 add2(u64 a, u64 b) {
    u64 d; asm("add.rn.f32x2 %0, %1, %2;" : "=l"(d) : "l"(a), "l"(b)); return d;
}
__device__ __forceinline__ u64 bcast2(float x) { return pack2(x, x); }

// ---------------------------------------------------------------------------
// GEMM 1: QKV projection.  C[m,f] = sum_e X[m,e] * Wqkv[f,e]
// 128x128x16 tile, 256 threads, 8x8 micro-tile, FFMA2 inner loop.
// ---------------------------------------------------------------------------
__global__ __launch_bounds__(256) void qkv_gemm_kernel(
    const float* __restrict__ X, const float* __restrict__ W)
{
    __shared__ float As[16][128];
    __shared__ float Bs[16][128];

    const int tid = threadIdx.x;
    const int tx = tid & 15;
    const int ty = tid >> 4;
    const int mBase = blockIdx.y * 128;
    const int fBase = blockIdx.x * 128;

    const int lr = tid >> 2;
    const int lc = (tid & 3) << 2;

    u64 acc2[8][4];
#pragma unroll
    for (int i = 0; i < 8; ++i)
#pragma unroll
        for (int j = 0; j < 4; ++j) acc2[i][j] = 0ull;

    for (int k0 = 0; k0 < EE; k0 += 16) {
#pragma unroll
        for (int p = 0; p < 2; ++p) {
            const int r = lr + 64 * p;
            float4 a = *(const float4*)&X[(size_t)(mBase + r) * EE + k0 + lc];
            As[lc + 0][r] = a.x; As[lc + 1][r] = a.y;
            As[lc + 2][r] = a.z; As[lc + 3][r] = a.w;
            float4 b = *(const float4*)&W[(size_t)(fBase + r) * EE + k0 + lc];
            Bs[lc + 0][r] = b.x; Bs[lc + 1][r] = b.y;
            Bs[lc + 2][r] = b.z; Bs[lc + 3][r] = b.w;
        }
        __syncthreads();

#pragma unroll
        for (int k = 0; k < 16; ++k) {
            float ar[8];
            *(float4*)&ar[0] = *(const float4*)&As[k][ty * 8];
            *(float4*)&ar[4] = *(const float4*)&As[k][ty * 8 + 4];
            ulonglong2 t0 = *(const ulonglong2*)&Bs[k][tx * 8];
            ulonglong2 t1 = *(const ulonglong2*)&Bs[k][tx * 8 + 4];
            u64 br2[4] = {t0.x, t0.y, t1.x, t1.y};
#pragma unroll
            for (int i = 0; i < 8; ++i) {
                const u64 a2 = bcast2(ar[i]);
#pragma unroll
                for (int j = 0; j < 4; ++j)
                    acc2[i][j] = fma2(a2, br2[j], acc2[i][j]);
            }
        }
        __syncthreads();
    }

    // Epilogue: scatter into q/k/v [B,H,N,D].
    const int f0 = fBase + tx * 8;
    const int which = f0 >> 10;
    const int h = (f0 >> 6) & (HH - 1);
    const int d0 = f0 & (DD - 1);
    float* base = (which == 0) ? g_q : (which == 1) ? g_k : g_v;

#pragma unroll
    for (int i = 0; i < 8; ++i) {
        const int m = mBase + ty * 8 + i;
        const int b = m >> 11;
        const int n = m & (NN - 1);
        float* dst = base + ((size_t)((b * HH + h) * NN + n)) * DD + d0;
        float2 f0v = unpack2(acc2[i][0]);
        float2 f1v = unpack2(acc2[i][1]);
        float2 f2v = unpack2(acc2[i][2]);
        float2 f3v = unpack2(acc2[i][3]);
        float4 w0; w0.x = f0v.x; w0.y = f0v.y; w0.z = f1v.x; w0.w = f1v.y;
        float4 w1; w1.x = f2v.x; w1.y = f2v.y; w1.z = f3v.x; w1.w = f3v.y;
        *(float4*)&dst[0] = w0;
        *(float4*)&dst[4] = w1;
    }
}

// ---------------------------------------------------------------------------
// Flash attention, FFMA2 hot loops. grid = (B*H, N/128), block = 128.
// ---------------------------------------------------------------------------
__global__ __launch_bounds__(128) void attn_kernel()
{
    __shared__ float Ks[64][64];
    __shared__ float Vs[64][64];

    const int bh = blockIdx.x;
    const int qt = blockIdx.y;
    const int t = threadIdx.x;

    const float scale = 0.125f;   // D^-0.5

    const float* Qp = g_q + ((size_t)bh * NN + qt * 128 + t) * DD;
    u64 q2[32];
    {
        const u64 s2 = bcast2(scale);
#pragma unroll
        for (int i = 0; i < 16; ++i) {
            float4 v = *(const float4*)&Qp[i * 4];
            q2[2 * i + 0] = mul2(pack2(v.x, v.y), s2);
            q2[2 * i + 1] = mul2(pack2(v.z, v.w), s2);
        }
    }

    u64 o2[32];
#pragma unroll
    for (int i = 0; i < 32; ++i) o2[i] = 0ull;
    float mx = -3.0e38f;
    float l = 0.f;

    const float* Kbase = g_k + (size_t)bh * NN * DD;
    const float* Vbase = g_v + (size_t)bh * NN * DD;

    const int lrr = t >> 4;
    const int lcc = (t & 15) << 2;

    for (int kt = 0; kt < NN; kt += 64) {
        if (kt) __syncthreads();
#pragma unroll
        for (int p = 0; p < 8; ++p) {
            const int r = lrr + 8 * p;
            *(float4*)&Ks[r][lcc] = *(const float4*)&Kbase[(size_t)(kt + r) * DD + lcc];
            *(float4*)&Vs[r][lcc] = *(const float4*)&Vbase[(size_t)(kt + r) * DD + lcc];
        }
        __syncthreads();

#pragma unroll 1
        for (int sub = 0; sub < 8; ++sub) {
            const int j0 = sub * 8;
            float s[8];
#pragma unroll
            for (int jj = 0; jj < 8; ++jj) {
                const int row = j0 + jj;
                u64 accA = 0ull, accB = 0ull;
#pragma unroll
                for (int d4 = 0; d4 < 16; ++d4) {
                    ulonglong2 kk = *(const ulonglong2*)&Ks[row][d4 * 4];
                    accA = fma2(q2[2 * d4 + 0], kk.x, accA);
                    accB = fma2(q2[2 * d4 + 1], kk.y, accB);
                }
                float2 f = unpack2(add2(accA, accB));
                s[jj] = f.x + f.y;
            }

            // online softmax update over these 8 keys
            float mnew = mx;
#pragma unroll
            for (int jj = 0; jj < 8; ++jj) mnew = fmaxf(mnew, s[jj]);
            const float alpha = fast_exp2((mx - mnew) * 1.44269504f);
            mx = mnew;
            float psum = 0.f;
#pragma unroll
            for (int jj = 0; jj < 8; ++jj) {
                s[jj] = fast_exp2((s[jj] - mnew) * 1.44269504f);
                psum += s[jj];
            }
            l = l * alpha + psum;
            if (alpha != 1.0f) {
                const u64 a2 = bcast2(alpha);
#pragma unroll
                for (int d = 0; d < 32; ++d) o2[d] = mul2(o2[d], a2);
            }

#pragma unroll
            for (int jj = 0; jj < 8; ++jj) {
                const u64 p2 = bcast2(s[jj]);
                const int row = j0 + jj;
#pragma unroll
                for (int d4 = 0; d4 < 16; ++d4) {
                    ulonglong2 vv = *(const ulonglong2*)&Vs[row][d4 * 4];
                    o2[2 * d4 + 0] = fma2(p2, vv.x, o2[2 * d4 + 0]);
                    o2[2 * d4 + 1] = fma2(p2, vv.y, o2[2 * d4 + 1]);
                }
            }
        }
    }

    const float inv = 1.f / l;
    const u64 inv2 = bcast2(inv);
    const int b = bh >> 4;
    const int h = bh & (HH - 1);
    const int n = qt * 128 + t;
    float* dst = g_att + ((size_t)(b * NN + n)) * EE + h * DD;
#pragma unroll
    for (int d4 = 0; d4 < 16; ++d4) {
        float2 a = unpack2(mul2(o2[2 * d4 + 0], inv2));
        float2 c = unpack2(mul2(o2[2 * d4 + 1], inv2));
        float4 w; w.x = a.x; w.y = a.y; w.z = c.x; w.w = c.y;
        *(float4*)&dst[d4 * 4] = w;
    }
}

// ---------------------------------------------------------------------------
// GEMM 2: output projection. out[m,f] = sum_e g_att[m,e] * Wout[f,e]
// ---------------------------------------------------------------------------
__global__ __launch_bounds__(256) void out_gemm_kernel(
    const float* __restrict__ W, float* __restrict__ Cout)
{
    __shared__ float As[16][128];
    __shared__ float Bs[16][128];

    const int tid = threadIdx.x;
    const int tx = tid & 15;
    const int ty = tid >> 4;
    const int mBase = blockIdx.y * 128;
    const int fBase = blockIdx.x * 128;

    const int lr = tid >> 2;
    const int lc = (tid & 3) << 2;

    u64 acc2[8][4];
#pragma unroll
    for (int i = 0; i < 8; ++i)
#pragma unroll
        for (int j = 0; j < 4; ++j) acc2[i][j] = 0ull;

    for (int k0 = 0; k0 < EE; k0 += 16) {
#pragma unroll
        for (int p = 0; p < 2; ++p) {
            const int r = lr + 64 * p;
            float4 a = *(const float4*)&g_att[(size_t)(mBase + r) * EE + k0 + lc];
            As[lc + 0][r] = a.x; As[lc + 1][r] = a.y;
            As[lc + 2][r] = a.z; As[lc + 3][r] = a.w;
            float4 b = *(const float4*)&W[(size_t)(fBase + r) * EE + k0 + lc];
            Bs[lc + 0][r] = b.x; Bs[lc + 1][r] = b.y;
            Bs[lc + 2][r] = b.z; Bs[lc + 3][r] = b.w;
        }
        __syncthreads();

#pragma unroll
        for (int k = 0; k < 16; ++k) {
            float ar[8];
            *(float4*)&ar[0] = *(const float4*)&As[k][ty * 8];
            *(float4*)&ar[4] = *(const float4*)&As[k][ty * 8 + 4];
            ulonglong2 t0 = *(const ulonglong2*)&Bs[k][tx * 8];
            ulonglong2 t1 = *(const ulonglong2*)&Bs[k][tx * 8 + 4];
            u64 br2[4] = {t0.x, t0.y, t1.x, t1.y};
#pragma unroll
            for (int i = 0; i < 8; ++i) {
                const u64 a2 = bcast2(ar[i]);
#pragma unroll
                for (int j = 0; j < 4; ++j)
                    acc2[i][j] = fma2(a2, br2[j], acc2[i][j]);
            }
        }
        __syncthreads();
    }

#pragma unroll
    for (int i = 0; i < 8; ++i) {
        const int m = mBase + ty * 8 + i;
        float* dst = Cout + (size_t)m * EE + fBase + tx * 8;
        float2 f0v = unpack2(acc2[i][0]);
        float2 f1v = unpack2(acc2[i][1]);
        float2 f2v = unpack2(acc2[i][2]);
        float2 f3v = unpack2(acc2[i][3]);
        float4 w0; w0.x = f0v.x; w0.y = f0v.y; w0.z = f1v.x; w0.w = f1v.y;
        float4 w1; w1.x = f2v.x; w1.y = f2v.y; w1.z = f3v.x; w1.w = f3v.y;
        *(float4*)&dst[0] = w0;
        *(float4*)&dst[4] = w1;
    }
}

// ---------------------------------------------------------------------------
extern "C" void kernel_launch(void* const* d_in, const int* in_sizes, int n_in,
                              void* d_out, int out_size)
{
    const float* x     = (const float*)d_in[0];
    const float* w_qkv = (const float*)d_in[1];
    const float* w_out = (const float*)d_in[2];
    float* out = (float*)d_out;

    {
        dim3 grid(3 * EE / 128, (BB * NN) / 128);
        qkv_gemm_kernel<<<grid, 256>>>(x, w_qkv);
    }
    {
        dim3 grid(BB * HH, NN / 128);
        attn_kernel<<<grid, 128>>>();
    }
    {
        dim3 grid(EE / 128, (BB * NN) / 128);
        out_gemm_kernel<<<grid, 256>>>(w_out, out);
    }
}

// round 4
// speedup vs baseline: 1.2714x; 1.2714x over previous
#include <cuda_runtime.h>
#include <cuda_bf16.h>
#include <cstdint>

// Problem constants
#define BB 4
#define NN 2048
#define EE 1024
#define HH 16
#define DD 64
#define MM (BB * NN)        // 8192
#define FQKV (3 * EE)       // 3072

// ---------------------------------------------------------------------------
// Scratch (__device__ globals; allocation-free rule)
// ---------------------------------------------------------------------------
__device__ float g_q[BB * HH * NN * DD];
__device__ float g_k[BB * HH * NN * DD];
__device__ float g_v[BB * HH * NN * DD];
__device__ float g_att[MM * EE];

__device__ __nv_bfloat16 g_xh[MM * EE];
__device__ __nv_bfloat16 g_xl[MM * EE];
__device__ __nv_bfloat16 g_wqh[FQKV * EE];
__device__ __nv_bfloat16 g_wql[FQKV * EE];
__device__ __nv_bfloat16 g_woh[EE * EE];
__device__ __nv_bfloat16 g_wol[EE * EE];
__device__ __nv_bfloat16 g_ah[MM * EE];
__device__ __nv_bfloat16 g_al[MM * EE];

__device__ __forceinline__ float fast_exp2(float x) {
    float y;
    asm("ex2.approx.ftz.f32 %0, %1;" : "=f"(y) : "f"(x));
    return y;
}

// ---------------------------------------------------------------------------
// bf16 hi/lo split kernels (elementwise, memory-bound)
// ---------------------------------------------------------------------------
__device__ __forceinline__ void split4(float4 v, __nv_bfloat16* hdst, __nv_bfloat16* ldst) {
    __nv_bfloat16 h0 = __float2bfloat16(v.x);
    __nv_bfloat16 h1 = __float2bfloat16(v.y);
    __nv_bfloat16 h2 = __float2bfloat16(v.z);
    __nv_bfloat16 h3 = __float2bfloat16(v.w);
    __nv_bfloat16 l0 = __float2bfloat16(v.x - __bfloat162float(h0));
    __nv_bfloat16 l1 = __float2bfloat16(v.y - __bfloat162float(h1));
    __nv_bfloat16 l2 = __float2bfloat16(v.z - __bfloat162float(h2));
    __nv_bfloat16 l3 = __float2bfloat16(v.w - __bfloat162float(h3));
    __nv_bfloat162 hp0 = {h0, h1}, hp1 = {h2, h3};
    __nv_bfloat162 lp0 = {l0, l1}, lp1 = {l2, l3};
    ((__nv_bfloat162*)hdst)[0] = hp0;
    ((__nv_bfloat162*)hdst)[1] = hp1;
    ((__nv_bfloat162*)ldst)[0] = lp0;
    ((__nv_bfloat162*)ldst)[1] = lp1;
}

__global__ void split_x_kernel(const float* __restrict__ src) {
    int i = blockIdx.x * blockDim.x + threadIdx.x;
    float4 v = ((const float4*)src)[i];
    split4(v, &g_xh[i * 4], &g_xl[i * 4]);
}
__global__ void split_wq_kernel(const float* __restrict__ src) {
    int i = blockIdx.x * blockDim.x + threadIdx.x;
    float4 v = ((const float4*)src)[i];
    split4(v, &g_wqh[i * 4], &g_wql[i * 4]);
}
__global__ void split_wo_kernel(const float* __restrict__ src) {
    int i = blockIdx.x * blockDim.x + threadIdx.x;
    float4 v = ((const float4*)src)[i];
    split4(v, &g_woh[i * 4], &g_wol[i * 4]);
}
__global__ void split_att_kernel() {
    int i = blockIdx.x * blockDim.x + threadIdx.x;
    float4 v = ((const float4*)g_att)[i];
    split4(v, &g_ah[i * 4], &g_al[i * 4]);
}

// ---------------------------------------------------------------------------
// HMMA (mma.sync m16n8k16 bf16) 3-split GEMM:  C[m,f] = sum_e A[m,e]*B[f,e]
// Block tile 128x128, 8 warps (2x4), warp tile 64x32, K-chunk 16,
// double-buffered static smem (exactly 48KB). Smem rows padded to 12 words
// -> conflict-free fragment loads.
// ---------------------------------------------------------------------------
#define SROW 12                  // words per smem tile row (16 bf16 data + pad)
#define TWORDS (128 * SROW)      // words per tile = 1536
#define NCHUNK (EE / 16)         // 64

__device__ __forceinline__ void mma16816(float* c, const uint32_t* a, const uint32_t* b) {
    asm volatile(
        "mma.sync.aligned.m16n8k16.row.col.f32.bf16.bf16.f32 "
        "{%0,%1,%2,%3}, {%4,%5,%6,%7}, {%8,%9}, {%0,%1,%2,%3};"
        : "+f"(c[0]), "+f"(c[1]), "+f"(c[2]), "+f"(c[3])
        : "r"(a[0]), "r"(a[1]), "r"(a[2]), "r"(a[3]),
          "r"(b[0]), "r"(b[1]));
}

struct GPtrs {
    const __nv_bfloat16 *ah, *al, *bh, *bl;
};

__device__ __forceinline__ void hmma_mainloop(
    uint32_t (*sm)[4][TWORDS], const GPtrs tp,
    int mBase, int fBase, float (&acc)[4][4][4])
{
    const int tid = threadIdx.x;
    const int lane = tid & 31;
    const int wid = tid >> 5;
    const int wm = wid >> 2;           // 0..1
    const int wn = wid & 3;            // 0..3
    const int g = lane >> 2;           // 0..7
    const int cc = lane & 3;           // 0..3

    // staging-load mapping: thread -> (row, 16B half-row)
    const int lrow = tid >> 1;
    const int lhalf = tid & 1;
    const size_t offA = (size_t)(mBase + lrow) * EE + lhalf * 8;
    const size_t offB = (size_t)(fBase + lrow) * EE + lhalf * 8;
    const int woff = lrow * SROW + lhalf * 4;

    const int aw = (wm * 64 + g) * SROW + cc;
    const int bw = (wn * 32 + g) * SROW + cc;

#pragma unroll
    for (int i = 0; i < 4; ++i)
#pragma unroll
        for (int j = 0; j < 4; ++j)
#pragma unroll
            for (int r = 0; r < 4; ++r) acc[i][j][r] = 0.f;

    // prologue: chunk 0
    uint4 rah = *(const uint4*)(tp.ah + offA);
    uint4 ral = *(const uint4*)(tp.al + offA);
    uint4 rbh = *(const uint4*)(tp.bh + offB);
    uint4 rbl = *(const uint4*)(tp.bl + offB);
    *(uint4*)&sm[0][0][woff] = rah;
    *(uint4*)&sm[0][1][woff] = ral;
    *(uint4*)&sm[0][2][woff] = rbh;
    *(uint4*)&sm[0][3][woff] = rbl;
    __syncthreads();

    for (int ch = 0; ch < NCHUNK; ++ch) {
        const int s = ch & 1;
        if (ch + 1 < NCHUNK) {
            const int k0 = (ch + 1) * 16;
            rah = *(const uint4*)(tp.ah + offA + k0);
            ral = *(const uint4*)(tp.al + offA + k0);
            rbh = *(const uint4*)(tp.bh + offB + k0);
            rbl = *(const uint4*)(tp.bl + offB + k0);
        }

        const uint32_t* smAh = sm[s][0];
        const uint32_t* smAl = sm[s][1];
        const uint32_t* smBh = sm[s][2];
        const uint32_t* smBl = sm[s][3];

        uint32_t af[4][4], bfh[4][2], bfl[4][2];
#pragma unroll
        for (int j = 0; j < 4; ++j) {
            bfh[j][0] = smBh[bw + j * 96];
            bfh[j][1] = smBh[bw + j * 96 + 4];
            bfl[j][0] = smBl[bw + j * 96];
            bfl[j][1] = smBl[bw + j * 96 + 4];
        }
#pragma unroll
        for (int i = 0; i < 4; ++i) {
            af[i][0] = smAh[aw + i * 192];
            af[i][1] = smAh[aw + i * 192 + 96];
            af[i][2] = smAh[aw + i * 192 + 4];
            af[i][3] = smAh[aw + i * 192 + 100];
        }
#pragma unroll
        for (int i = 0; i < 4; ++i)
#pragma unroll
            for (int j = 0; j < 4; ++j) mma16816(acc[i][j], af[i], bfh[j]);
#pragma unroll
        for (int i = 0; i < 4; ++i)
#pragma unroll
            for (int j = 0; j < 4; ++j) mma16816(acc[i][j], af[i], bfl[j]);
        // reuse af registers for Al fragments
#pragma unroll
        for (int i = 0; i < 4; ++i) {
            af[i][0] = smAl[aw + i * 192];
            af[i][1] = smAl[aw + i * 192 + 96];
            af[i][2] = smAl[aw + i * 192 + 4];
            af[i][3] = smAl[aw + i * 192 + 100];
        }
#pragma unroll
        for (int i = 0; i < 4; ++i)
#pragma unroll
            for (int j = 0; j < 4; ++j) mma16816(acc[i][j], af[i], bfh[j]);

        if (ch + 1 < NCHUNK) {
            const int s2 = s ^ 1;
            *(uint4*)&sm[s2][0][woff] = rah;
            *(uint4*)&sm[s2][1][woff] = ral;
            *(uint4*)&sm[s2][2][woff] = rbh;
            *(uint4*)&sm[s2][3][woff] = rbl;
        }
        __syncthreads();
    }
}

__global__ __launch_bounds__(256) void qkv_gemm_hmma() {
    __shared__ __align__(16) uint32_t sm[2][4][TWORDS];   // 48 KB
    const int mBase = blockIdx.y * 128;
    const int fBase = blockIdx.x * 128;
    float acc[4][4][4];
    GPtrs tp = {g_xh, g_xl, g_wqh, g_wql};
    hmma_mainloop(sm, tp, mBase, fBase, acc);

    const int tid = threadIdx.x;
    const int lane = tid & 31;
    const int wid = tid >> 5;
    const int wm = wid >> 2, wn = wid & 3;
    const int g = lane >> 2, cc = lane & 3;

#pragma unroll
    for (int i = 0; i < 4; ++i) {
        const int m0 = mBase + wm * 64 + i * 16 + g;
        const int b = m0 >> 11;
        const int n0 = m0 & (NN - 1);
#pragma unroll
        for (int j = 0; j < 4; ++j) {
            const int col = fBase + wn * 32 + j * 8 + cc * 2;
            const int which = col >> 10;
            const int h = (col >> 6) & (HH - 1);
            const int d0 = col & (DD - 1);
            float* bp = (which == 0) ? g_q : (which == 1) ? g_k : g_v;
            float* d1 = bp + ((size_t)((b * HH + h) * NN + n0)) * DD + d0;
            float* d2 = bp + ((size_t)((b * HH + h) * NN + n0 + 8)) * DD + d0;
            *(float2*)d1 = make_float2(acc[i][j][0], acc[i][j][1]);
            *(float2*)d2 = make_float2(acc[i][j][2], acc[i][j][3]);
        }
    }
}

__global__ __launch_bounds__(256) void out_gemm_hmma(float* __restrict__ Cout) {
    __shared__ __align__(16) uint32_t sm[2][4][TWORDS];
    const int mBase = blockIdx.y * 128;
    const int fBase = blockIdx.x * 128;
    float acc[4][4][4];
    GPtrs tp = {g_ah, g_al, g_woh, g_wol};
    hmma_mainloop(sm, tp, mBase, fBase, acc);

    const int tid = threadIdx.x;
    const int lane = tid & 31;
    const int wid = tid >> 5;
    const int wm = wid >> 2, wn = wid & 3;
    const int g = lane >> 2, cc = lane & 3;

#pragma unroll
    for (int i = 0; i < 4; ++i) {
        const int m0 = mBase + wm * 64 + i * 16 + g;
#pragma unroll
        for (int j = 0; j < 4; ++j) {
            const int col = fBase + wn * 32 + j * 8 + cc * 2;
            float* d1 = Cout + (size_t)m0 * EE + col;
            float* d2 = Cout + (size_t)(m0 + 8) * EE + col;
            *(float2*)d1 = make_float2(acc[i][j][0], acc[i][j][1]);
            *(float2*)d2 = make_float2(acc[i][j][2], acc[i][j][3]);
        }
    }
}

// ---------------------------------------------------------------------------
// Flash attention (scalar FP32; fastest verified version)
// ---------------------------------------------------------------------------
__global__ __launch_bounds__(128) void attn_kernel()
{
    __shared__ float Ks[64][64];
    __shared__ float Vs[64][64];

    const int bh = blockIdx.x;
    const int qt = blockIdx.y;
    const int t = threadIdx.x;

    const float scale = 0.125f;

    const float* Qp = g_q + ((size_t)bh * NN + qt * 128 + t) * DD;
    float q[DD];
#pragma unroll
    for (int i = 0; i < 16; ++i) {
        float4 v = *(const float4*)&Qp[i * 4];
        q[4 * i + 0] = v.x * scale;
        q[4 * i + 1] = v.y * scale;
        q[4 * i + 2] = v.z * scale;
        q[4 * i + 3] = v.w * scale;
    }

    float o[DD];
#pragma unroll
    for (int i = 0; i < DD; ++i) o[i] = 0.f;
    float mx = -3.0e38f;
    float l = 0.f;

    const float* Kbase = g_k + (size_t)bh * NN * DD;
    const float* Vbase = g_v + (size_t)bh * NN * DD;

    const int lrr = t >> 4;
    const int lcc = (t & 15) << 2;

    for (int kt = 0; kt < NN; kt += 64) {
        if (kt) __syncthreads();
#pragma unroll
        for (int p = 0; p < 8; ++p) {
            const int r = lrr + 8 * p;
            *(float4*)&Ks[r][lcc] = *(const float4*)&Kbase[(size_t)(kt + r) * DD + lcc];
            *(float4*)&Vs[r][lcc] = *(const float4*)&Vbase[(size_t)(kt + r) * DD + lcc];
        }
        __syncthreads();

#pragma unroll 1
        for (int sub = 0; sub < 8; ++sub) {
            const int j0 = sub * 8;
            float s[8];
#pragma unroll
            for (int jj = 0; jj < 8; ++jj) {
                const int row = j0 + jj;
                float a0 = 0.f, a1 = 0.f;
#pragma unroll
                for (int d4 = 0; d4 < 16; d4 += 2) {
                    float4 k0v = *(const float4*)&Ks[row][d4 * 4];
                    float4 k1v = *(const float4*)&Ks[row][d4 * 4 + 4];
                    a0 = fmaf(q[4 * d4 + 0], k0v.x, a0);
                    a0 = fmaf(q[4 * d4 + 1], k0v.y, a0);
                    a0 = fmaf(q[4 * d4 + 2], k0v.z, a0);
                    a0 = fmaf(q[4 * d4 + 3], k0v.w, a0);
                    a1 = fmaf(q[4 * d4 + 4], k1v.x, a1);
                    a1 = fmaf(q[4 * d4 + 5], k1v.y, a1);
                    a1 = fmaf(q[4 * d4 + 6], k1v.z, a1);
                    a1 = fmaf(q[4 * d4 + 7], k1v.w, a1);
                }
                s[jj] = a0 + a1;
            }

            float mnew = mx;
#pragma unroll
            for (int jj = 0; jj < 8; ++jj) mnew = fmaxf(mnew, s[jj]);
            const float alpha = fast_exp2((mx - mnew) * 1.44269504f);
            mx = mnew;
            float psum = 0.f;
#pragma unroll
            for (int jj = 0; jj < 8; ++jj) {
                s[jj] = fast_exp2((s[jj] - mnew) * 1.44269504f);
                psum += s[jj];
            }
            l = l * alpha + psum;
            if (alpha != 1.0f) {
#pragma unroll
                for (int d = 0; d < DD; ++d) o[d] *= alpha;
            }

#pragma unroll
            for (int jj = 0; jj < 8; ++jj) {
                const float p = s[jj];
                const int row = j0 + jj;
#pragma unroll
                for (int d4 = 0; d4 < 16; ++d4) {
                    float4 vv = *(const float4*)&Vs[row][d4 * 4];
                    o[4 * d4 + 0] = fmaf(p, vv.x, o[4 * d4 + 0]);
                    o[4 * d4 + 1] = fmaf(p, vv.y, o[4 * d4 + 1]);
                    o[4 * d4 + 2] = fmaf(p, vv.z, o[4 * d4 + 2]);
                    o[4 * d4 + 3] = fmaf(p, vv.w, o[4 * d4 + 3]);
                }
            }
        }
    }

    const float inv = 1.f / l;
    const int b = bh >> 4;
    const int h = bh & (HH - 1);
    const int n = qt * 128 + t;
    float* dst = g_att + ((size_t)(b * NN + n)) * EE + h * DD;
#pragma unroll
    for (int d4 = 0; d4 < 16; ++d4) {
        float4 w;
        w.x = o[4 * d4 + 0] * inv;
        w.y = o[4 * d4 + 1] * inv;
        w.z = o[4 * d4 + 2] * inv;
        w.w = o[4 * d4 + 3] * inv;
        *(float4*)&dst[d4 * 4] = w;
    }
}

// ---------------------------------------------------------------------------
extern "C" void kernel_launch(void* const* d_in, const int* in_sizes, int n_in,
                              void* d_out, int out_size)
{
    const float* x     = (const float*)d_in[0];
    const float* w_qkv = (const float*)d_in[1];
    const float* w_out = (const float*)d_in[2];
    float* out = (float*)d_out;

    // 1) bf16 hi/lo splits of inputs
    split_x_kernel<<<(MM * EE / 4) / 256, 256>>>(x);
    split_wq_kernel<<<(FQKV * EE / 4) / 256, 256>>>(w_qkv);
    split_wo_kernel<<<(EE * EE / 4) / 256, 256>>>(w_out);

    // 2) QKV projection (HMMA) -> g_q/g_k/g_v
    {
        dim3 grid(FQKV / 128, MM / 128);   // (24, 64)
        qkv_gemm_hmma<<<grid, 256>>>();
    }
    // 3) Attention -> g_att
    {
        dim3 grid(BB * HH, NN / 128);
        attn_kernel<<<grid, 128>>>();
    }
    // 4) Split attention output, 5) output projection (HMMA)
    split_att_kernel<<<(MM * EE / 4) / 256, 256>>>();
    {
        dim3 grid(EE / 128, MM / 128);     // (8, 64)
        out_gemm_hmma<<<grid, 256>>>(out);
    }
}

// round 5
// speedup vs baseline: 2.9256x; 2.3012x over previous
#include <cuda_runtime.h>
#include <cuda_bf16.h>
#include <cstdint>

// Problem constants
#define BB 4
#define NN 2048
#define EE 1024
#define HH 16
#define DD 64
#define MM (BB * NN)        // 8192
#define FQKV (3 * EE)       // 3072
#define BHND (64 * 2048 * 64)

// ---------------------------------------------------------------------------
// Scratch (__device__ globals; allocation-free rule)
// ---------------------------------------------------------------------------
__device__ float g_att[MM * EE];

__device__ __nv_bfloat16 g_qh[BHND], g_ql[BHND];      // [bh][n][d], prescaled
__device__ __nv_bfloat16 g_kh[BHND], g_kl[BHND];      // [bh][n][d]
__device__ __nv_bfloat16 g_vth[BHND], g_vtl[BHND];    // [bh][d][n] (transposed)

__device__ __nv_bfloat16 g_xh[MM * EE], g_xl[MM * EE];
__device__ __nv_bfloat16 g_wqh[FQKV * EE], g_wql[FQKV * EE];
__device__ __nv_bfloat16 g_woh[EE * EE], g_wol[EE * EE];
__device__ __nv_bfloat16 g_ah[MM * EE], g_al[MM * EE];

__device__ __forceinline__ float fast_exp2(float x) {
    float y;
    asm("ex2.approx.ftz.f32 %0, %1;" : "=f"(y) : "f"(x));
    return y;
}
__device__ __forceinline__ uint32_t pack_bf2(float lo, float hi) {
    __nv_bfloat162 t = __floats2bfloat162_rn(lo, hi);   // x=lo, y=hi
    uint32_t r; r = *reinterpret_cast<uint32_t*>(&t); return r;
}
__device__ __forceinline__ uint32_t smem_u32(const void* p) {
    uint32_t a;
    asm("{ .reg .u64 t; cvta.to.shared.u64 t, %1; cvt.u32.u64 %0, t; }"
        : "=r"(a) : "l"(p));
    return a;
}
__device__ __forceinline__ void cp16(uint32_t saddr, const void* g) {
    asm volatile("cp.async.cg.shared.global [%0], [%1], 16;" :: "r"(saddr), "l"(g));
}
__device__ __forceinline__ void cp_commit() {
    asm volatile("cp.async.commit_group;" ::: "memory");
}
__device__ __forceinline__ void cp_wait0() {
    asm volatile("cp.async.wait_group 0;" ::: "memory");
}

// ---------------------------------------------------------------------------
// bf16 hi/lo split kernels
// ---------------------------------------------------------------------------
__device__ __forceinline__ void split4(float4 v, __nv_bfloat16* hdst, __nv_bfloat16* ldst) {
    __nv_bfloat16 h0 = __float2bfloat16(v.x);
    __nv_bfloat16 h1 = __float2bfloat16(v.y);
    __nv_bfloat16 h2 = __float2bfloat16(v.z);
    __nv_bfloat16 h3 = __float2bfloat16(v.w);
    __nv_bfloat16 l0 = __float2bfloat16(v.x - __bfloat162float(h0));
    __nv_bfloat16 l1 = __float2bfloat16(v.y - __bfloat162float(h1));
    __nv_bfloat16 l2 = __float2bfloat16(v.z - __bfloat162float(h2));
    __nv_bfloat16 l3 = __float2bfloat16(v.w - __bfloat162float(h3));
    __nv_bfloat162 hp0 = {h0, h1}, hp1 = {h2, h3};
    __nv_bfloat162 lp0 = {l0, l1}, lp1 = {l2, l3};
    ((__nv_bfloat162*)hdst)[0] = hp0;
    ((__nv_bfloat162*)hdst)[1] = hp1;
    ((__nv_bfloat162*)ldst)[0] = lp0;
    ((__nv_bfloat162*)ldst)[1] = lp1;
}
__global__ void split_x_kernel(const float* __restrict__ src) {
    int i = blockIdx.x * blockDim.x + threadIdx.x;
    float4 v = ((const float4*)src)[i];
    split4(v, &g_xh[i * 4], &g_xl[i * 4]);
}
__global__ void split_wq_kernel(const float* __restrict__ src) {
    int i = blockIdx.x * blockDim.x + threadIdx.x;
    float4 v = ((const float4*)src)[i];
    split4(v, &g_wqh[i * 4], &g_wql[i * 4]);
}
__global__ void split_wo_kernel(const float* __restrict__ src) {
    int i = blockIdx.x * blockDim.x + threadIdx.x;
    float4 v = ((const float4*)src)[i];
    split4(v, &g_woh[i * 4], &g_wol[i * 4]);
}
__global__ void split_att_kernel() {
    int i = blockIdx.x * blockDim.x + threadIdx.x;
    float4 v = ((const float4*)g_att)[i];
    split4(v, &g_ah[i * 4], &g_al[i * 4]);
}

// ---------------------------------------------------------------------------
// HMMA building block
// ---------------------------------------------------------------------------
__device__ __forceinline__ void mma16816(float* c, const uint32_t* a, const uint32_t* b) {
    asm volatile(
        "mma.sync.aligned.m16n8k16.row.col.f32.bf16.bf16.f32 "
        "{%0,%1,%2,%3}, {%4,%5,%6,%7}, {%8,%9}, {%0,%1,%2,%3};"
        : "+f"(c[0]), "+f"(c[1]), "+f"(c[2]), "+f"(c[3])
        : "r"(a[0]), "r"(a[1]), "r"(a[2]), "r"(a[3]),
          "r"(b[0]), "r"(b[1]));
}

// ---------------------------------------------------------------------------
// 3-split HMMA GEMM mainloop (same as round 4, verified)
// ---------------------------------------------------------------------------
#define SROW 12
#define TWORDS (128 * SROW)
#define NCHUNK (EE / 16)

struct GPtrs { const __nv_bfloat16 *ah, *al, *bh, *bl; };

__device__ __forceinline__ void hmma_mainloop(
    uint32_t (*sm)[4][TWORDS], const GPtrs tp,
    int mBase, int fBase, float (&acc)[4][4][4])
{
    const int tid = threadIdx.x;
    const int lane = tid & 31;
    const int wid = tid >> 5;
    const int wm = wid >> 2;
    const int wn = wid & 3;
    const int g = lane >> 2;
    const int cc = lane & 3;

    const int lrow = tid >> 1;
    const int lhalf = tid & 1;
    const size_t offA = (size_t)(mBase + lrow) * EE + lhalf * 8;
    const size_t offB = (size_t)(fBase + lrow) * EE + lhalf * 8;
    const int woff = lrow * SROW + lhalf * 4;

    const int aw = (wm * 64 + g) * SROW + cc;
    const int bw = (wn * 32 + g) * SROW + cc;

#pragma unroll
    for (int i = 0; i < 4; ++i)
#pragma unroll
        for (int j = 0; j < 4; ++j)
#pragma unroll
            for (int r = 0; r < 4; ++r) acc[i][j][r] = 0.f;

    uint4 rah = *(const uint4*)(tp.ah + offA);
    uint4 ral = *(const uint4*)(tp.al + offA);
    uint4 rbh = *(const uint4*)(tp.bh + offB);
    uint4 rbl = *(const uint4*)(tp.bl + offB);
    *(uint4*)&sm[0][0][woff] = rah;
    *(uint4*)&sm[0][1][woff] = ral;
    *(uint4*)&sm[0][2][woff] = rbh;
    *(uint4*)&sm[0][3][woff] = rbl;
    __syncthreads();

    for (int ch = 0; ch < NCHUNK; ++ch) {
        const int s = ch & 1;
        if (ch + 1 < NCHUNK) {
            const int k0 = (ch + 1) * 16;
            rah = *(const uint4*)(tp.ah + offA + k0);
            ral = *(const uint4*)(tp.al + offA + k0);
            rbh = *(const uint4*)(tp.bh + offB + k0);
            rbl = *(const uint4*)(tp.bl + offB + k0);
        }
        const uint32_t* smAh = sm[s][0];
        const uint32_t* smAl = sm[s][1];
        const uint32_t* smBh = sm[s][2];
        const uint32_t* smBl = sm[s][3];

        uint32_t af[4][4], bfh[4][2], bfl[4][2];
#pragma unroll
        for (int j = 0; j < 4; ++j) {
            bfh[j][0] = smBh[bw + j * 96];
            bfh[j][1] = smBh[bw + j * 96 + 4];
            bfl[j][0] = smBl[bw + j * 96];
            bfl[j][1] = smBl[bw + j * 96 + 4];
        }
#pragma unroll
        for (int i = 0; i < 4; ++i) {
            af[i][0] = smAh[aw + i * 192];
            af[i][1] = smAh[aw + i * 192 + 96];
            af[i][2] = smAh[aw + i * 192 + 4];
            af[i][3] = smAh[aw + i * 192 + 100];
        }
#pragma unroll
        for (int i = 0; i < 4; ++i)
#pragma unroll
            for (int j = 0; j < 4; ++j) mma16816(acc[i][j], af[i], bfh[j]);
#pragma unroll
        for (int i = 0; i < 4; ++i)
#pragma unroll
            for (int j = 0; j < 4; ++j) mma16816(acc[i][j], af[i], bfl[j]);
#pragma unroll
        for (int i = 0; i < 4; ++i) {
            af[i][0] = smAl[aw + i * 192];
            af[i][1] = smAl[aw + i * 192 + 96];
            af[i][2] = smAl[aw + i * 192 + 4];
            af[i][3] = smAl[aw + i * 192 + 100];
        }
#pragma unroll
        for (int i = 0; i < 4; ++i)
#pragma unroll
            for (int j = 0; j < 4; ++j) mma16816(acc[i][j], af[i], bfh[j]);

        if (ch + 1 < NCHUNK) {
            const int s2 = s ^ 1;
            *(uint4*)&sm[s2][0][woff] = rah;
            *(uint4*)&sm[s2][1][woff] = ral;
            *(uint4*)&sm[s2][2][woff] = rbh;
            *(uint4*)&sm[s2][3][woff] = rbl;
        }
        __syncthreads();
    }
}

// ---------------------------------------------------------------------------
// QKV GEMM: epilogue writes bf16 hi/lo Q,K ([bh][n][d]) and transposed V
// ---------------------------------------------------------------------------
__global__ __launch_bounds__(256) void qkv_gemm_hmma() {
    __shared__ __align__(16) uint32_t sm[2][4][TWORDS];
    const int mBase = blockIdx.y * 128;
    const int fBase = blockIdx.x * 128;
    float acc[4][4][4];
    GPtrs tp = {g_xh, g_xl, g_wqh, g_wql};
    hmma_mainloop(sm, tp, mBase, fBase, acc);

    const int tid = threadIdx.x;
    const int lane = tid & 31;
    const int wid = tid >> 5;
    const int wm = wid >> 2, wn = wid & 3;
    const int g = lane >> 2, cc = lane & 3;
    const int which = fBase >> 10;    // uniform per CTA

    if (which == 2) {
        // V -> g_vth/g_vtl [bh][d][n]
#pragma unroll
        for (int i = 0; i < 4; ++i) {
            const int m0 = mBase + wm * 64 + i * 16 + g;
            const int b = m0 >> 11;
            const int n0 = m0 & (NN - 1);
#pragma unroll
            for (int j = 0; j < 4; ++j) {
                const int col = fBase + wn * 32 + j * 8 + cc * 2;
                const int h = (col >> 6) & (HH - 1);
                const int d0 = col & (DD - 1);
                const size_t base = (size_t)(b * HH + h) * DD;
#pragma unroll
                for (int r = 0; r < 4; ++r) {
                    const int dd = d0 + (r & 1);
                    const int nn = n0 + (r >> 1) * 8;
                    float v = acc[i][j][r];
                    __nv_bfloat16 hh = __float2bfloat16(v);
                    __nv_bfloat16 ll = __float2bfloat16(v - __bfloat162float(hh));
                    g_vth[(base + dd) * NN + nn] = hh;
                    g_vtl[(base + dd) * NN + nn] = ll;
                }
            }
        }
    } else {
        const float qs = (which == 0) ? 0.125f * 1.44269504f : 1.0f;
        uint32_t* ph_ = (uint32_t*)((which == 0) ? g_qh : g_kh);
        uint32_t* pl_ = (uint32_t*)((which == 0) ? g_ql : g_kl);
#pragma unroll
        for (int i = 0; i < 4; ++i) {
            const int m0 = mBase + wm * 64 + i * 16 + g;
            const int b = m0 >> 11;
            const int n0 = m0 & (NN - 1);
#pragma unroll
            for (int j = 0; j < 4; ++j) {
                const int col = fBase + wn * 32 + j * 8 + cc * 2;
                const int h = (col >> 6) & (HH - 1);
                const int d0 = col & (DD - 1);
                const size_t rowbase = (size_t)(b * HH + h) * NN;
                float v0 = acc[i][j][0] * qs, v1 = acc[i][j][1] * qs;
                float v2 = acc[i][j][2] * qs, v3 = acc[i][j][3] * qs;
                uint32_t hp0 = pack_bf2(v0, v1);
                float f0 = __int_as_float(hp0 << 16);
                float f1 = __int_as_float(hp0 & 0xFFFF0000u);
                uint32_t lp0 = pack_bf2(v0 - f0, v1 - f1);
                uint32_t hp1 = pack_bf2(v2, v3);
                float f2 = __int_as_float(hp1 << 16);
                float f3 = __int_as_float(hp1 & 0xFFFF0000u);
                uint32_t lp1 = pack_bf2(v2 - f2, v3 - f3);
                ph_[(rowbase + n0) * 32 + (d0 >> 1)] = hp0;
                pl_[(rowbase + n0) * 32 + (d0 >> 1)] = lp0;
                ph_[(rowbase + n0 + 8) * 32 + (d0 >> 1)] = hp1;
                pl_[(rowbase + n0 + 8) * 32 + (d0 >> 1)] = lp1;
            }
        }
    }
}

// ---------------------------------------------------------------------------
// Output projection GEMM (unchanged)
// ---------------------------------------------------------------------------
__global__ __launch_bounds__(256) void out_gemm_hmma(float* __restrict__ Cout) {
    __shared__ __align__(16) uint32_t sm[2][4][TWORDS];
    const int mBase = blockIdx.y * 128;
    const int fBase = blockIdx.x * 128;
    float acc[4][4][4];
    GPtrs tp = {g_ah, g_al, g_woh, g_wol};
    hmma_mainloop(sm, tp, mBase, fBase, acc);

    const int tid = threadIdx.x;
    const int lane = tid & 31;
    const int wid = tid >> 5;
    const int wm = wid >> 2, wn = wid & 3;
    const int g = lane >> 2, cc = lane & 3;

#pragma unroll
    for (int i = 0; i < 4; ++i) {
        const int m0 = mBase + wm * 64 + i * 16 + g;
#pragma unroll
        for (int j = 0; j < 4; ++j) {
            const int col = fBase + wn * 32 + j * 8 + cc * 2;
            float* d1 = Cout + (size_t)m0 * EE + col;
            float* d2 = Cout + (size_t)(m0 + 8) * EE + col;
            *(float2*)d1 = make_float2(acc[i][j][0], acc[i][j][1]);
            *(float2*)d2 = make_float2(acc[i][j][2], acc[i][j][3]);
        }
    }
}

// ---------------------------------------------------------------------------
// Flash attention with HMMA. grid=(64 bh, 16 qtile), block=256 (8 warps).
// 128-key chunks, cp.async double-buffered smem.
// smem layout per stage: Kh[128][72B-pad] Kl Vth[64][136B-pad] Vtl
// ---------------------------------------------------------------------------
#define KROW 36                       // u32 stride of K smem row
#define VROW 68                       // u32 stride of Vt smem row
#define KWORDS (128 * KROW)           // 4608
#define VWORDS (64 * VROW)            // 4352
#define STAGEW (2 * KWORDS + 2 * VWORDS)   // 17920 u32
#define STAGEB (STAGEW * 4)           // 71680 B
#define ATTN_SMEM (2 * STAGEB)        // 143360 B
#define KBYTES (KWORDS * 4)           // 18432
#define VBYTES (VWORDS * 4)           // 17408

__global__ __launch_bounds__(256, 1) void attn_hmma() {
    extern __shared__ __align__(16) uint32_t smdyn[];

    const int bh = blockIdx.x;
    const int qt = blockIdx.y;
    const int tid = threadIdx.x;
    const int lane = tid & 31, wid = tid >> 5;
    const int g = lane >> 2, cc = lane & 3;

    const size_t qoff = (size_t)bh * NN * DD;   // elements per bh = 131072
    const uint32_t* qhw = (const uint32_t*)g_qh + (qoff >> 1);
    const uint32_t* qlw = (const uint32_t*)g_ql + (qoff >> 1);
    const char* kh_g = (const char*)(g_kh + qoff);
    const char* kl_g = (const char*)(g_kl + qoff);
    const char* vh_g = (const char*)(g_vth + qoff);
    const char* vl_g = (const char*)(g_vtl + qoff);
    const uint32_t sb = smem_u32(smdyn);

    // Q fragments (A-layout), rows r0 = qt*128 + wid*16 + g and r0+8
    const int r0 = qt * 128 + wid * 16 + g;
    uint32_t qa[4][4], qb[4][4];
#pragma unroll
    for (int kc = 0; kc < 4; ++kc) {
        const int w0 = r0 * 32 + kc * 8 + cc;
        qa[kc][0] = qhw[w0];       qa[kc][1] = qhw[w0 + 256];
        qa[kc][2] = qhw[w0 + 4];   qa[kc][3] = qhw[w0 + 260];
        qb[kc][0] = qlw[w0];       qb[kc][1] = qlw[w0 + 256];
        qb[kc][2] = qlw[w0 + 4];   qb[kc][3] = qlw[w0 + 260];
    }

    float o[8][4];
#pragma unroll
    for (int j = 0; j < 8; ++j) { o[j][0] = o[j][1] = o[j][2] = o[j][3] = 0.f; }
    float m0 = -30000.f, m1 = -30000.f, l0 = 0.f, l1 = 0.f;

    // loader: chunk kt -> stage s
    auto load_chunk = [&](int kt, int s) {
        const uint32_t base = sb + s * STAGEB;
#pragma unroll
        for (int i = 0; i < 4; ++i) {
            const int idx = tid + 256 * i;
            const int r = idx >> 3, c = idx & 7;
            const int goff = kt * 16384 + r * 128 + c * 16;
            const uint32_t so = (uint32_t)(r * 144 + c * 16);
            cp16(base + so, kh_g + goff);
            cp16(base + KBYTES + so, kl_g + goff);
        }
#pragma unroll
        for (int i = 0; i < 4; ++i) {
            const int idx = tid + 256 * i;
            const int r = idx >> 4, c = idx & 15;
            const int goff = r * 4096 + kt * 256 + c * 16;
            const uint32_t so = (uint32_t)(r * 272 + c * 16);
            cp16(base + 2 * KBYTES + so, vh_g + goff);
            cp16(base + 2 * KBYTES + VBYTES + so, vl_g + goff);
        }
        cp_commit();
    };

    load_chunk(0, 0);
    cp_wait0();
    __syncthreads();

    for (int ch = 0; ch < 16; ++ch) {
        const int s = ch & 1;
        if (ch + 1 < 16) load_chunk(ch + 1, s ^ 1);

        const uint32_t* sKh = smdyn + s * STAGEW;
        const uint32_t* sKl = sKh + KWORDS;
        const uint32_t* sVh = sKl + KWORDS;
        const uint32_t* sVl = sVh + VWORDS;

        // --- scores S[16q x 128k] ---
        float sc[16][4];
#pragma unroll
        for (int j = 0; j < 16; ++j) { sc[j][0] = sc[j][1] = sc[j][2] = sc[j][3] = 0.f; }
#pragma unroll
        for (int kc = 0; kc < 4; ++kc) {
#pragma unroll
            for (int j = 0; j < 16; ++j) {
                const int bw = (j * 8 + g) * KROW + kc * 8 + cc;
                uint32_t bh_[2] = { sKh[bw], sKh[bw + 4] };
                uint32_t bl_[2] = { sKl[bw], sKl[bw + 4] };
                mma16816(sc[j], qa[kc], bh_);
                mma16816(sc[j], qa[kc], bl_);
                mma16816(sc[j], qb[kc], bh_);
            }
        }

        // --- online softmax (log2 domain) ---
        float cm0 = -30000.f, cm1 = -30000.f;
#pragma unroll
        for (int j = 0; j < 16; ++j) {
            cm0 = fmaxf(cm0, fmaxf(sc[j][0], sc[j][1]));
            cm1 = fmaxf(cm1, fmaxf(sc[j][2], sc[j][3]));
        }
        cm0 = fmaxf(cm0, __shfl_xor_sync(0xffffffffu, cm0, 1));
        cm0 = fmaxf(cm0, __shfl_xor_sync(0xffffffffu, cm0, 2));
        cm1 = fmaxf(cm1, __shfl_xor_sync(0xffffffffu, cm1, 1));
        cm1 = fmaxf(cm1, __shfl_xor_sync(0xffffffffu, cm1, 2));
        const float mn0 = fmaxf(m0, cm0), mn1 = fmaxf(m1, cm1);
        const float a0 = fast_exp2(m0 - mn0), a1 = fast_exp2(m1 - mn1);
        m0 = mn0; m1 = mn1;
#pragma unroll
        for (int j = 0; j < 8; ++j) {
            o[j][0] *= a0; o[j][1] *= a0; o[j][2] *= a1; o[j][3] *= a1;
        }

        float rs0 = 0.f, rs1 = 0.f;
#pragma unroll
        for (int kc2 = 0; kc2 < 8; ++kc2) {
            uint32_t pah[4], pal[4];
#pragma unroll
            for (int t = 0; t < 2; ++t) {
                const int j = kc2 * 2 + t;
                float p0 = fast_exp2(sc[j][0] - m0);
                float p1 = fast_exp2(sc[j][1] - m0);
                float p2 = fast_exp2(sc[j][2] - m1);
                float p3 = fast_exp2(sc[j][3] - m1);
                rs0 += p0 + p1; rs1 += p2 + p3;
                uint32_t h01 = pack_bf2(p0, p1);
                uint32_t h23 = pack_bf2(p2, p3);
                float f0 = __int_as_float(h01 << 16);
                float f1 = __int_as_float(h01 & 0xFFFF0000u);
                float f2 = __int_as_float(h23 << 16);
                float f3 = __int_as_float(h23 & 0xFFFF0000u);
                uint32_t l01 = pack_bf2(p0 - f0, p1 - f1);
                uint32_t l23 = pack_bf2(p2 - f2, p3 - f3);
                pah[2 * t] = h01; pah[2 * t + 1] = h23;
                pal[2 * t] = l01; pal[2 * t + 1] = l23;
            }
#pragma unroll
            for (int j = 0; j < 8; ++j) {
                const int bw = (j * 8 + g) * VROW + kc2 * 8 + cc;
                uint32_t bvh[2] = { sVh[bw], sVh[bw + 4] };
                uint32_t bvl[2] = { sVl[bw], sVl[bw + 4] };
                mma16816(o[j], pah, bvh);
                mma16816(o[j], pal, bvh);
                mma16816(o[j], pah, bvl);
            }
        }
        rs0 += __shfl_xor_sync(0xffffffffu, rs0, 1);
        rs0 += __shfl_xor_sync(0xffffffffu, rs0, 2);
        rs1 += __shfl_xor_sync(0xffffffffu, rs1, 1);
        rs1 += __shfl_xor_sync(0xffffffffu, rs1, 2);
        l0 = l0 * a0 + rs0;
        l1 = l1 * a1 + rs1;

        if (ch + 1 < 16) {
            cp_wait0();
            __syncthreads();
        }
    }

    const float i0 = 1.f / l0, i1 = 1.f / l1;
    const int b = bh >> 4, h = bh & (HH - 1);
    float* dst0 = g_att + ((size_t)(b * NN + r0)) * EE + h * DD;
    float* dst1 = dst0 + 8 * EE;
#pragma unroll
    for (int j = 0; j < 8; ++j) {
        *(float2*)(dst0 + j * 8 + cc * 2) = make_float2(o[j][0] * i0, o[j][1] * i0);
        *(float2*)(dst1 + j * 8 + cc * 2) = make_float2(o[j][2] * i1, o[j][3] * i1);
    }
}

// ---------------------------------------------------------------------------
extern "C" void kernel_launch(void* const* d_in, const int* in_sizes, int n_in,
                              void* d_out, int out_size)
{
    const float* x     = (const float*)d_in[0];
    const float* w_qkv = (const float*)d_in[1];
    const float* w_out = (const float*)d_in[2];
    float* out = (float*)d_out;

    cudaFuncSetAttribute(attn_hmma,
                         cudaFuncAttributeMaxDynamicSharedMemorySize, ATTN_SMEM);

    split_x_kernel<<<(MM * EE / 4) / 256, 256>>>(x);
    split_wq_kernel<<<(FQKV * EE / 4) / 256, 256>>>(w_qkv);
    split_wo_kernel<<<(EE * EE / 4) / 256, 256>>>(w_out);

    {
        dim3 grid(FQKV / 128, MM / 128);
        qkv_gemm_hmma<<<grid, 256>>>();
    }
    {
        dim3 grid(BB * HH, NN / 128);
        attn_hmma<<<grid, 256, ATTN_SMEM>>>();
    }
    split_att_kernel<<<(MM * EE / 4) / 256, 256>>>();
    {
        dim3 grid(EE / 128, MM / 128);
        out_gemm_hmma<<<grid, 256>>>(out);
    }
}

// round 6
// speedup vs baseline: 3.0189x; 1.0319x over previous
#include <cuda_runtime.h>
#include <cuda_bf16.h>
#include <cstdint>

// Problem constants
#define BB 4
#define NN 2048
#define EE 1024
#define HH 16
#define DD 64
#define MM (BB * NN)        // 8192
#define FQKV (3 * EE)       // 3072
#define BHND (64 * 2048 * 64)

// ---------------------------------------------------------------------------
// Scratch (__device__ globals; allocation-free rule)
// ---------------------------------------------------------------------------
__device__ __nv_bfloat16 g_qh[BHND], g_ql[BHND];      // [bh][n][d], prescaled
__device__ __nv_bfloat16 g_kh[BHND], g_kl[BHND];      // [bh][n][d]
__device__ __nv_bfloat16 g_vth[BHND], g_vtl[BHND];    // [bh][d][n] (transposed)

__device__ __nv_bfloat16 g_xh[MM * EE], g_xl[MM * EE];
__device__ __nv_bfloat16 g_wqh[FQKV * EE], g_wql[FQKV * EE];
__device__ __nv_bfloat16 g_woh[EE * EE], g_wol[EE * EE];
__device__ __nv_bfloat16 g_ah[MM * EE], g_al[MM * EE];   // attn out hi/lo

__device__ __forceinline__ float fast_exp2(float x) {
    float y;
    asm("ex2.approx.ftz.f32 %0, %1;" : "=f"(y) : "f"(x));
    return y;
}
__device__ __forceinline__ uint32_t pack_bf2(float lo, float hi) {
    __nv_bfloat162 t = __floats2bfloat162_rn(lo, hi);
    uint32_t r; r = *reinterpret_cast<uint32_t*>(&t); return r;
}
__device__ __forceinline__ uint32_t smem_u32(const void* p) {
    uint32_t a;
    asm("{ .reg .u64 t; cvta.to.shared.u64 t, %1; cvt.u32.u64 %0, t; }"
        : "=r"(a) : "l"(p));
    return a;
}
__device__ __forceinline__ void cp16(uint32_t saddr, const void* g) {
    asm volatile("cp.async.cg.shared.global [%0], [%1], 16;" :: "r"(saddr), "l"(g));
}
__device__ __forceinline__ void cp_commit() {
    asm volatile("cp.async.commit_group;" ::: "memory");
}
__device__ __forceinline__ void cp_wait0() {
    asm volatile("cp.async.wait_group 0;" ::: "memory");
}
__device__ __forceinline__ void cp_wait1() {
    asm volatile("cp.async.wait_group 1;" ::: "memory");
}
__device__ __forceinline__ void ldsm_x4(uint32_t* r, uint32_t addr) {
    asm volatile("ldmatrix.sync.aligned.m8n8.x4.shared.b16 {%0,%1,%2,%3}, [%4];"
        : "=r"(r[0]), "=r"(r[1]), "=r"(r[2]), "=r"(r[3]) : "r"(addr));
}
__device__ __forceinline__ void mma16816(float* c, const uint32_t* a, const uint32_t* b) {
    asm volatile(
        "mma.sync.aligned.m16n8k16.row.col.f32.bf16.bf16.f32 "
        "{%0,%1,%2,%3}, {%4,%5,%6,%7}, {%8,%9}, {%0,%1,%2,%3};"
        : "+f"(c[0]), "+f"(c[1]), "+f"(c[2]), "+f"(c[3])
        : "r"(a[0]), "r"(a[1]), "r"(a[2]), "r"(a[3]),
          "r"(b[0]), "r"(b[1]));
}

// ---------------------------------------------------------------------------
// bf16 hi/lo split kernels
// ---------------------------------------------------------------------------
__device__ __forceinline__ void split4(float4 v, __nv_bfloat16* hdst, __nv_bfloat16* ldst) {
    __nv_bfloat16 h0 = __float2bfloat16(v.x);
    __nv_bfloat16 h1 = __float2bfloat16(v.y);
    __nv_bfloat16 h2 = __float2bfloat16(v.z);
    __nv_bfloat16 h3 = __float2bfloat16(v.w);
    __nv_bfloat16 l0 = __float2bfloat16(v.x - __bfloat162float(h0));
    __nv_bfloat16 l1 = __float2bfloat16(v.y - __bfloat162float(h1));
    __nv_bfloat16 l2 = __float2bfloat16(v.z - __bfloat162float(h2));
    __nv_bfloat16 l3 = __float2bfloat16(v.w - __bfloat162float(h3));
    __nv_bfloat162 hp0 = {h0, h1}, hp1 = {h2, h3};
    __nv_bfloat162 lp0 = {l0, l1}, lp1 = {l2, l3};
    ((__nv_bfloat162*)hdst)[0] = hp0;
    ((__nv_bfloat162*)hdst)[1] = hp1;
    ((__nv_bfloat162*)ldst)[0] = lp0;
    ((__nv_bfloat162*)ldst)[1] = lp1;
}
__global__ void split_x_kernel(const float* __restrict__ src) {
    int i = blockIdx.x * blockDim.x + threadIdx.x;
    float4 v = ((const float4*)src)[i];
    split4(v, &g_xh[i * 4], &g_xl[i * 4]);
}
__global__ void split_wq_kernel(const float* __restrict__ src) {
    int i = blockIdx.x * blockDim.x + threadIdx.x;
    float4 v = ((const float4*)src)[i];
    split4(v, &g_wqh[i * 4], &g_wql[i * 4]);
}
__global__ void split_wo_kernel(const float* __restrict__ src) {
    int i = blockIdx.x * blockDim.x + threadIdx.x;
    float4 v = ((const float4*)src)[i];
    split4(v, &g_woh[i * 4], &g_wol[i * 4]);
}

// ---------------------------------------------------------------------------
// 3-split HMMA GEMM: CTA 128x256, 8 warps (2x4), warp tile 64x64, K-chunk 16.
// cp.async double-buffered dynamic smem; ldmatrix fragment loads.
// Smem rows padded to 48B -> conflict-free LDSM phases.
// ---------------------------------------------------------------------------
#define A_W (128 * 12)             // words per A tile = 1536 (6KB)
#define B_W (256 * 12)             // words per B tile = 3072 (12KB)
#define GSTAGE_W (2 * A_W + 2 * B_W)   // 9216 words = 36KB
#define GEMM_SMEM (2 * GSTAGE_W * 4)   // 73728 B

struct GPtrs { const __nv_bfloat16 *ah, *al, *bh, *bl; };

__device__ __forceinline__ void hmma_mainloop256(
    uint32_t* sm, const GPtrs tp, int mBase, int fBase, float (&acc)[4][8][4])
{
    const int tid = threadIdx.x;
    const int lane = tid & 31;
    const int wid = tid >> 5;
    const int wm = wid >> 2;           // 0..1
    const int wn = wid & 3;            // 0..3
    const uint32_t sb = smem_u32(sm);

#pragma unroll
    for (int i = 0; i < 4; ++i)
#pragma unroll
        for (int j = 0; j < 8; ++j)
#pragma unroll
            for (int r = 0; r < 4; ++r) acc[i][j][r] = 0.f;

    // fragment addresses (byte offsets within tiles)
    const uint32_t aoffb = (uint32_t)((lane & 15) * 48 + (lane >> 4) * 16);
    const uint32_t boffb = (uint32_t)(((lane & 7) + (lane >> 4) * 8) * 48 + ((lane >> 3) & 1) * 16);

    auto load_chunk = [&](int ch, int s) {
        const int k0 = ch * 16;
        const uint32_t stb = sb + (uint32_t)s * (GSTAGE_W * 4);
        // A: 2 cp16/thread  (t = split)
#pragma unroll
        for (int t = 0; t < 2; ++t) {
            const int r = tid >> 1;
            const int half = tid & 1;
            const __nv_bfloat16* gp = (t == 0 ? tp.ah : tp.al)
                                    + (size_t)(mBase + r) * EE + k0 + half * 8;
            cp16(stb + (uint32_t)(t * (A_W * 4) + r * 48 + half * 16), gp);
        }
        // B: 4 cp16/thread
#pragma unroll
        for (int t = 0; t < 4; ++t) {
            const int idx = t * 256 + tid;
            const int split = idx >> 9;
            const int w = idx & 511;
            const int r = w >> 1;
            const int half = w & 1;
            const __nv_bfloat16* gp = (split == 0 ? tp.bh : tp.bl)
                                    + (size_t)(fBase + r) * EE + k0 + half * 8;
            cp16(stb + (uint32_t)(2 * (A_W * 4) + split * (B_W * 4) + r * 48 + half * 16), gp);
        }
        cp_commit();
    };

    load_chunk(0, 0);

    for (int ch = 0; ch < 64; ++ch) {
        const int s = ch & 1;
        const bool more = (ch + 1 < 64);
        if (more) load_chunk(ch + 1, s ^ 1);
        if (more) cp_wait1(); else cp_wait0();
        __syncthreads();

        const uint32_t stb = sb + (uint32_t)s * (GSTAGE_W * 4);
        const uint32_t aHb = stb;
        const uint32_t aLb = stb + A_W * 4;
        const uint32_t bHb = stb + 2 * (A_W * 4);
        const uint32_t bLb = bHb + B_W * 4;

        uint32_t bh[8][2], bl[8][2];
#pragma unroll
        for (int jp = 0; jp < 4; ++jp) {
            const uint32_t ar = (uint32_t)((wn * 64 + jp * 16) * 48) + boffb;
            uint32_t r4[4];
            ldsm_x4(r4, bHb + ar);
            bh[jp * 2][0] = r4[0]; bh[jp * 2][1] = r4[1];
            bh[jp * 2 + 1][0] = r4[2]; bh[jp * 2 + 1][1] = r4[3];
            ldsm_x4(r4, bLb + ar);
            bl[jp * 2][0] = r4[0]; bl[jp * 2][1] = r4[1];
            bl[jp * 2 + 1][0] = r4[2]; bl[jp * 2 + 1][1] = r4[3];
        }
#pragma unroll
        for (int i = 0; i < 4; ++i) {
            const uint32_t ao = (uint32_t)((wm * 64 + i * 16) * 48) + aoffb;
            uint32_t ah4[4], al4[4];
            ldsm_x4(ah4, aHb + ao);
            ldsm_x4(al4, aLb + ao);
#pragma unroll
            for (int j = 0; j < 8; ++j) {
                mma16816(acc[i][j], ah4, bh[j]);
                mma16816(acc[i][j], ah4, bl[j]);
                mma16816(acc[i][j], al4, bh[j]);
            }
        }
        __syncthreads();
    }
}

// ---------------------------------------------------------------------------
// QKV GEMM: epilogue writes bf16 hi/lo Q,K ([bh][n][d]) and transposed V
// ---------------------------------------------------------------------------
__global__ __launch_bounds__(256, 1) void qkv_gemm_hmma() {
    extern __shared__ __align__(16) uint32_t smg[];
    const int mBase = blockIdx.y * 128;
    const int fBase = blockIdx.x * 256;
    float acc[4][8][4];
    GPtrs tp = {g_xh, g_xl, g_wqh, g_wql};
    hmma_mainloop256(smg, tp, mBase, fBase, acc);

    const int tid = threadIdx.x;
    const int lane = tid & 31;
    const int wid = tid >> 5;
    const int wm = wid >> 2, wn = wid & 3;
    const int g = lane >> 2, cc = lane & 3;
    const int which = fBase >> 10;     // uniform per CTA

    if (which == 2) {
#pragma unroll
        for (int i = 0; i < 4; ++i) {
            const int m0 = mBase + wm * 64 + i * 16 + g;
            const int b = m0 >> 11;
            const int n0 = m0 & (NN - 1);
#pragma unroll
            for (int j = 0; j < 8; ++j) {
                const int col = fBase + wn * 64 + j * 8 + cc * 2;
                const int h = (col >> 6) & (HH - 1);
                const int d0 = col & (DD - 1);
                const size_t base = (size_t)(b * HH + h) * DD;
#pragma unroll
                for (int r = 0; r < 4; ++r) {
                    const int dd = d0 + (r & 1);
                    const int nn = n0 + (r >> 1) * 8;
                    float v = acc[i][j][r];
                    __nv_bfloat16 hh = __float2bfloat16(v);
                    __nv_bfloat16 ll = __float2bfloat16(v - __bfloat162float(hh));
                    g_vth[(base + dd) * NN + nn] = hh;
                    g_vtl[(base + dd) * NN + nn] = ll;
                }
            }
        }
    } else {
        const float qs = (which == 0) ? 0.125f * 1.44269504f : 1.0f;
        uint32_t* ph_ = (uint32_t*)((which == 0) ? g_qh : g_kh);
        uint32_t* pl_ = (uint32_t*)((which == 0) ? g_ql : g_kl);
#pragma unroll
        for (int i = 0; i < 4; ++i) {
            const int m0 = mBase + wm * 64 + i * 16 + g;
            const int b = m0 >> 11;
            const int n0 = m0 & (NN - 1);
#pragma unroll
            for (int j = 0; j < 8; ++j) {
                const int col = fBase + wn * 64 + j * 8 + cc * 2;
                const int h = (col >> 6) & (HH - 1);
                const int d0 = col & (DD - 1);
                const size_t rowbase = (size_t)(b * HH + h) * NN;
                float v0 = acc[i][j][0] * qs, v1 = acc[i][j][1] * qs;
                float v2 = acc[i][j][2] * qs, v3 = acc[i][j][3] * qs;
                uint32_t hp0 = pack_bf2(v0, v1);
                float f0 = __int_as_float(hp0 << 16);
                float f1 = __int_as_float(hp0 & 0xFFFF0000u);
                uint32_t lp0 = pack_bf2(v0 - f0, v1 - f1);
                uint32_t hp1 = pack_bf2(v2, v3);
                float f2 = __int_as_float(hp1 << 16);
                float f3 = __int_as_float(hp1 & 0xFFFF0000u);
                uint32_t lp1 = pack_bf2(v2 - f2, v3 - f3);
                ph_[(rowbase + n0) * 32 + (d0 >> 1)] = hp0;
                pl_[(rowbase + n0) * 32 + (d0 >> 1)] = lp0;
                ph_[(rowbase + n0 + 8) * 32 + (d0 >> 1)] = hp1;
                pl_[(rowbase + n0 + 8) * 32 + (d0 >> 1)] = lp1;
            }
        }
    }
}

// ---------------------------------------------------------------------------
// Output projection GEMM
// ---------------------------------------------------------------------------
__global__ __launch_bounds__(256, 1) void out_gemm_hmma(float* __restrict__ Cout) {
    extern __shared__ __align__(16) uint32_t smg[];
    const int mBase = blockIdx.y * 128;
    const int fBase = blockIdx.x * 256;
    float acc[4][8][4];
    GPtrs tp = {g_ah, g_al, g_woh, g_wol};
    hmma_mainloop256(smg, tp, mBase, fBase, acc);

    const int tid = threadIdx.x;
    const int lane = tid & 31;
    const int wid = tid >> 5;
    const int wm = wid >> 2, wn = wid & 3;
    const int g = lane >> 2, cc = lane & 3;

#pragma unroll
    for (int i = 0; i < 4; ++i) {
        const int m0 = mBase + wm * 64 + i * 16 + g;
#pragma unroll
        for (int j = 0; j < 8; ++j) {
            const int col = fBase + wn * 64 + j * 8 + cc * 2;
            float* d1 = Cout + (size_t)m0 * EE + col;
            float* d2 = Cout + (size_t)(m0 + 8) * EE + col;
            *(float2*)d1 = make_float2(acc[i][j][0], acc[i][j][1]);
            *(float2*)d2 = make_float2(acc[i][j][2], acc[i][j][3]);
        }
    }
}

// ---------------------------------------------------------------------------
// Flash attention with HMMA (verified round-5 mainloop; epilogue now emits
// bf16 hi/lo directly -> g_ah/g_al).
// ---------------------------------------------------------------------------
#define KROW 36
#define VROW 68
#define KWORDS (128 * KROW)
#define VWORDS (64 * VROW)
#define STAGEW (2 * KWORDS + 2 * VWORDS)
#define STAGEB (STAGEW * 4)
#define ATTN_SMEM (2 * STAGEB)
#define KBYTES (KWORDS * 4)
#define VBYTES (VWORDS * 4)

__global__ __launch_bounds__(256, 1) void attn_hmma() {
    extern __shared__ __align__(16) uint32_t smdyn[];

    const int bh = blockIdx.x;
    const int qt = blockIdx.y;
    const int tid = threadIdx.x;
    const int lane = tid & 31, wid = tid >> 5;
    const int g = lane >> 2, cc = lane & 3;

    const size_t qoff = (size_t)bh * NN * DD;
    const uint32_t* qhw = (const uint32_t*)g_qh + (qoff >> 1);
    const uint32_t* qlw = (const uint32_t*)g_ql + (qoff >> 1);
    const char* kh_g = (const char*)(g_kh + qoff);
    const char* kl_g = (const char*)(g_kl + qoff);
    const char* vh_g = (const char*)(g_vth + qoff);
    const char* vl_g = (const char*)(g_vtl + qoff);
    const uint32_t sb = smem_u32(smdyn);

    const int r0 = qt * 128 + wid * 16 + g;
    uint32_t qa[4][4], qb[4][4];
#pragma unroll
    for (int kc = 0; kc < 4; ++kc) {
        const int w0 = r0 * 32 + kc * 8 + cc;
        qa[kc][0] = qhw[w0];       qa[kc][1] = qhw[w0 + 256];
        qa[kc][2] = qhw[w0 + 4];   qa[kc][3] = qhw[w0 + 260];
        qb[kc][0] = qlw[w0];       qb[kc][1] = qlw[w0 + 256];
        qb[kc][2] = qlw[w0 + 4];   qb[kc][3] = qlw[w0 + 260];
    }

    float o[8][4];
#pragma unroll
    for (int j = 0; j < 8; ++j) { o[j][0] = o[j][1] = o[j][2] = o[j][3] = 0.f; }
    float m0 = -30000.f, m1 = -30000.f, l0 = 0.f, l1 = 0.f;

    auto load_chunk = [&](int kt, int s) {
        const uint32_t base = sb + s * STAGEB;
#pragma unroll
        for (int i = 0; i < 4; ++i) {
            const int idx = tid + 256 * i;
            const int r = idx >> 3, c = idx & 7;
            const int goff = kt * 16384 + r * 128 + c * 16;
            const uint32_t so = (uint32_t)(r * 144 + c * 16);
            cp16(base + so, kh_g + goff);
            cp16(base + KBYTES + so, kl_g + goff);
        }
#pragma unroll
        for (int i = 0; i < 4; ++i) {
            const int idx = tid + 256 * i;
            const int r = idx >> 4, c = idx & 15;
            const int goff = r * 4096 + kt * 256 + c * 16;
            const uint32_t so = (uint32_t)(r * 272 + c * 16);
            cp16(base + 2 * KBYTES + so, vh_g + goff);
            cp16(base + 2 * KBYTES + VBYTES + so, vl_g + goff);
        }
        cp_commit();
    };

    load_chunk(0, 0);
    cp_wait0();
    __syncthreads();

    for (int ch = 0; ch < 16; ++ch) {
        const int s = ch & 1;
        if (ch + 1 < 16) load_chunk(ch + 1, s ^ 1);

        const uint32_t* sKh = smdyn + s * STAGEW;
        const uint32_t* sKl = sKh + KWORDS;
        const uint32_t* sVh = sKl + KWORDS;
        const uint32_t* sVl = sVh + VWORDS;

        float sc[16][4];
#pragma unroll
        for (int j = 0; j < 16; ++j) { sc[j][0] = sc[j][1] = sc[j][2] = sc[j][3] = 0.f; }
#pragma unroll
        for (int kc = 0; kc < 4; ++kc) {
#pragma unroll
            for (int j = 0; j < 16; ++j) {
                const int bw = (j * 8 + g) * KROW + kc * 8 + cc;
                uint32_t bh_[2] = { sKh[bw], sKh[bw + 4] };
                uint32_t bl_[2] = { sKl[bw], sKl[bw + 4] };
                mma16816(sc[j], qa[kc], bh_);
                mma16816(sc[j], qa[kc], bl_);
                mma16816(sc[j], qb[kc], bh_);
            }
        }

        float cm0 = -30000.f, cm1 = -30000.f;
#pragma unroll
        for (int j = 0; j < 16; ++j) {
            cm0 = fmaxf(cm0, fmaxf(sc[j][0], sc[j][1]));
            cm1 = fmaxf(cm1, fmaxf(sc[j][2], sc[j][3]));
        }
        cm0 = fmaxf(cm0, __shfl_xor_sync(0xffffffffu, cm0, 1));
        cm0 = fmaxf(cm0, __shfl_xor_sync(0xffffffffu, cm0, 2));
        cm1 = fmaxf(cm1, __shfl_xor_sync(0xffffffffu, cm1, 1));
        cm1 = fmaxf(cm1, __shfl_xor_sync(0xffffffffu, cm1, 2));
        const float mn0 = fmaxf(m0, cm0), mn1 = fmaxf(m1, cm1);
        const float a0 = fast_exp2(m0 - mn0), a1 = fast_exp2(m1 - mn1);
        m0 = mn0; m1 = mn1;
#pragma unroll
        for (int j = 0; j < 8; ++j) {
            o[j][0] *= a0; o[j][1] *= a0; o[j][2] *= a1; o[j][3] *= a1;
        }

        float rs0 = 0.f, rs1 = 0.f;
#pragma unroll
        for (int kc2 = 0; kc2 < 8; ++kc2) {
            uint32_t pah[4], pal[4];
#pragma unroll
            for (int t = 0; t < 2; ++t) {
                const int j = kc2 * 2 + t;
                float p0 = fast_exp2(sc[j][0] - m0);
                float p1 = fast_exp2(sc[j][1] - m0);
                float p2 = fast_exp2(sc[j][2] - m1);
                float p3 = fast_exp2(sc[j][3] - m1);
                rs0 += p0 + p1; rs1 += p2 + p3;
                uint32_t h01 = pack_bf2(p0, p1);
                uint32_t h23 = pack_bf2(p2, p3);
                float f0 = __int_as_float(h01 << 16);
                float f1 = __int_as_float(h01 & 0xFFFF0000u);
                float f2 = __int_as_float(h23 << 16);
                float f3 = __int_as_float(h23 & 0xFFFF0000u);
                uint32_t l01 = pack_bf2(p0 - f0, p1 - f1);
                uint32_t l23 = pack_bf2(p2 - f2, p3 - f3);
                pah[2 * t] = h01; pah[2 * t + 1] = h23;
                pal[2 * t] = l01; pal[2 * t + 1] = l23;
            }
#pragma unroll
            for (int j = 0; j < 8; ++j) {
                const int bw = (j * 8 + g) * VROW + kc2 * 8 + cc;
                uint32_t bvh[2] = { sVh[bw], sVh[bw + 4] };
                uint32_t bvl[2] = { sVl[bw], sVl[bw + 4] };
                mma16816(o[j], pah, bvh);
                mma16816(o[j], pal, bvh);
                mma16816(o[j], pah, bvl);
            }
        }
        rs0 += __shfl_xor_sync(0xffffffffu, rs0, 1);
        rs0 += __shfl_xor_sync(0xffffffffu, rs0, 2);
        rs1 += __shfl_xor_sync(0xffffffffu, rs1, 1);
        rs1 += __shfl_xor_sync(0xffffffffu, rs1, 2);
        l0 = l0 * a0 + rs0;
        l1 = l1 * a1 + rs1;

        if (ch + 1 < 16) {
            cp_wait0();
            __syncthreads();
        }
    }

    // Epilogue: write bf16 hi/lo attention output directly (A operand of out-proj)
    const float i0 = 1.f / l0, i1 = 1.f / l1;
    const int b = bh >> 4, h = bh & (HH - 1);
    const int mg = b * NN + r0;
    uint32_t* pah_ = (uint32_t*)g_ah;
    uint32_t* pal_ = (uint32_t*)g_al;
#pragma unroll
    for (int j = 0; j < 8; ++j) {
        float v0 = o[j][0] * i0, v1 = o[j][1] * i0;
        uint32_t hp0 = pack_bf2(v0, v1);
        float f0 = __int_as_float(hp0 << 16);
        float f1 = __int_as_float(hp0 & 0xFFFF0000u);
        uint32_t lp0 = pack_bf2(v0 - f0, v1 - f1);
        float v2 = o[j][2] * i1, v3 = o[j][3] * i1;
        uint32_t hp1 = pack_bf2(v2, v3);
        float f2 = __int_as_float(hp1 << 16);
        float f3 = __int_as_float(hp1 & 0xFFFF0000u);
        uint32_t lp1 = pack_bf2(v2 - f2, v3 - f3);
        const size_t w0 = (size_t)mg * 512 + h * 32 + j * 4 + cc;
        const size_t w1 = (size_t)(mg + 8) * 512 + h * 32 + j * 4 + cc;
        pah_[w0] = hp0; pal_[w0] = lp0;
        pah_[w1] = hp1; pal_[w1] = lp1;
    }
}

// ---------------------------------------------------------------------------
extern "C" void kernel_launch(void* const* d_in, const int* in_sizes, int n_in,
                              void* d_out, int out_size)
{
    const float* x     = (const float*)d_in[0];
    const float* w_qkv = (const float*)d_in[1];
    const float* w_out = (const float*)d_in[2];
    float* out = (float*)d_out;

    cudaFuncSetAttribute(attn_hmma,
                         cudaFuncAttributeMaxDynamicSharedMemorySize, ATTN_SMEM);
    cudaFuncSetAttribute(qkv_gemm_hmma,
                         cudaFuncAttributeMaxDynamicSharedMemorySize, GEMM_SMEM);
    cudaFuncSetAttribute(out_gemm_hmma,
                         cudaFuncAttributeMaxDynamicSharedMemorySize, GEMM_SMEM);

    split_x_kernel<<<(MM * EE / 4) / 256, 256>>>(x);
    split_wq_kernel<<<(FQKV * EE / 4) / 256, 256>>>(w_qkv);
    split_wo_kernel<<<(EE * EE / 4) / 256, 256>>>(w_out);

    {
        dim3 grid(FQKV / 256, MM / 128);   // (12, 64)
        qkv_gemm_hmma<<<grid, 256, GEMM_SMEM>>>();
    }
    {
        dim3 grid(BB * HH, NN / 128);      // (64, 16)
        attn_hmma<<<grid, 256, ATTN_SMEM>>>();
    }
    {
        dim3 grid(EE / 256, MM / 128);     // (4, 64)
        out_gemm_hmma<<<grid, 256, GEMM_SMEM>>>(out);
    }
}

// round 7
// speedup vs baseline: 3.0510x; 1.0107x over previous
#include <cuda_runtime.h>
#include <cuda_bf16.h>
#include <cstdint>

// Problem constants
#define BB 4
#define NN 2048
#define EE 1024
#define HH 16
#define DD 64
#define MM (BB * NN)        // 8192
#define FQKV (3 * EE)       // 3072
#define BHND (64 * 2048 * 64)

// ---------------------------------------------------------------------------
// Scratch (__device__ globals; allocation-free rule)
// ---------------------------------------------------------------------------
__device__ __nv_bfloat16 g_qh[BHND], g_ql[BHND];      // [bh][n][d], prescaled
__device__ __nv_bfloat16 g_kh[BHND], g_kl[BHND];      // [bh][n][d]
__device__ __nv_bfloat16 g_vth[BHND], g_vtl[BHND];    // [bh][d][n] (transposed)

__device__ __nv_bfloat16 g_xh[MM * EE], g_xl[MM * EE];
__device__ __nv_bfloat16 g_wqh[FQKV * EE], g_wql[FQKV * EE];
__device__ __nv_bfloat16 g_woh[EE * EE], g_wol[EE * EE];
__device__ __nv_bfloat16 g_ah[MM * EE], g_al[MM * EE];   // attn out hi/lo

__device__ __forceinline__ float fast_exp2(float x) {
    float y;
    asm("ex2.approx.ftz.f32 %0, %1;" : "=f"(y) : "f"(x));
    return y;
}
__device__ __forceinline__ uint32_t pack_bf2(float lo, float hi) {
    __nv_bfloat162 t = __floats2bfloat162_rn(lo, hi);
    uint32_t r; r = *reinterpret_cast<uint32_t*>(&t); return r;
}
__device__ __forceinline__ uint32_t smem_u32(const void* p) {
    uint32_t a;
    asm("{ .reg .u64 t; cvta.to.shared.u64 t, %1; cvt.u32.u64 %0, t; }"
        : "=r"(a) : "l"(p));
    return a;
}
__device__ __forceinline__ void cp16(uint32_t saddr, const void* g) {
    asm volatile("cp.async.cg.shared.global [%0], [%1], 16;" :: "r"(saddr), "l"(g));
}
__device__ __forceinline__ void cp_commit() {
    asm volatile("cp.async.commit_group;" ::: "memory");
}
__device__ __forceinline__ void cp_wait0() {
    asm volatile("cp.async.wait_group 0;" ::: "memory");
}
__device__ __forceinline__ void cp_wait2() {
    asm volatile("cp.async.wait_group 2;" ::: "memory");
}
__device__ __forceinline__ void ldsm_x4(uint32_t* r, uint32_t addr) {
    asm volatile("ldmatrix.sync.aligned.m8n8.x4.shared.b16 {%0,%1,%2,%3}, [%4];"
        : "=r"(r[0]), "=r"(r[1]), "=r"(r[2]), "=r"(r[3]) : "r"(addr));
}
__device__ __forceinline__ void mma16816(float* c, const uint32_t* a, const uint32_t* b) {
    asm volatile(
        "mma.sync.aligned.m16n8k16.row.col.f32.bf16.bf16.f32 "
        "{%0,%1,%2,%3}, {%4,%5,%6,%7}, {%8,%9}, {%0,%1,%2,%3};"
        : "+f"(c[0]), "+f"(c[1]), "+f"(c[2]), "+f"(c[3])
        : "r"(a[0]), "r"(a[1]), "r"(a[2]), "r"(a[3]),
          "r"(b[0]), "r"(b[1]));
}

// ---------------------------------------------------------------------------
// bf16 hi/lo split kernels
// ---------------------------------------------------------------------------
__device__ __forceinline__ void split4(float4 v, __nv_bfloat16* hdst, __nv_bfloat16* ldst) {
    __nv_bfloat16 h0 = __float2bfloat16(v.x);
    __nv_bfloat16 h1 = __float2bfloat16(v.y);
    __nv_bfloat16 h2 = __float2bfloat16(v.z);
    __nv_bfloat16 h3 = __float2bfloat16(v.w);
    __nv_bfloat16 l0 = __float2bfloat16(v.x - __bfloat162float(h0));
    __nv_bfloat16 l1 = __float2bfloat16(v.y - __bfloat162float(h1));
    __nv_bfloat16 l2 = __float2bfloat16(v.z - __bfloat162float(h2));
    __nv_bfloat16 l3 = __float2bfloat16(v.w - __bfloat162float(h3));
    __nv_bfloat162 hp0 = {h0, h1}, hp1 = {h2, h3};
    __nv_bfloat162 lp0 = {l0, l1}, lp1 = {l2, l3};
    ((__nv_bfloat162*)hdst)[0] = hp0;
    ((__nv_bfloat162*)hdst)[1] = hp1;
    ((__nv_bfloat162*)ldst)[0] = lp0;
    ((__nv_bfloat162*)ldst)[1] = lp1;
}
__global__ void split_x_kernel(const float* __restrict__ src) {
    int i = blockIdx.x * blockDim.x + threadIdx.x;
    float4 v = ((const float4*)src)[i];
    split4(v, &g_xh[i * 4], &g_xl[i * 4]);
}
__global__ void split_wq_kernel(const float* __restrict__ src) {
    int i = blockIdx.x * blockDim.x + threadIdx.x;
    float4 v = ((const float4*)src)[i];
    split4(v, &g_wqh[i * 4], &g_wql[i * 4]);
}
__global__ void split_wo_kernel(const float* __restrict__ src) {
    int i = blockIdx.x * blockDim.x + threadIdx.x;
    float4 v = ((const float4*)src)[i];
    split4(v, &g_woh[i * 4], &g_wol[i * 4]);
}

// ---------------------------------------------------------------------------
// 3-split HMMA GEMM: CTA 128x256, 8 warps (2x4), warp tile 64x64, K-chunk 16.
// 4-stage cp.async pipeline, ONE __syncthreads per chunk.
// ---------------------------------------------------------------------------
#define A_W (128 * 12)             // words per A tile = 1536 (6KB)
#define B_W (256 * 12)             // words per B tile = 3072 (12KB)
#define GSTAGE_W (2 * A_W + 2 * B_W)   // 9216 words = 36KB
#define GSTAGES 4
#define GEMM_SMEM (GSTAGES * GSTAGE_W * 4)   // 147456 B

struct GPtrs { const __nv_bfloat16 *ah, *al, *bh, *bl; };

__device__ __forceinline__ void hmma_mainloop256(
    uint32_t* sm, const GPtrs tp, int mBase, int fBase, float (&acc)[4][8][4])
{
    const int tid = threadIdx.x;
    const int lane = tid & 31;
    const int wid = tid >> 5;
    const int wm = wid >> 2;           // 0..1
    const int wn = wid & 3;            // 0..3
    const uint32_t sb = smem_u32(sm);

#pragma unroll
    for (int i = 0; i < 4; ++i)
#pragma unroll
        for (int j = 0; j < 8; ++j)
#pragma unroll
            for (int r = 0; r < 4; ++r) acc[i][j][r] = 0.f;

    const uint32_t aoffb = (uint32_t)((lane & 15) * 48 + (lane >> 4) * 16);
    const uint32_t boffb = (uint32_t)(((lane & 7) + (lane >> 4) * 8) * 48 + ((lane >> 3) & 1) * 16);

    auto load_chunk = [&](int ch, int s) {
        const int k0 = ch * 16;
        const uint32_t stb = sb + (uint32_t)s * (GSTAGE_W * 4);
#pragma unroll
        for (int t = 0; t < 2; ++t) {
            const int r = tid >> 1;
            const int half = tid & 1;
            const __nv_bfloat16* gp = (t == 0 ? tp.ah : tp.al)
                                    + (size_t)(mBase + r) * EE + k0 + half * 8;
            cp16(stb + (uint32_t)(t * (A_W * 4) + r * 48 + half * 16), gp);
        }
#pragma unroll
        for (int t = 0; t < 4; ++t) {
            const int idx = t * 256 + tid;
            const int split = idx >> 9;
            const int w = idx & 511;
            const int r = w >> 1;
            const int half = w & 1;
            const __nv_bfloat16* gp = (split == 0 ? tp.bh : tp.bl)
                                    + (size_t)(fBase + r) * EE + k0 + half * 8;
            cp16(stb + (uint32_t)(2 * (A_W * 4) + split * (B_W * 4) + r * 48 + half * 16), gp);
        }
        cp_commit();
    };

    load_chunk(0, 0);
    load_chunk(1, 1);
    load_chunk(2, 2);

    for (int ch = 0; ch < 64; ++ch) {
        const int s = ch & 3;
        cp_wait2();                 // chunk ch has landed
        __syncthreads();            // all warps done with stage (ch-1)&3; data visible
        if (ch + 3 < 64) load_chunk(ch + 3, (ch + 3) & 3);

        const uint32_t stb = sb + (uint32_t)s * (GSTAGE_W * 4);
        const uint32_t aHb = stb;
        const uint32_t aLb = stb + A_W * 4;
        const uint32_t bHb = stb + 2 * (A_W * 4);
        const uint32_t bLb = bHb + B_W * 4;

        uint32_t bh[8][2], bl[8][2];
#pragma unroll
        for (int jp = 0; jp < 4; ++jp) {
            const uint32_t ar = (uint32_t)((wn * 64 + jp * 16) * 48) + boffb;
            uint32_t r4[4];
            ldsm_x4(r4, bHb + ar);
            bh[jp * 2][0] = r4[0]; bh[jp * 2][1] = r4[1];
            bh[jp * 2 + 1][0] = r4[2]; bh[jp * 2 + 1][1] = r4[3];
            ldsm_x4(r4, bLb + ar);
            bl[jp * 2][0] = r4[0]; bl[jp * 2][1] = r4[1];
            bl[jp * 2 + 1][0] = r4[2]; bl[jp * 2 + 1][1] = r4[3];
        }
#pragma unroll
        for (int i = 0; i < 4; ++i) {
            const uint32_t ao = (uint32_t)((wm * 64 + i * 16) * 48) + aoffb;
            uint32_t ah4[4], al4[4];
            ldsm_x4(ah4, aHb + ao);
            ldsm_x4(al4, aLb + ao);
#pragma unroll
            for (int j = 0; j < 8; ++j) {
                mma16816(acc[i][j], ah4, bh[j]);
                mma16816(acc[i][j], ah4, bl[j]);
                mma16816(acc[i][j], al4, bh[j]);
            }
        }
    }
}

// ---------------------------------------------------------------------------
// QKV GEMM: epilogue writes bf16 hi/lo Q,K ([bh][n][d]) and transposed V
// ---------------------------------------------------------------------------
__global__ __launch_bounds__(256, 1) void qkv_gemm_hmma() {
    extern __shared__ __align__(16) uint32_t smg[];
    const int mBase = blockIdx.y * 128;
    const int fBase = blockIdx.x * 256;
    float acc[4][8][4];
    GPtrs tp = {g_xh, g_xl, g_wqh, g_wql};
    hmma_mainloop256(smg, tp, mBase, fBase, acc);

    const int tid = threadIdx.x;
    const int lane = tid & 31;
    const int wid = tid >> 5;
    const int wm = wid >> 2, wn = wid & 3;
    const int g = lane >> 2, cc = lane & 3;
    const int which = fBase >> 10;     // uniform per CTA

    if (which == 2) {
#pragma unroll
        for (int i = 0; i < 4; ++i) {
            const int m0 = mBase + wm * 64 + i * 16 + g;
            const int b = m0 >> 11;
            const int n0 = m0 & (NN - 1);
#pragma unroll
            for (int j = 0; j < 8; ++j) {
                const int col = fBase + wn * 64 + j * 8 + cc * 2;
                const int h = (col >> 6) & (HH - 1);
                const int d0 = col & (DD - 1);
                const size_t base = (size_t)(b * HH + h) * DD;
#pragma unroll
                for (int r = 0; r < 4; ++r) {
                    const int dd = d0 + (r & 1);
                    const int nn = n0 + (r >> 1) * 8;
                    float v = acc[i][j][r];
                    __nv_bfloat16 hh = __float2bfloat16(v);
                    __nv_bfloat16 ll = __float2bfloat16(v - __bfloat162float(hh));
                    g_vth[(base + dd) * NN + nn] = hh;
                    g_vtl[(base + dd) * NN + nn] = ll;
                }
            }
        }
    } else {
        const float qs = (which == 0) ? 0.125f * 1.44269504f : 1.0f;
        uint32_t* ph_ = (uint32_t*)((which == 0) ? g_qh : g_kh);
        uint32_t* pl_ = (uint32_t*)((which == 0) ? g_ql : g_kl);
#pragma unroll
        for (int i = 0; i < 4; ++i) {
            const int m0 = mBase + wm * 64 + i * 16 + g;
            const int b = m0 >> 11;
            const int n0 = m0 & (NN - 1);
#pragma unroll
            for (int j = 0; j < 8; ++j) {
                const int col = fBase + wn * 64 + j * 8 + cc * 2;
                const int h = (col >> 6) & (HH - 1);
                const int d0 = col & (DD - 1);
                const size_t rowbase = (size_t)(b * HH + h) * NN;
                float v0 = acc[i][j][0] * qs, v1 = acc[i][j][1] * qs;
                float v2 = acc[i][j][2] * qs, v3 = acc[i][j][3] * qs;
                uint32_t hp0 = pack_bf2(v0, v1);
                float f0 = __int_as_float(hp0 << 16);
                float f1 = __int_as_float(hp0 & 0xFFFF0000u);
                uint32_t lp0 = pack_bf2(v0 - f0, v1 - f1);
                uint32_t hp1 = pack_bf2(v2, v3);
                float f2 = __int_as_float(hp1 << 16);
                float f3 = __int_as_float(hp1 & 0xFFFF0000u);
                uint32_t lp1 = pack_bf2(v2 - f2, v3 - f3);
                ph_[(rowbase + n0) * 32 + (d0 >> 1)] = hp0;
                pl_[(rowbase + n0) * 32 + (d0 >> 1)] = lp0;
                ph_[(rowbase + n0 + 8) * 32 + (d0 >> 1)] = hp1;
                pl_[(rowbase + n0 + 8) * 32 + (d0 >> 1)] = lp1;
            }
        }
    }
}

// ---------------------------------------------------------------------------
// Output projection GEMM
// ---------------------------------------------------------------------------
__global__ __launch_bounds__(256, 1) void out_gemm_hmma(float* __restrict__ Cout) {
    extern __shared__ __align__(16) uint32_t smg[];
    const int mBase = blockIdx.y * 128;
    const int fBase = blockIdx.x * 256;
    float acc[4][8][4];
    GPtrs tp = {g_ah, g_al, g_woh, g_wol};
    hmma_mainloop256(smg, tp, mBase, fBase, acc);

    const int tid = threadIdx.x;
    const int lane = tid & 31;
    const int wid = tid >> 5;
    const int wm = wid >> 2, wn = wid & 3;
    const int g = lane >> 2, cc = lane & 3;

#pragma unroll
    for (int i = 0; i < 4; ++i) {
        const int m0 = mBase + wm * 64 + i * 16 + g;
#pragma unroll
        for (int j = 0; j < 8; ++j) {
            const int col = fBase + wn * 64 + j * 8 + cc * 2;
            float* d1 = Cout + (size_t)m0 * EE + col;
            float* d2 = Cout + (size_t)(m0 + 8) * EE + col;
            *(float2*)d1 = make_float2(acc[i][j][0], acc[i][j][1]);
            *(float2*)d2 = make_float2(acc[i][j][2], acc[i][j][3]);
        }
    }
}

// ---------------------------------------------------------------------------
// Flash attention with HMMA (verified round-5/6 mainloop)
// ---------------------------------------------------------------------------
#define KROW 36
#define VROW 68
#define KWORDS (128 * KROW)
#define VWORDS (64 * VROW)
#define STAGEW (2 * KWORDS + 2 * VWORDS)
#define STAGEB (STAGEW * 4)
#define ATTN_SMEM (2 * STAGEB)
#define KBYTES (KWORDS * 4)
#define VBYTES (VWORDS * 4)

__global__ __launch_bounds__(256, 1) void attn_hmma() {
    extern __shared__ __align__(16) uint32_t smdyn[];

    const int bh = blockIdx.x;
    const int qt = blockIdx.y;
    const int tid = threadIdx.x;
    const int lane = tid & 31, wid = tid >> 5;
    const int g = lane >> 2, cc = lane & 3;

    const size_t qoff = (size_t)bh * NN * DD;
    const uint32_t* qhw = (const uint32_t*)g_qh + (qoff >> 1);
    const uint32_t* qlw = (const uint32_t*)g_ql + (qoff >> 1);
    const char* kh_g = (const char*)(g_kh + qoff);
    const char* kl_g = (const char*)(g_kl + qoff);
    const char* vh_g = (const char*)(g_vth + qoff);
    const char* vl_g = (const char*)(g_vtl + qoff);
    const uint32_t sb = smem_u32(smdyn);

    const int r0 = qt * 128 + wid * 16 + g;
    uint32_t qa[4][4], qb[4][4];
#pragma unroll
    for (int kc = 0; kc < 4; ++kc) {
        const int w0 = r0 * 32 + kc * 8 + cc;
        qa[kc][0] = qhw[w0];       qa[kc][1] = qhw[w0 + 256];
        qa[kc][2] = qhw[w0 + 4];   qa[kc][3] = qhw[w0 + 260];
        qb[kc][0] = qlw[w0];       qb[kc][1] = qlw[w0 + 256];
        qb[kc][2] = qlw[w0 + 4];   qb[kc][3] = qlw[w0 + 260];
    }

    float o[8][4];
#pragma unroll
    for (int j = 0; j < 8; ++j) { o[j][0] = o[j][1] = o[j][2] = o[j][3] = 0.f; }
    float m0 = -30000.f, m1 = -30000.f, l0 = 0.f, l1 = 0.f;

    auto load_chunk = [&](int kt, int s) {
        const uint32_t base = sb + s * STAGEB;
#pragma unroll
        for (int i = 0; i < 4; ++i) {
            const int idx = tid + 256 * i;
            const int r = idx >> 3, c = idx & 7;
            const int goff = kt * 16384 + r * 128 + c * 16;
            const uint32_t so = (uint32_t)(r * 144 + c * 16);
            cp16(base + so, kh_g + goff);
            cp16(base + KBYTES + so, kl_g + goff);
        }
#pragma unroll
        for (int i = 0; i < 4; ++i) {
            const int idx = tid + 256 * i;
            const int r = idx >> 4, c = idx & 15;
            const int goff = r * 4096 + kt * 256 + c * 16;
            const uint32_t so = (uint32_t)(r * 272 + c * 16);
            cp16(base + 2 * KBYTES + so, vh_g + goff);
            cp16(base + 2 * KBYTES + VBYTES + so, vl_g + goff);
        }
        cp_commit();
    };

    load_chunk(0, 0);
    cp_wait0();
    __syncthreads();

    for (int ch = 0; ch < 16; ++ch) {
        const int s = ch & 1;
        if (ch + 1 < 16) load_chunk(ch + 1, s ^ 1);

        const uint32_t* sKh = smdyn + s * STAGEW;
        const uint32_t* sKl = sKh + KWORDS;
        const uint32_t* sVh = sKl + KWORDS;
        const uint32_t* sVl = sVh + VWORDS;

        float sc[16][4];
#pragma unroll
        for (int j = 0; j < 16; ++j) { sc[j][0] = sc[j][1] = sc[j][2] = sc[j][3] = 0.f; }
#pragma unroll
        for (int kc = 0; kc < 4; ++kc) {
#pragma unroll
            for (int j = 0; j < 16; ++j) {
                const int bw = (j * 8 + g) * KROW + kc * 8 + cc;
                uint32_t bh_[2] = { sKh[bw], sKh[bw + 4] };
                uint32_t bl_[2] = { sKl[bw], sKl[bw + 4] };
                mma16816(sc[j], qa[kc], bh_);
                mma16816(sc[j], qa[kc], bl_);
                mma16816(sc[j], qb[kc], bh_);
            }
        }

        float cm0 = -30000.f, cm1 = -30000.f;
#pragma unroll
        for (int j = 0; j < 16; ++j) {
            cm0 = fmaxf(cm0, fmaxf(sc[j][0], sc[j][1]));
            cm1 = fmaxf(cm1, fmaxf(sc[j][2], sc[j][3]));
        }
        cm0 = fmaxf(cm0, __shfl_xor_sync(0xffffffffu, cm0, 1));
        cm0 = fmaxf(cm0, __shfl_xor_sync(0xffffffffu, cm0, 2));
        cm1 = fmaxf(cm1, __shfl_xor_sync(0xffffffffu, cm1, 1));
        cm1 = fmaxf(cm1, __shfl_xor_sync(0xffffffffu, cm1, 2));
        const float mn0 = fmaxf(m0, cm0), mn1 = fmaxf(m1, cm1);
        const float a0 = fast_exp2(m0 - mn0), a1 = fast_exp2(m1 - mn1);
        m0 = mn0; m1 = mn1;
#pragma unroll
        for (int j = 0; j < 8; ++j) {
            o[j][0] *= a0; o[j][1] *= a0; o[j][2] *= a1; o[j][3] *= a1;
        }

        float rs0 = 0.f, rs1 = 0.f;
#pragma unroll
        for (int kc2 = 0; kc2 < 8; ++kc2) {
            uint32_t pah[4], pal[4];
#pragma unroll
            for (int t = 0; t < 2; ++t) {
                const int j = kc2 * 2 + t;
                float p0 = fast_exp2(sc[j][0] - m0);
                float p1 = fast_exp2(sc[j][1] - m0);
                float p2 = fast_exp2(sc[j][2] - m1);
                float p3 = fast_exp2(sc[j][3] - m1);
                rs0 += p0 + p1; rs1 += p2 + p3;
                uint32_t h01 = pack_bf2(p0, p1);
                uint32_t h23 = pack_bf2(p2, p3);
                float f0 = __int_as_float(h01 << 16);
                float f1 = __int_as_float(h01 & 0xFFFF0000u);
                float f2 = __int_as_float(h23 << 16);
                float f3 = __int_as_float(h23 & 0xFFFF0000u);
                uint32_t l01 = pack_bf2(p0 - f0, p1 - f1);
                uint32_t l23 = pack_bf2(p2 - f2, p3 - f3);
                pah[2 * t] = h01; pah[2 * t + 1] = h23;
                pal[2 * t] = l01; pal[2 * t + 1] = l23;
            }
#pragma unroll
            for (int j = 0; j < 8; ++j) {
                const int bw = (j * 8 + g) * VROW + kc2 * 8 + cc;
                uint32_t bvh[2] = { sVh[bw], sVh[bw + 4] };
                uint32_t bvl[2] = { sVl[bw], sVl[bw + 4] };
                mma16816(o[j], pah, bvh);
                mma16816(o[j], pal, bvh);
                mma16816(o[j], pah, bvl);
            }
        }
        rs0 += __shfl_xor_sync(0xffffffffu, rs0, 1);
        rs0 += __shfl_xor_sync(0xffffffffu, rs0, 2);
        rs1 += __shfl_xor_sync(0xffffffffu, rs1, 1);
        rs1 += __shfl_xor_sync(0xffffffffu, rs1, 2);
        l0 = l0 * a0 + rs0;
        l1 = l1 * a1 + rs1;

        if (ch + 1 < 16) {
            cp_wait0();
            __syncthreads();
        }
    }

    const float i0 = 1.f / l0, i1 = 1.f / l1;
    const int b = bh >> 4, h = bh & (HH - 1);
    const int mg = b * NN + r0;
    uint32_t* pah_ = (uint32_t*)g_ah;
    uint32_t* pal_ = (uint32_t*)g_al;
#pragma unroll
    for (int j = 0; j < 8; ++j) {
        float v0 = o[j][0] * i0, v1 = o[j][1] * i0;
        uint32_t hp0 = pack_bf2(v0, v1);
        float f0 = __int_as_float(hp0 << 16);
        float f1 = __int_as_float(hp0 & 0xFFFF0000u);
        uint32_t lp0 = pack_bf2(v0 - f0, v1 - f1);
        float v2 = o[j][2] * i1, v3 = o[j][3] * i1;
        uint32_t hp1 = pack_bf2(v2, v3);
        float f2 = __int_as_float(hp1 << 16);
        float f3 = __int_as_float(hp1 & 0xFFFF0000u);
        uint32_t lp1 = pack_bf2(v2 - f2, v3 - f3);
        const size_t w0 = (size_t)mg * 512 + h * 32 + j * 4 + cc;
        const size_t w1 = (size_t)(mg + 8) * 512 + h * 32 + j * 4 + cc;
        pah_[w0] = hp0; pal_[w0] = lp0;
        pah_[w1] = hp1; pal_[w1] = lp1;
    }
}

// ---------------------------------------------------------------------------
extern "C" void kernel_launch(void* const* d_in, const int* in_sizes, int n_in,
                              void* d_out, int out_size)
{
    const float* x     = (const float*)d_in[0];
    const float* w_qkv = (const float*)d_in[1];
    const float* w_out = (const float*)d_in[2];
    float* out = (float*)d_out;

    cudaFuncSetAttribute(attn_hmma,
                         cudaFuncAttributeMaxDynamicSharedMemorySize, ATTN_SMEM);
    cudaFuncSetAttribute(qkv_gemm_hmma,
                         cudaFuncAttributeMaxDynamicSharedMemorySize, GEMM_SMEM);
    cudaFuncSetAttribute(out_gemm_hmma,
                         cudaFuncAttributeMaxDynamicSharedMemorySize, GEMM_SMEM);

    split_x_kernel<<<(MM * EE / 4) / 256, 256>>>(x);
    split_wq_kernel<<<(FQKV * EE / 4) / 256, 256>>>(w_qkv);
    split_wo_kernel<<<(EE * EE / 4) / 256, 256>>>(w_out);

    {
        dim3 grid(FQKV / 256, MM / 128);   // (12, 64)
        qkv_gemm_hmma<<<grid, 256, GEMM_SMEM>>>();
    }
    {
        dim3 grid(BB * HH, NN / 128);      // (64, 16)
        attn_hmma<<<grid, 256, ATTN_SMEM>>>();
    }
    {
        dim3 grid(EE / 256, MM / 128);     // (4, 64)
        out_gemm_hmma<<<grid, 256, GEMM_SMEM>>>(out);
    }
}

// round 8
// speedup vs baseline: 3.0612x; 1.0033x over previous
#include <cuda_runtime.h>
#include <cuda_bf16.h>
#include <cstdint>

// Problem constants
#define BB 4
#define NN 2048
#define EE 1024
#define HH 16
#define DD 64
#define MM (BB * NN)        // 8192
#define FQKV (3 * EE)       // 3072
#define BHND (64 * 2048 * 64)

// ---------------------------------------------------------------------------
// Scratch (__device__ globals; allocation-free rule)
// ---------------------------------------------------------------------------
__device__ __nv_bfloat16 g_qh[BHND], g_ql[BHND];      // [bh][n][d], prescaled
__device__ __nv_bfloat16 g_kh[BHND], g_kl[BHND];      // [bh][n][d]
__device__ __nv_bfloat16 g_vth[BHND], g_vtl[BHND];    // [bh][d][n] (transposed)

__device__ __nv_bfloat16 g_xh[MM * EE], g_xl[MM * EE];
__device__ __nv_bfloat16 g_wqh[FQKV * EE], g_wql[FQKV * EE];
__device__ __nv_bfloat16 g_woh[EE * EE], g_wol[EE * EE];
__device__ __nv_bfloat16 g_ah[MM * EE], g_al[MM * EE];   // attn out hi/lo

__device__ __forceinline__ float fast_exp2(float x) {
    float y;
    asm("ex2.approx.ftz.f32 %0, %1;" : "=f"(y) : "f"(x));
    return y;
}
__device__ __forceinline__ uint32_t pack_bf2(float lo, float hi) {
    __nv_bfloat162 t = __floats2bfloat162_rn(lo, hi);
    uint32_t r; r = *reinterpret_cast<uint32_t*>(&t); return r;
}
__device__ __forceinline__ uint32_t smem_u32(const void* p) {
    uint32_t a;
    asm("{ .reg .u64 t; cvta.to.shared.u64 t, %1; cvt.u32.u64 %0, t; }"
        : "=r"(a) : "l"(p));
    return a;
}
__device__ __forceinline__ void cp16(uint32_t saddr, const void* g) {
    asm volatile("cp.async.cg.shared.global [%0], [%1], 16;" :: "r"(saddr), "l"(g));
}
__device__ __forceinline__ void cp_commit() {
    asm volatile("cp.async.commit_group;" ::: "memory");
}
__device__ __forceinline__ void cp_wait0() {
    asm volatile("cp.async.wait_group 0;" ::: "memory");
}
__device__ __forceinline__ void cp_wait2() {
    asm volatile("cp.async.wait_group 2;" ::: "memory");
}
__device__ __forceinline__ void ldsm_x4(uint32_t* r, uint32_t addr) {
    asm volatile("ldmatrix.sync.aligned.m8n8.x4.shared.b16 {%0,%1,%2,%3}, [%4];"
        : "=r"(r[0]), "=r"(r[1]), "=r"(r[2]), "=r"(r[3]) : "r"(addr));
}
__device__ __forceinline__ void mma16816(float* c, const uint32_t* a, const uint32_t* b) {
    asm volatile(
        "mma.sync.aligned.m16n8k16.row.col.f32.bf16.bf16.f32 "
        "{%0,%1,%2,%3}, {%4,%5,%6,%7}, {%8,%9}, {%0,%1,%2,%3};"
        : "+f"(c[0]), "+f"(c[1]), "+f"(c[2]), "+f"(c[3])
        : "r"(a[0]), "r"(a[1]), "r"(a[2]), "r"(a[3]),
          "r"(b[0]), "r"(b[1]));
}

// ---------------------------------------------------------------------------
// bf16 hi/lo split kernels
// ---------------------------------------------------------------------------
__device__ __forceinline__ void split4(float4 v, __nv_bfloat16* hdst, __nv_bfloat16* ldst) {
    __nv_bfloat16 h0 = __float2bfloat16(v.x);
    __nv_bfloat16 h1 = __float2bfloat16(v.y);
    __nv_bfloat16 h2 = __float2bfloat16(v.z);
    __nv_bfloat16 h3 = __float2bfloat16(v.w);
    __nv_bfloat16 l0 = __float2bfloat16(v.x - __bfloat162float(h0));
    __nv_bfloat16 l1 = __float2bfloat16(v.y - __bfloat162float(h1));
    __nv_bfloat16 l2 = __float2bfloat16(v.z - __bfloat162float(h2));
    __nv_bfloat16 l3 = __float2bfloat16(v.w - __bfloat162float(h3));
    __nv_bfloat162 hp0 = {h0, h1}, hp1 = {h2, h3};
    __nv_bfloat162 lp0 = {l0, l1}, lp1 = {l2, l3};
    ((__nv_bfloat162*)hdst)[0] = hp0;
    ((__nv_bfloat162*)hdst)[1] = hp1;
    ((__nv_bfloat162*)ldst)[0] = lp0;
    ((__nv_bfloat162*)ldst)[1] = lp1;
}
__global__ void split_x_kernel(const float* __restrict__ src) {
    int i = blockIdx.x * blockDim.x + threadIdx.x;
    float4 v = ((const float4*)src)[i];
    split4(v, &g_xh[i * 4], &g_xl[i * 4]);
}
__global__ void split_wq_kernel(const float* __restrict__ src) {
    int i = blockIdx.x * blockDim.x + threadIdx.x;
    float4 v = ((const float4*)src)[i];
    split4(v, &g_wqh[i * 4], &g_wql[i * 4]);
}
__global__ void split_wo_kernel(const float* __restrict__ src) {
    int i = blockIdx.x * blockDim.x + threadIdx.x;
    float4 v = ((const float4*)src)[i];
    split4(v, &g_woh[i * 4], &g_wol[i * 4]);
}

// ---------------------------------------------------------------------------
// 3-split HMMA GEMM: CTA 128x256, 8 warps (2x4), warp tile 64x64, K-chunk 16.
// 4-stage cp.async pipeline. Pass-major MMA ordering (RAW chains broken).
// ---------------------------------------------------------------------------
#define A_W (128 * 12)             // words per A tile = 1536 (6KB)
#define B_W (256 * 12)             // words per B tile = 3072 (12KB)
#define GSTAGE_W (2 * A_W + 2 * B_W)   // 9216 words = 36KB
#define GSTAGES 4
#define GEMM_SMEM (GSTAGES * GSTAGE_W * 4)   // 147456 B

struct GPtrs { const __nv_bfloat16 *ah, *al, *bh, *bl; };

__device__ __forceinline__ void hmma_mainloop256(
    uint32_t* sm, const GPtrs tp, int mBase, int fBase, float (&acc)[4][8][4])
{
    const int tid = threadIdx.x;
    const int lane = tid & 31;
    const int wid = tid >> 5;
    const int wm = wid >> 2;           // 0..1
    const int wn = wid & 3;            // 0..3
    const uint32_t sb = smem_u32(sm);

#pragma unroll
    for (int i = 0; i < 4; ++i)
#pragma unroll
        for (int j = 0; j < 8; ++j)
#pragma unroll
            for (int r = 0; r < 4; ++r) acc[i][j][r] = 0.f;

    const uint32_t aoffb = (uint32_t)((lane & 15) * 48 + (lane >> 4) * 16);
    const uint32_t boffb = (uint32_t)(((lane & 7) + (lane >> 4) * 8) * 48 + ((lane >> 3) & 1) * 16);

    auto load_chunk = [&](int ch, int s) {
        const int k0 = ch * 16;
        const uint32_t stb = sb + (uint32_t)s * (GSTAGE_W * 4);
#pragma unroll
        for (int t = 0; t < 2; ++t) {
            const int r = tid >> 1;
            const int half = tid & 1;
            const __nv_bfloat16* gp = (t == 0 ? tp.ah : tp.al)
                                    + (size_t)(mBase + r) * EE + k0 + half * 8;
            cp16(stb + (uint32_t)(t * (A_W * 4) + r * 48 + half * 16), gp);
        }
#pragma unroll
        for (int t = 0; t < 4; ++t) {
            const int idx = t * 256 + tid;
            const int split = idx >> 9;
            const int w = idx & 511;
            const int r = w >> 1;
            const int half = w & 1;
            const __nv_bfloat16* gp = (split == 0 ? tp.bh : tp.bl)
                                    + (size_t)(fBase + r) * EE + k0 + half * 8;
            cp16(stb + (uint32_t)(2 * (A_W * 4) + split * (B_W * 4) + r * 48 + half * 16), gp);
        }
        cp_commit();
    };

    load_chunk(0, 0);
    load_chunk(1, 1);
    load_chunk(2, 2);

    for (int ch = 0; ch < 64; ++ch) {
        const int s = ch & 3;
        cp_wait2();                 // chunk ch has landed
        __syncthreads();
        if (ch + 3 < 64) load_chunk(ch + 3, (ch + 3) & 3);

        const uint32_t stb = sb + (uint32_t)s * (GSTAGE_W * 4);
        const uint32_t aHb = stb;
        const uint32_t aLb = stb + A_W * 4;
        const uint32_t bHb = stb + 2 * (A_W * 4);
        const uint32_t bLb = bHb + B_W * 4;

        uint32_t bh[8][2], bl[8][2];
#pragma unroll
        for (int jp = 0; jp < 4; ++jp) {
            const uint32_t ar = (uint32_t)((wn * 64 + jp * 16) * 48) + boffb;
            uint32_t r4[4];
            ldsm_x4(r4, bHb + ar);
            bh[jp * 2][0] = r4[0]; bh[jp * 2][1] = r4[1];
            bh[jp * 2 + 1][0] = r4[2]; bh[jp * 2 + 1][1] = r4[3];
            ldsm_x4(r4, bLb + ar);
            bl[jp * 2][0] = r4[0]; bl[jp * 2][1] = r4[1];
            bl[jp * 2 + 1][0] = r4[2]; bl[jp * 2 + 1][1] = r4[3];
        }
#pragma unroll
        for (int i = 0; i < 4; ++i) {
            const uint32_t ao = (uint32_t)((wm * 64 + i * 16) * 48) + aoffb;
            uint32_t ah4[4], al4[4];
            ldsm_x4(ah4, aHb + ao);
            ldsm_x4(al4, aLb + ao);
            // pass-major: consecutive HMMAs hit different accumulators
#pragma unroll
            for (int j = 0; j < 8; ++j) mma16816(acc[i][j], ah4, bh[j]);
#pragma unroll
            for (int j = 0; j < 8; ++j) mma16816(acc[i][j], ah4, bl[j]);
#pragma unroll
            for (int j = 0; j < 8; ++j) mma16816(acc[i][j], al4, bh[j]);
        }
    }
}

// ---------------------------------------------------------------------------
// QKV GEMM: epilogue writes bf16 hi/lo Q,K ([bh][n][d]) and transposed V
// ---------------------------------------------------------------------------
__global__ __launch_bounds__(256, 1) void qkv_gemm_hmma() {
    extern __shared__ __align__(16) uint32_t smg[];
    const int mBase = blockIdx.y * 128;
    const int fBase = blockIdx.x * 256;
    float acc[4][8][4];
    GPtrs tp = {g_xh, g_xl, g_wqh, g_wql};
    hmma_mainloop256(smg, tp, mBase, fBase, acc);

    const int tid = threadIdx.x;
    const int lane = tid & 31;
    const int wid = tid >> 5;
    const int wm = wid >> 2, wn = wid & 3;
    const int g = lane >> 2, cc = lane & 3;
    const int which = fBase >> 10;     // uniform per CTA

    if (which == 2) {
#pragma unroll
        for (int i = 0; i < 4; ++i) {
            const int m0 = mBase + wm * 64 + i * 16 + g;
            const int b = m0 >> 11;
            const int n0 = m0 & (NN - 1);
#pragma unroll
            for (int j = 0; j < 8; ++j) {
                const int col = fBase + wn * 64 + j * 8 + cc * 2;
                const int h = (col >> 6) & (HH - 1);
                const int d0 = col & (DD - 1);
                const size_t base = (size_t)(b * HH + h) * DD;
#pragma unroll
                for (int r = 0; r < 4; ++r) {
                    const int dd = d0 + (r & 1);
                    const int nn = n0 + (r >> 1) * 8;
                    float v = acc[i][j][r];
                    __nv_bfloat16 hh = __float2bfloat16(v);
                    __nv_bfloat16 ll = __float2bfloat16(v - __bfloat162float(hh));
                    g_vth[(base + dd) * NN + nn] = hh;
                    g_vtl[(base + dd) * NN + nn] = ll;
                }
            }
        }
    } else {
        const float qs = (which == 0) ? 0.125f * 1.44269504f : 1.0f;
        uint32_t* ph_ = (uint32_t*)((which == 0) ? g_qh : g_kh);
        uint32_t* pl_ = (uint32_t*)((which == 0) ? g_ql : g_kl);
#pragma unroll
        for (int i = 0; i < 4; ++i) {
            const int m0 = mBase + wm * 64 + i * 16 + g;
            const int b = m0 >> 11;
            const int n0 = m0 & (NN - 1);
#pragma unroll
            for (int j = 0; j < 8; ++j) {
                const int col = fBase + wn * 64 + j * 8 + cc * 2;
                const int h = (col >> 6) & (HH - 1);
                const int d0 = col & (DD - 1);
                const size_t rowbase = (size_t)(b * HH + h) * NN;
                float v0 = acc[i][j][0] * qs, v1 = acc[i][j][1] * qs;
                float v2 = acc[i][j][2] * qs, v3 = acc[i][j][3] * qs;
                uint32_t hp0 = pack_bf2(v0, v1);
                float f0 = __int_as_float(hp0 << 16);
                float f1 = __int_as_float(hp0 & 0xFFFF0000u);
                uint32_t lp0 = pack_bf2(v0 - f0, v1 - f1);
                uint32_t hp1 = pack_bf2(v2, v3);
                float f2 = __int_as_float(hp1 << 16);
                float f3 = __int_as_float(hp1 & 0xFFFF0000u);
                uint32_t lp1 = pack_bf2(v2 - f2, v3 - f3);
                ph_[(rowbase + n0) * 32 + (d0 >> 1)] = hp0;
                pl_[(rowbase + n0) * 32 + (d0 >> 1)] = lp0;
                ph_[(rowbase + n0 + 8) * 32 + (d0 >> 1)] = hp1;
                pl_[(rowbase + n0 + 8) * 32 + (d0 >> 1)] = lp1;
            }
        }
    }
}

// ---------------------------------------------------------------------------
// Output projection GEMM
// ---------------------------------------------------------------------------
__global__ __launch_bounds__(256, 1) void out_gemm_hmma(float* __restrict__ Cout) {
    extern __shared__ __align__(16) uint32_t smg[];
    const int mBase = blockIdx.y * 128;
    const int fBase = blockIdx.x * 256;
    float acc[4][8][4];
    GPtrs tp = {g_ah, g_al, g_woh, g_wol};
    hmma_mainloop256(smg, tp, mBase, fBase, acc);

    const int tid = threadIdx.x;
    const int lane = tid & 31;
    const int wid = tid >> 5;
    const int wm = wid >> 2, wn = wid & 3;
    const int g = lane >> 2, cc = lane & 3;

#pragma unroll
    for (int i = 0; i < 4; ++i) {
        const int m0 = mBase + wm * 64 + i * 16 + g;
#pragma unroll
        for (int j = 0; j < 8; ++j) {
            const int col = fBase + wn * 64 + j * 8 + cc * 2;
            float* d1 = Cout + (size_t)m0 * EE + col;
            float* d2 = Cout + (size_t)(m0 + 8) * EE + col;
            *(float2*)d1 = make_float2(acc[i][j][0], acc[i][j][1]);
            *(float2*)d2 = make_float2(acc[i][j][2], acc[i][j][3]);
        }
    }
}

// ---------------------------------------------------------------------------
// Flash attention with HMMA; pass-major MMA ordering in QK^T and PV loops.
// ---------------------------------------------------------------------------
#define KROW 36
#define VROW 68
#define KWORDS (128 * KROW)
#define VWORDS (64 * VROW)
#define STAGEW (2 * KWORDS + 2 * VWORDS)
#define STAGEB (STAGEW * 4)
#define ATTN_SMEM (2 * STAGEB)
#define KBYTES (KWORDS * 4)
#define VBYTES (VWORDS * 4)

__global__ __launch_bounds__(256, 1) void attn_hmma() {
    extern __shared__ __align__(16) uint32_t smdyn[];

    const int bh = blockIdx.x;
    const int qt = blockIdx.y;
    const int tid = threadIdx.x;
    const int lane = tid & 31, wid = tid >> 5;
    const int g = lane >> 2, cc = lane & 3;

    const size_t qoff = (size_t)bh * NN * DD;
    const uint32_t* qhw = (const uint32_t*)g_qh + (qoff >> 1);
    const uint32_t* qlw = (const uint32_t*)g_ql + (qoff >> 1);
    const char* kh_g = (const char*)(g_kh + qoff);
    const char* kl_g = (const char*)(g_kl + qoff);
    const char* vh_g = (const char*)(g_vth + qoff);
    const char* vl_g = (const char*)(g_vtl + qoff);
    const uint32_t sb = smem_u32(smdyn);

    const int r0 = qt * 128 + wid * 16 + g;
    uint32_t qa[4][4], qb[4][4];
#pragma unroll
    for (int kc = 0; kc < 4; ++kc) {
        const int w0 = r0 * 32 + kc * 8 + cc;
        qa[kc][0] = qhw[w0];       qa[kc][1] = qhw[w0 + 256];
        qa[kc][2] = qhw[w0 + 4];   qa[kc][3] = qhw[w0 + 260];
        qb[kc][0] = qlw[w0];       qb[kc][1] = qlw[w0 + 256];
        qb[kc][2] = qlw[w0 + 4];   qb[kc][3] = qlw[w0 + 260];
    }

    float o[8][4];
#pragma unroll
    for (int j = 0; j < 8; ++j) { o[j][0] = o[j][1] = o[j][2] = o[j][3] = 0.f; }
    float m0 = -30000.f, m1 = -30000.f, l0 = 0.f, l1 = 0.f;

    auto load_chunk = [&](int kt, int s) {
        const uint32_t base = sb + s * STAGEB;
#pragma unroll
        for (int i = 0; i < 4; ++i) {
            const int idx = tid + 256 * i;
            const int r = idx >> 3, c = idx & 7;
            const int goff = kt * 16384 + r * 128 + c * 16;
            const uint32_t so = (uint32_t)(r * 144 + c * 16);
            cp16(base + so, kh_g + goff);
            cp16(base + KBYTES + so, kl_g + goff);
        }
#pragma unroll
        for (int i = 0; i < 4; ++i) {
            const int idx = tid + 256 * i;
            const int r = idx >> 4, c = idx & 15;
            const int goff = r * 4096 + kt * 256 + c * 16;
            const uint32_t so = (uint32_t)(r * 272 + c * 16);
            cp16(base + 2 * KBYTES + so, vh_g + goff);
            cp16(base + 2 * KBYTES + VBYTES + so, vl_g + goff);
        }
        cp_commit();
    };

    load_chunk(0, 0);
    cp_wait0();
    __syncthreads();

    for (int ch = 0; ch < 16; ++ch) {
        const int s = ch & 1;
        if (ch + 1 < 16) load_chunk(ch + 1, s ^ 1);

        const uint32_t* sKh = smdyn + s * STAGEW;
        const uint32_t* sKl = sKh + KWORDS;
        const uint32_t* sVh = sKl + KWORDS;
        const uint32_t* sVl = sVh + VWORDS;

        float sc[16][4];
#pragma unroll
        for (int j = 0; j < 16; ++j) { sc[j][0] = sc[j][1] = sc[j][2] = sc[j][3] = 0.f; }
#pragma unroll
        for (int kc = 0; kc < 4; ++kc) {
            uint32_t kbh[16][2], kbl[16][2];
#pragma unroll
            for (int j = 0; j < 16; ++j) {
                const int bw = (j * 8 + g) * KROW + kc * 8 + cc;
                kbh[j][0] = sKh[bw]; kbh[j][1] = sKh[bw + 4];
                kbl[j][0] = sKl[bw]; kbl[j][1] = sKl[bw + 4];
            }
            // pass-major: 16 independent HMMAs per pass
#pragma unroll
            for (int j = 0; j < 16; ++j) mma16816(sc[j], qa[kc], kbh[j]);
#pragma unroll
            for (int j = 0; j < 16; ++j) mma16816(sc[j], qa[kc], kbl[j]);
#pragma unroll
            for (int j = 0; j < 16; ++j) mma16816(sc[j], qb[kc], kbh[j]);
        }

        float cm0 = -30000.f, cm1 = -30000.f;
#pragma unroll
        for (int j = 0; j < 16; ++j) {
            cm0 = fmaxf(cm0, fmaxf(sc[j][0], sc[j][1]));
            cm1 = fmaxf(cm1, fmaxf(sc[j][2], sc[j][3]));
        }
        cm0 = fmaxf(cm0, __shfl_xor_sync(0xffffffffu, cm0, 1));
        cm0 = fmaxf(cm0, __shfl_xor_sync(0xffffffffu, cm0, 2));
        cm1 = fmaxf(cm1, __shfl_xor_sync(0xffffffffu, cm1, 1));
        cm1 = fmaxf(cm1, __shfl_xor_sync(0xffffffffu, cm1, 2));
        const float mn0 = fmaxf(m0, cm0), mn1 = fmaxf(m1, cm1);
        const float a0 = fast_exp2(m0 - mn0), a1 = fast_exp2(m1 - mn1);
        m0 = mn0; m1 = mn1;
#pragma unroll
        for (int j = 0; j < 8; ++j) {
            o[j][0] *= a0; o[j][1] *= a0; o[j][2] *= a1; o[j][3] *= a1;
        }

        float rs0 = 0.f, rs1 = 0.f;
#pragma unroll
        for (int kc2 = 0; kc2 < 8; ++kc2) {
            uint32_t pah[4], pal[4];
#pragma unroll
            for (int t = 0; t < 2; ++t) {
                const int j = kc2 * 2 + t;
                float p0 = fast_exp2(sc[j][0] - m0);
                float p1 = fast_exp2(sc[j][1] - m0);
                float p2 = fast_exp2(sc[j][2] - m1);
                float p3 = fast_exp2(sc[j][3] - m1);
                rs0 += p0 + p1; rs1 += p2 + p3;
                uint32_t h01 = pack_bf2(p0, p1);
                uint32_t h23 = pack_bf2(p2, p3);
                float f0 = __int_as_float(h01 << 16);
                float f1 = __int_as_float(h01 & 0xFFFF0000u);
                float f2 = __int_as_float(h23 << 16);
                float f3 = __int_as_float(h23 & 0xFFFF0000u);
                uint32_t l01 = pack_bf2(p0 - f0, p1 - f1);
                uint32_t l23 = pack_bf2(p2 - f2, p3 - f3);
                pah[2 * t] = h01; pah[2 * t + 1] = h23;
                pal[2 * t] = l01; pal[2 * t + 1] = l23;
            }
            uint32_t vbh[8][2], vbl[8][2];
#pragma unroll
            for (int j = 0; j < 8; ++j) {
                const int bw = (j * 8 + g) * VROW + kc2 * 8 + cc;
                vbh[j][0] = sVh[bw]; vbh[j][1] = sVh[bw + 4];
                vbl[j][0] = sVl[bw]; vbl[j][1] = sVl[bw + 4];
            }
#pragma unroll
            for (int j = 0; j < 8; ++j) mma16816(o[j], pah, vbh[j]);
#pragma unroll
            for (int j = 0; j < 8; ++j) mma16816(o[j], pal, vbh[j]);
#pragma unroll
            for (int j = 0; j < 8; ++j) mma16816(o[j], pah, vbl[j]);
        }
        rs0 += __shfl_xor_sync(0xffffffffu, rs0, 1);
        rs0 += __shfl_xor_sync(0xffffffffu, rs0, 2);
        rs1 += __shfl_xor_sync(0xffffffffu, rs1, 1);
        rs1 += __shfl_xor_sync(0xffffffffu, rs1, 2);
        l0 = l0 * a0 + rs0;
        l1 = l1 * a1 + rs1;

        if (ch + 1 < 16) {
            cp_wait0();
            __syncthreads();
        }
    }

    const float i0 = 1.f / l0, i1 = 1.f / l1;
    const int b = bh >> 4, h = bh & (HH - 1);
    const int mg = b * NN + r0;
    uint32_t* pah_ = (uint32_t*)g_ah;
    uint32_t* pal_ = (uint32_t*)g_al;
#pragma unroll
    for (int j = 0; j < 8; ++j) {
        float v0 = o[j][0] * i0, v1 = o[j][1] * i0;
        uint32_t hp0 = pack_bf2(v0, v1);
        float f0 = __int_as_float(hp0 << 16);
        float f1 = __int_as_float(hp0 & 0xFFFF0000u);
        uint32_t lp0 = pack_bf2(v0 - f0, v1 - f1);
        float v2 = o[j][2] * i1, v3 = o[j][3] * i1;
        uint32_t hp1 = pack_bf2(v2, v3);
        float f2 = __int_as_float(hp1 << 16);
        float f3 = __int_as_float(hp1 & 0xFFFF0000u);
        uint32_t lp1 = pack_bf2(v2 - f2, v3 - f3);
        const size_t w0 = (size_t)mg * 512 + h * 32 + j * 4 + cc;
        const size_t w1 = (size_t)(mg + 8) * 512 + h * 32 + j * 4 + cc;
        pah_[w0] = hp0; pal_[w0] = lp0;
        pah_[w1] = hp1; pal_[w1] = lp1;
    }
}

// ---------------------------------------------------------------------------
extern "C" void kernel_launch(void* const* d_in, const int* in_sizes, int n_in,
                              void* d_out, int out_size)
{
    const float* x     = (const float*)d_in[0];
    const float* w_qkv = (const float*)d_in[1];
    const float* w_out = (const float*)d_in[2];
    float* out = (float*)d_out;

    cudaFuncSetAttribute(attn_hmma,
                         cudaFuncAttributeMaxDynamicSharedMemorySize, ATTN_SMEM);
    cudaFuncSetAttribute(qkv_gemm_hmma,
                         cudaFuncAttributeMaxDynamicSharedMemorySize, GEMM_SMEM);
    cudaFuncSetAttribute(out_gemm_hmma,
                         cudaFuncAttributeMaxDynamicSharedMemorySize, GEMM_SMEM);

    split_x_kernel<<<(MM * EE / 4) / 256, 256>>>(x);
    split_wq_kernel<<<(FQKV * EE / 4) / 256, 256>>>(w_qkv);
    split_wo_kernel<<<(EE * EE / 4) / 256, 256>>>(w_out);

    {
        dim3 grid(FQKV / 256, MM / 128);   // (12, 64)
        qkv_gemm_hmma<<<grid, 256, GEMM_SMEM>>>();
    }
    {
        dim3 grid(BB * HH, NN / 128);      // (64, 16)
        attn_hmma<<<grid, 256, ATTN_SMEM>>>();
    }
    {
        dim3 grid(EE / 256, MM / 128);     // (4, 64)
        out_gemm_hmma<<<grid, 256, GEMM_SMEM>>>(out);
    }
}

// round 9
// speedup vs baseline: 3.9507x; 1.2906x over previous
#include <cuda_runtime.h>
#include <cuda_bf16.h>
#include <cstdint>

// Problem constants
#define BB 4
#define NN 2048
#define EE 1024
#define HH 16
#define DD 64
#define MM (BB * NN)        // 8192
#define FQKV (3 * EE)       // 3072
#define BHND (64 * 2048 * 64)

// Blocked-layout block sizes (bytes)
#define XBLK 12288          // A block: [hi 128x48][lo 128x48]
#define WBLK 24576          // B block: [hi 256x48][lo 256x48]
#define KVBLK 71680         // attn chunk: [Kh 18432][Kl 18432][Vh 17408][Vl 17408]

// ---------------------------------------------------------------------------
// Scratch (__device__ globals; allocation-free rule)
// ---------------------------------------------------------------------------
__device__ __nv_bfloat16 g_qh[BHND], g_ql[BHND];      // [bh][n][d], prescaled (linear)

__device__ __align__(16) char g_xb[64 * 64 * XBLK];    // X blocked  [mT][kc]
__device__ __align__(16) char g_ab[64 * 64 * XBLK];    // attn-out blocked [mT][kc]
__device__ __align__(16) char g_wqb[12 * 64 * WBLK];   // Wqkv blocked [fT][kc]
__device__ __align__(16) char g_wob[4 * 64 * WBLK];    // Wout blocked [fT][kc]
__device__ __align__(16) char g_kvb[64 * 16 * KVBLK];  // K/V blocked  [bh][chunk]

__device__ __forceinline__ float fast_exp2(float x) {
    float y;
    asm("ex2.approx.ftz.f32 %0, %1;" : "=f"(y) : "f"(x));
    return y;
}
__device__ __forceinline__ uint32_t pack_bf2(float lo, float hi) {
    __nv_bfloat162 t = __floats2bfloat162_rn(lo, hi);
    uint32_t r; r = *reinterpret_cast<uint32_t*>(&t); return r;
}
__device__ __forceinline__ void split_pair(float a, float b, uint32_t& hw, uint32_t& lw) {
    hw = pack_bf2(a, b);
    float fa = __int_as_float(hw << 16);
    float fb = __int_as_float(hw & 0xFFFF0000u);
    lw = pack_bf2(a - fa, b - fb);
}
__device__ __forceinline__ uint32_t smem_u32(const void* p) {
    uint32_t a;
    asm("{ .reg .u64 t; cvta.to.shared.u64 t, %1; cvt.u32.u64 %0, t; }"
        : "=r"(a) : "l"(p));
    return a;
}
__device__ __forceinline__ void mbar_init(uint32_t a, uint32_t cnt) {
    asm volatile("mbarrier.init.shared.b64 [%0], %1;" :: "r"(a), "r"(cnt) : "memory");
}
__device__ __forceinline__ void mbar_expect(uint32_t a, uint32_t bytes) {
    asm volatile("mbarrier.arrive.expect_tx.shared.b64 _, [%0], %1;"
                 :: "r"(a), "r"(bytes) : "memory");
}
__device__ __forceinline__ void mbar_wait(uint32_t addr, uint32_t parity) {
    asm volatile(
        "{\n\t.reg .pred P1;\n\t"
        "WAIT_LOOP_%=:\n\t"
        "mbarrier.try_wait.parity.acquire.cta.shared::cta.b64 P1, [%0], %1, 0x989680;\n\t"
        "@P1 bra.uni WAIT_DONE_%=;\n\t"
        "bra.uni WAIT_LOOP_%=;\n\t"
        "WAIT_DONE_%=:\n\t}"
        :: "r"(addr), "r"(parity) : "memory");
}
__device__ __forceinline__ void bulk_g2s(uint32_t dst, const void* src,
                                         uint32_t bytes, uint32_t mbar) {
    asm volatile(
        "cp.async.bulk.shared::cluster.global.mbarrier::complete_tx::bytes "
        "[%0], [%1], %2, [%3];"
        :: "r"(dst), "l"(src), "r"(bytes), "r"(mbar) : "memory");
}
__device__ __forceinline__ void fence_proxy() {
    asm volatile("fence.proxy.async.shared::cta;" ::: "memory");
}
__device__ __forceinline__ void ldsm_x4(uint32_t* r, uint32_t addr) {
    asm volatile("ldmatrix.sync.aligned.m8n8.x4.shared.b16 {%0,%1,%2,%3}, [%4];"
        : "=r"(r[0]), "=r"(r[1]), "=r"(r[2]), "=r"(r[3]) : "r"(addr));
}
__device__ __forceinline__ void mma16816(float* c, const uint32_t* a, const uint32_t* b) {
    asm volatile(
        "mma.sync.aligned.m16n8k16.row.col.f32.bf16.bf16.f32 "
        "{%0,%1,%2,%3}, {%4,%5,%6,%7}, {%8,%9}, {%0,%1,%2,%3};"
        : "+f"(c[0]), "+f"(c[1]), "+f"(c[2]), "+f"(c[3])
        : "r"(a[0]), "r"(a[1]), "r"(a[2]), "r"(a[3]),
          "r"(b[0]), "r"(b[1]));
}

// ---------------------------------------------------------------------------
// Split kernels -> blocked layouts
// ---------------------------------------------------------------------------
__global__ __launch_bounds__(256) void split_x_blocked(const float* __restrict__ x) {
    const int mT = blockIdx.x, kc = blockIdx.y;
    const int t = threadIdx.x;
    const int r = t >> 1, hf = t & 1;
    const float* src = x + ((size_t)(mT * 128 + r)) * EE + kc * 16 + hf * 8;
    float4 v0 = *(const float4*)src;
    float4 v1 = *(const float4*)(src + 4);
    uint32_t h0, h1, h2, h3, l0, l1, l2, l3;
    split_pair(v0.x, v0.y, h0, l0);
    split_pair(v0.z, v0.w, h1, l1);
    split_pair(v1.x, v1.y, h2, l2);
    split_pair(v1.z, v1.w, h3, l3);
    char* blk = g_xb + ((size_t)mT * 64 + kc) * XBLK + r * 48 + hf * 16;
    *(uint4*)blk = make_uint4(h0, h1, h2, h3);
    *(uint4*)(blk + 6144) = make_uint4(l0, l1, l2, l3);
}
__global__ __launch_bounds__(512) void split_wq_blocked(const float* __restrict__ w) {
    const int fT = blockIdx.x, kc = blockIdx.y;
    const int t = threadIdx.x;
    const int r = t >> 1, hf = t & 1;
    const float* src = w + ((size_t)(fT * 256 + r)) * EE + kc * 16 + hf * 8;
    float4 v0 = *(const float4*)src;
    float4 v1 = *(const float4*)(src + 4);
    uint32_t h0, h1, h2, h3, l0, l1, l2, l3;
    split_pair(v0.x, v0.y, h0, l0);
    split_pair(v0.z, v0.w, h1, l1);
    split_pair(v1.x, v1.y, h2, l2);
    split_pair(v1.z, v1.w, h3, l3);
    char* blk = g_wqb + ((size_t)fT * 64 + kc) * WBLK + r * 48 + hf * 16;
    *(uint4*)blk = make_uint4(h0, h1, h2, h3);
    *(uint4*)(blk + 12288) = make_uint4(l0, l1, l2, l3);
}
__global__ __launch_bounds__(512) void split_wo_blocked(const float* __restrict__ w) {
    const int fT = blockIdx.x, kc = blockIdx.y;
    const int t = threadIdx.x;
    const int r = t >> 1, hf = t & 1;
    const float* src = w + ((size_t)(fT * 256 + r)) * EE + kc * 16 + hf * 8;
    float4 v0 = *(const float4*)src;
    float4 v1 = *(const float4*)(src + 4);
    uint32_t h0, h1, h2, h3, l0, l1, l2, l3;
    split_pair(v0.x, v0.y, h0, l0);
    split_pair(v0.z, v0.w, h1, l1);
    split_pair(v1.x, v1.y, h2, l2);
    split_pair(v1.z, v1.w, h3, l3);
    char* blk = g_wob + ((size_t)fT * 64 + kc) * WBLK + r * 48 + hf * 16;
    *(uint4*)blk = make_uint4(h0, h1, h2, h3);
    *(uint4*)(blk + 12288) = make_uint4(l0, l1, l2, l3);
}

// ---------------------------------------------------------------------------
// 3-split HMMA GEMM: CTA 128x256, 8 warps, warp tile 64x64, K-chunk 16.
// 4-stage pipeline fed by cp.async.bulk (2 bulks/chunk) + mbarriers.
// ---------------------------------------------------------------------------
#define A_W (128 * 12)
#define B_W (256 * 12)
#define GSTAGE_W (2 * A_W + 2 * B_W)        // 9216 words = 36KB
#define GEMM_SMEM (4 * GSTAGE_W * 4 + 64)   // + mbarriers

__device__ __forceinline__ void hmma_mainloop256(
    uint32_t* sm, const char* aBlocks, const char* bBlocks, float (&acc)[4][8][4])
{
    const int tid = threadIdx.x;
    const int lane = tid & 31;
    const int wid = tid >> 5;
    const int wm = wid >> 2;
    const int wn = wid & 3;
    const uint32_t sb = smem_u32(sm);
    const uint32_t mb = sb + 4 * GSTAGE_W * 4;

#pragma unroll
    for (int i = 0; i < 4; ++i)
#pragma unroll
        for (int j = 0; j < 8; ++j)
#pragma unroll
            for (int r = 0; r < 4; ++r) acc[i][j][r] = 0.f;

    const uint32_t aoffb = (uint32_t)((lane & 15) * 48 + (lane >> 4) * 16);
    const uint32_t boffb = (uint32_t)(((lane & 7) + (lane >> 4) * 8) * 48 + ((lane >> 3) & 1) * 16);

    if (tid == 0) {
#pragma unroll
        for (int s = 0; s < 4; ++s) mbar_init(mb + 8 * s, 1);
    }
    fence_proxy();
    __syncthreads();

    auto issue = [&](int ch) {
        const int s = ch & 3;
        const uint32_t m = mb + 8 * s;
        const uint32_t d = sb + (uint32_t)s * (GSTAGE_W * 4);
        mbar_expect(m, XBLK + WBLK);
        bulk_g2s(d, aBlocks + (size_t)ch * XBLK, XBLK, m);
        bulk_g2s(d + XBLK, bBlocks + (size_t)ch * WBLK, WBLK, m);
    };

    if (tid == 0) { issue(0); issue(1); issue(2); }

    for (int ch = 0; ch < 64; ++ch) {
        const int s = ch & 3;
        __syncthreads();                 // all warps done with stage (ch+3)&3 old data
        if (tid == 0 && ch + 3 < 64) issue(ch + 3);
        mbar_wait(mb + 8 * s, (ch >> 2) & 1);

        const uint32_t stb = sb + (uint32_t)s * (GSTAGE_W * 4);
        const uint32_t aHb = stb;
        const uint32_t aLb = stb + A_W * 4;
        const uint32_t bHb = stb + 2 * (A_W * 4);
        const uint32_t bLb = bHb + B_W * 4;

        uint32_t bh[8][2], bl[8][2];
#pragma unroll
        for (int jp = 0; jp < 4; ++jp) {
            const uint32_t ar = (uint32_t)((wn * 64 + jp * 16) * 48) + boffb;
            uint32_t r4[4];
            ldsm_x4(r4, bHb + ar);
            bh[jp * 2][0] = r4[0]; bh[jp * 2][1] = r4[1];
            bh[jp * 2 + 1][0] = r4[2]; bh[jp * 2 + 1][1] = r4[3];
            ldsm_x4(r4, bLb + ar);
            bl[jp * 2][0] = r4[0]; bl[jp * 2][1] = r4[1];
            bl[jp * 2 + 1][0] = r4[2]; bl[jp * 2 + 1][1] = r4[3];
        }
#pragma unroll
        for (int i = 0; i < 4; ++i) {
            const uint32_t ao = (uint32_t)((wm * 64 + i * 16) * 48) + aoffb;
            uint32_t ah4[4], al4[4];
            ldsm_x4(ah4, aHb + ao);
            ldsm_x4(al4, aLb + ao);
#pragma unroll
            for (int j = 0; j < 8; ++j) mma16816(acc[i][j], ah4, bh[j]);
#pragma unroll
            for (int j = 0; j < 8; ++j) mma16816(acc[i][j], ah4, bl[j]);
#pragma unroll
            for (int j = 0; j < 8; ++j) mma16816(acc[i][j], al4, bh[j]);
        }
    }
}

// ---------------------------------------------------------------------------
// QKV GEMM: epilogue writes Q (linear bf16 hi/lo) and blocked K/V (g_kvb)
// ---------------------------------------------------------------------------
__global__ __launch_bounds__(256, 1) void qkv_gemm_hmma() {
    extern __shared__ __align__(16) uint32_t smg[];
    const int mBase = blockIdx.y * 128;
    const int fBase = blockIdx.x * 256;
    float acc[4][8][4];
    hmma_mainloop256(smg, g_xb + (size_t)blockIdx.y * 64 * XBLK,
                     g_wqb + (size_t)blockIdx.x * 64 * WBLK, acc);

    const int tid = threadIdx.x;
    const int lane = tid & 31;
    const int wid = tid >> 5;
    const int wm = wid >> 2, wn = wid & 3;
    const int g = lane >> 2, cc = lane & 3;
    const int which = fBase >> 10;

    if (which == 2) {
        // V -> g_kvb blocked: [bh][chunk] offset 36864 + split*17408 + d*272 + (n&127)*2
#pragma unroll
        for (int i = 0; i < 4; ++i) {
            const int m0 = mBase + wm * 64 + i * 16 + g;
            const int b = m0 >> 11;
            const int n0 = m0 & (NN - 1);
#pragma unroll
            for (int j = 0; j < 8; ++j) {
                const int col = fBase + wn * 64 + j * 8 + cc * 2;
                const int h = (col >> 6) & (HH - 1);
                const int d0 = col & (DD - 1);
                char* blk = g_kvb + ((size_t)((b * HH + h) * 16) + (n0 >> 7)) * KVBLK + 36864;
#pragma unroll
                for (int r = 0; r < 4; ++r) {
                    const int dd = d0 + (r & 1);
                    const int nn = (n0 & 127) + (r >> 1) * 8;
                    float v = acc[i][j][r];
                    __nv_bfloat16 hh = __float2bfloat16(v);
                    __nv_bfloat16 ll = __float2bfloat16(v - __bfloat162float(hh));
                    *(__nv_bfloat16*)(blk + dd * 272 + nn * 2) = hh;
                    *(__nv_bfloat16*)(blk + 17408 + dd * 272 + nn * 2) = ll;
                }
            }
        }
    } else if (which == 1) {
        // K -> g_kvb blocked: split*18432 + (n&127)*144 + d*2
#pragma unroll
        for (int i = 0; i < 4; ++i) {
            const int m0 = mBase + wm * 64 + i * 16 + g;
            const int b = m0 >> 11;
            const int n0 = m0 & (NN - 1);
#pragma unroll
            for (int j = 0; j < 8; ++j) {
                const int col = fBase + wn * 64 + j * 8 + cc * 2;
                const int h = (col >> 6) & (HH - 1);
                const int d0 = col & (DD - 1);
                char* blk = g_kvb + ((size_t)((b * HH + h) * 16) + (n0 >> 7)) * KVBLK;
                const int rr = n0 & 127;
                uint32_t hp0, lp0, hp1, lp1;
                split_pair(acc[i][j][0], acc[i][j][1], hp0, lp0);
                split_pair(acc[i][j][2], acc[i][j][3], hp1, lp1);
                *(uint32_t*)(blk + rr * 144 + d0 * 2) = hp0;
                *(uint32_t*)(blk + 18432 + rr * 144 + d0 * 2) = lp0;
                *(uint32_t*)(blk + (rr + 8) * 144 + d0 * 2) = hp1;
                *(uint32_t*)(blk + 18432 + (rr + 8) * 144 + d0 * 2) = lp1;
            }
        }
    } else {
        // Q -> linear hi/lo, prescaled by D^-0.5 * log2(e)
        const float qs = 0.125f * 1.44269504f;
        uint32_t* ph_ = (uint32_t*)g_qh;
        uint32_t* pl_ = (uint32_t*)g_ql;
#pragma unroll
        for (int i = 0; i < 4; ++i) {
            const int m0 = mBase + wm * 64 + i * 16 + g;
            const int b = m0 >> 11;
            const int n0 = m0 & (NN - 1);
#pragma unroll
            for (int j = 0; j < 8; ++j) {
                const int col = fBase + wn * 64 + j * 8 + cc * 2;
                const int h = (col >> 6) & (HH - 1);
                const int d0 = col & (DD - 1);
                const size_t rowbase = (size_t)(b * HH + h) * NN;
                uint32_t hp0, lp0, hp1, lp1;
                split_pair(acc[i][j][0] * qs, acc[i][j][1] * qs, hp0, lp0);
                split_pair(acc[i][j][2] * qs, acc[i][j][3] * qs, hp1, lp1);
                ph_[(rowbase + n0) * 32 + (d0 >> 1)] = hp0;
                pl_[(rowbase + n0) * 32 + (d0 >> 1)] = lp0;
                ph_[(rowbase + n0 + 8) * 32 + (d0 >> 1)] = hp1;
                pl_[(rowbase + n0 + 8) * 32 + (d0 >> 1)] = lp1;
            }
        }
    }
}

// ---------------------------------------------------------------------------
// Output projection GEMM
// ---------------------------------------------------------------------------
__global__ __launch_bounds__(256, 1) void out_gemm_hmma(float* __restrict__ Cout) {
    extern __shared__ __align__(16) uint32_t smg[];
    const int mBase = blockIdx.y * 128;
    const int fBase = blockIdx.x * 256;
    float acc[4][8][4];
    hmma_mainloop256(smg, g_ab + (size_t)blockIdx.y * 64 * XBLK,
                     g_wob + (size_t)blockIdx.x * 64 * WBLK, acc);

    const int tid = threadIdx.x;
    const int lane = tid & 31;
    const int wid = tid >> 5;
    const int wm = wid >> 2, wn = wid & 3;
    const int g = lane >> 2, cc = lane & 3;

#pragma unroll
    for (int i = 0; i < 4; ++i) {
        const int m0 = mBase + wm * 64 + i * 16 + g;
#pragma unroll
        for (int j = 0; j < 8; ++j) {
            const int col = fBase + wn * 64 + j * 8 + cc * 2;
            float* d1 = Cout + (size_t)m0 * EE + col;
            float* d2 = Cout + (size_t)(m0 + 8) * EE + col;
            *(float2*)d1 = make_float2(acc[i][j][0], acc[i][j][1]);
            *(float2*)d2 = make_float2(acc[i][j][2], acc[i][j][3]);
        }
    }
}

// ---------------------------------------------------------------------------
// Flash attention with HMMA; bulk-copy KV chunks; epilogue -> g_ab blocked.
// ---------------------------------------------------------------------------
#define KROW 36
#define VROW 68
#define KWORDS (128 * KROW)
#define VWORDS (64 * VROW)
#define STAGEW (2 * KWORDS + 2 * VWORDS)
#define STAGEB (STAGEW * 4)                 // 71680 = KVBLK
#define ATTN_SMEM (2 * STAGEB + 64)
#define KBYTES (KWORDS * 4)                 // 18432
#define VBYTES (VWORDS * 4)                 // 17408

__global__ __launch_bounds__(256, 1) void attn_hmma() {
    extern __shared__ __align__(16) uint32_t smdyn[];

    const int bh = blockIdx.x;
    const int qt = blockIdx.y;
    const int tid = threadIdx.x;
    const int lane = tid & 31, wid = tid >> 5;
    const int g = lane >> 2, cc = lane & 3;

    const size_t qoff = (size_t)bh * NN * DD;
    const uint32_t* qhw = (const uint32_t*)g_qh + (qoff >> 1);
    const uint32_t* qlw = (const uint32_t*)g_ql + (qoff >> 1);
    const char* kvsrc = g_kvb + (size_t)bh * 16 * KVBLK;
    const uint32_t sb = smem_u32(smdyn);
    const uint32_t mb = sb + 2 * STAGEB;

    const int r0 = qt * 128 + wid * 16 + g;
    uint32_t qa[4][4], qb[4][4];
#pragma unroll
    for (int kc = 0; kc < 4; ++kc) {
        const int w0 = r0 * 32 + kc * 8 + cc;
        qa[kc][0] = qhw[w0];       qa[kc][1] = qhw[w0 + 256];
        qa[kc][2] = qhw[w0 + 4];   qa[kc][3] = qhw[w0 + 260];
        qb[kc][0] = qlw[w0];       qb[kc][1] = qlw[w0 + 256];
        qb[kc][2] = qlw[w0 + 4];   qb[kc][3] = qlw[w0 + 260];
    }

    float o[8][4];
#pragma unroll
    for (int j = 0; j < 8; ++j) { o[j][0] = o[j][1] = o[j][2] = o[j][3] = 0.f; }
    float m0 = -30000.f, m1 = -30000.f, l0 = 0.f, l1 = 0.f;

    if (tid == 0) { mbar_init(mb, 1); mbar_init(mb + 8, 1); }
    fence_proxy();
    __syncthreads();

    auto issue = [&](int kt) {
        const int s = kt & 1;
        const uint32_t m = mb + 8 * s;
        const uint32_t d = sb + (uint32_t)s * STAGEB;
        const char* src = kvsrc + (size_t)kt * KVBLK;
        mbar_expect(m, KVBLK);
        bulk_g2s(d, src, KBYTES, m);
        bulk_g2s(d + KBYTES, src + KBYTES, KBYTES, m);
        bulk_g2s(d + 2 * KBYTES, src + 2 * KBYTES, VBYTES, m);
        bulk_g2s(d + 2 * KBYTES + VBYTES, src + 2 * KBYTES + VBYTES, VBYTES, m);
    };

    if (tid == 0) issue(0);

    for (int ch = 0; ch < 16; ++ch) {
        const int s = ch & 1;
        __syncthreads();
        if (tid == 0 && ch + 1 < 16) issue(ch + 1);
        mbar_wait(mb + 8 * s, (ch >> 1) & 1);

        const uint32_t* sKh = smdyn + s * STAGEW;
        const uint32_t* sKl = sKh + KWORDS;
        const uint32_t* sVh = sKl + KWORDS;
        const uint32_t* sVl = sVh + VWORDS;

        float sc[16][4];
#pragma unroll
        for (int j = 0; j < 16; ++j) { sc[j][0] = sc[j][1] = sc[j][2] = sc[j][3] = 0.f; }
#pragma unroll
        for (int kc = 0; kc < 4; ++kc) {
            uint32_t kbh[16][2], kbl[16][2];
#pragma unroll
            for (int j = 0; j < 16; ++j) {
                const int bw = (j * 8 + g) * KROW + kc * 8 + cc;
                kbh[j][0] = sKh[bw]; kbh[j][1] = sKh[bw + 4];
                kbl[j][0] = sKl[bw]; kbl[j][1] = sKl[bw + 4];
            }
#pragma unroll
            for (int j = 0; j < 16; ++j) mma16816(sc[j], qa[kc], kbh[j]);
#pragma unroll
            for (int j = 0; j < 16; ++j) mma16816(sc[j], qa[kc], kbl[j]);
#pragma unroll
            for (int j = 0; j < 16; ++j) mma16816(sc[j], qb[kc], kbh[j]);
        }

        float cm0 = -30000.f, cm1 = -30000.f;
#pragma unroll
        for (int j = 0; j < 16; ++j) {
            cm0 = fmaxf(cm0, fmaxf(sc[j][0], sc[j][1]));
            cm1 = fmaxf(cm1, fmaxf(sc[j][2], sc[j][3]));
        }
        cm0 = fmaxf(cm0, __shfl_xor_sync(0xffffffffu, cm0, 1));
        cm0 = fmaxf(cm0, __shfl_xor_sync(0xffffffffu, cm0, 2));
        cm1 = fmaxf(cm1, __shfl_xor_sync(0xffffffffu, cm1, 1));
        cm1 = fmaxf(cm1, __shfl_xor_sync(0xffffffffu, cm1, 2));
        const float mn0 = fmaxf(m0, cm0), mn1 = fmaxf(m1, cm1);
        const float a0 = fast_exp2(m0 - mn0), a1 = fast_exp2(m1 - mn1);
        m0 = mn0; m1 = mn1;
#pragma unroll
        for (int j = 0; j < 8; ++j) {
            o[j][0] *= a0; o[j][1] *= a0; o[j][2] *= a1; o[j][3] *= a1;
        }

        float rs0 = 0.f, rs1 = 0.f;
#pragma unroll
        for (int kc2 = 0; kc2 < 8; ++kc2) {
            uint32_t pah[4], pal[4];
#pragma unroll
            for (int t = 0; t < 2; ++t) {
                const int j = kc2 * 2 + t;
                float p0 = fast_exp2(sc[j][0] - m0);
                float p1 = fast_exp2(sc[j][1] - m0);
                float p2 = fast_exp2(sc[j][2] - m1);
                float p3 = fast_exp2(sc[j][3] - m1);
                rs0 += p0 + p1; rs1 += p2 + p3;
                uint32_t h01, l01, h23, l23;
                split_pair(p0, p1, h01, l01);
                split_pair(p2, p3, h23, l23);
                pah[2 * t] = h01; pah[2 * t + 1] = h23;
                pal[2 * t] = l01; pal[2 * t + 1] = l23;
            }
            uint32_t vbh[8][2], vbl[8][2];
#pragma unroll
            for (int j = 0; j < 8; ++j) {
                const int bw = (j * 8 + g) * VROW + kc2 * 8 + cc;
                vbh[j][0] = sVh[bw]; vbh[j][1] = sVh[bw + 4];
                vbl[j][0] = sVl[bw]; vbl[j][1] = sVl[bw + 4];
            }
#pragma unroll
            for (int j = 0; j < 8; ++j) mma16816(o[j], pah, vbh[j]);
#pragma unroll
            for (int j = 0; j < 8; ++j) mma16816(o[j], pal, vbh[j]);
#pragma unroll
            for (int j = 0; j < 8; ++j) mma16816(o[j], pah, vbl[j]);
        }
        rs0 += __shfl_xor_sync(0xffffffffu, rs0, 1);
        rs0 += __shfl_xor_sync(0xffffffffu, rs0, 2);
        rs1 += __shfl_xor_sync(0xffffffffu, rs1, 1);
        rs1 += __shfl_xor_sync(0xffffffffu, rs1, 2);
        l0 = l0 * a0 + rs0;
        l1 = l1 * a1 + rs1;
    }

    // Epilogue: bf16 hi/lo attention output -> g_ab blocked (out-proj A operand)
    const float i0 = 1.f / l0, i1 = 1.f / l1;
    const int b = bh >> 4, h = bh & (HH - 1);
    const int mg = b * NN + r0;
    const int mT = mg >> 7;
    const int rr = mg & 127;
#pragma unroll
    for (int j = 0; j < 8; ++j) {
        const int w = h * 32 + j * 4 + cc;     // word index in 512-word row; k = 2w
        uint32_t hp0, lp0, hp1, lp1;
        split_pair(o[j][0] * i0, o[j][1] * i0, hp0, lp0);
        split_pair(o[j][2] * i1, o[j][3] * i1, hp1, lp1);
        char* blk = g_ab + ((size_t)mT * 64 + (w >> 3)) * XBLK;
        const int off = (w & 7) * 4;
        *(uint32_t*)(blk + rr * 48 + off) = hp0;
        *(uint32_t*)(blk + 6144 + rr * 48 + off) = lp0;
        *(uint32_t*)(blk + (rr + 8) * 48 + off) = hp1;
        *(uint32_t*)(blk + 6144 + (rr + 8) * 48 + off) = lp1;
    }
}

// ---------------------------------------------------------------------------
extern "C" void kernel_launch(void* const* d_in, const int* in_sizes, int n_in,
                              void* d_out, int out_size)
{
    const float* x     = (const float*)d_in[0];
    const float* w_qkv = (const float*)d_in[1];
    const float* w_out = (const float*)d_in[2];
    float* out = (float*)d_out;

    cudaFuncSetAttribute(attn_hmma,
                         cudaFuncAttributeMaxDynamicSharedMemorySize, ATTN_SMEM);
    cudaFuncSetAttribute(qkv_gemm_hmma,
                         cudaFuncAttributeMaxDynamicSharedMemorySize, GEMM_SMEM);
    cudaFuncSetAttribute(out_gemm_hmma,
                         cudaFuncAttributeMaxDynamicSharedMemorySize, GEMM_SMEM);

    split_x_blocked<<<dim3(64, 64), 256>>>(x);
    split_wq_blocked<<<dim3(12, 64), 512>>>(w_qkv);
    split_wo_blocked<<<dim3(4, 64), 512>>>(w_out);

    {
        dim3 grid(FQKV / 256, MM / 128);   // (12, 64)
        qkv_gemm_hmma<<<grid, 256, GEMM_SMEM>>>();
    }
    {
        dim3 grid(BB * HH, NN / 128);      // (64, 16)
        attn_hmma<<<grid, 256, ATTN_SMEM>>>();
    }
    {
        dim3 grid(EE / 256, MM / 128);     // (4, 64)
        out_gemm_hmma<<<grid, 256, GEMM_SMEM>>>(out);
    }
}

// round 10
// speedup vs baseline: 4.0604x; 1.0278x over previous
#include <cuda_runtime.h>
#include <cuda_bf16.h>
#include <cstdint>

// Problem constants
#define BB 4
#define NN 2048
#define EE 1024
#define HH 16
#define DD 64
#define MM (BB * NN)        // 8192
#define FQKV (3 * EE)       // 3072
#define BHND (64 * 2048 * 64)

// Blocked-layout block sizes (bytes)
#define XBLK 12288          // A block: [hi 128x48][lo 128x48]
#define WBLK 24576          // B block: [hi 256x48][lo 256x48]
#define KVBLK 71680         // attn chunk: [Kh 18432][Kl 18432][Vh 17408][Vl 17408]

// ---------------------------------------------------------------------------
// Scratch (__device__ globals; allocation-free rule)
// ---------------------------------------------------------------------------
__device__ __nv_bfloat16 g_qh[BHND], g_ql[BHND];      // [bh][n][d], prescaled (linear)

__device__ __align__(16) char g_xb[64 * 64 * XBLK];    // X blocked  [mT][kc]
__device__ __align__(16) char g_ab[64 * 64 * XBLK];    // attn-out blocked [mT][kc]
__device__ __align__(16) char g_wqb[12 * 64 * WBLK];   // Wqkv blocked [fT][kc]
__device__ __align__(16) char g_wob[4 * 64 * WBLK];    // Wout blocked [fT][kc]
__device__ __align__(16) char g_kvb[64 * 16 * KVBLK];  // K/V blocked  [bh][chunk]

__device__ __forceinline__ float fast_exp2(float x) {
    float y;
    asm("ex2.approx.ftz.f32 %0, %1;" : "=f"(y) : "f"(x));
    return y;
}
__device__ __forceinline__ uint32_t pack_bf2(float lo, float hi) {
    __nv_bfloat162 t = __floats2bfloat162_rn(lo, hi);
    uint32_t r; r = *reinterpret_cast<uint32_t*>(&t); return r;
}
__device__ __forceinline__ void split_pair(float a, float b, uint32_t& hw, uint32_t& lw) {
    hw = pack_bf2(a, b);
    float fa = __int_as_float(hw << 16);
    float fb = __int_as_float(hw & 0xFFFF0000u);
    lw = pack_bf2(a - fa, b - fb);
}
__device__ __forceinline__ uint32_t smem_u32(const void* p) {
    uint32_t a;
    asm("{ .reg .u64 t; cvta.to.shared.u64 t, %1; cvt.u32.u64 %0, t; }"
        : "=r"(a) : "l"(p));
    return a;
}
__device__ __forceinline__ void mbar_init(uint32_t a, uint32_t cnt) {
    asm volatile("mbarrier.init.shared.b64 [%0], %1;" :: "r"(a), "r"(cnt) : "memory");
}
__device__ __forceinline__ void mbar_expect(uint32_t a, uint32_t bytes) {
    asm volatile("mbarrier.arrive.expect_tx.shared.b64 _, [%0], %1;"
                 :: "r"(a), "r"(bytes) : "memory");
}
__device__ __forceinline__ void mbar_wait(uint32_t addr, uint32_t parity) {
    asm volatile(
        "{\n\t.reg .pred P1;\n\t"
        "WAIT_LOOP_%=:\n\t"
        "mbarrier.try_wait.parity.acquire.cta.shared::cta.b64 P1, [%0], %1, 0x989680;\n\t"
        "@P1 bra.uni WAIT_DONE_%=;\n\t"
        "bra.uni WAIT_LOOP_%=;\n\t"
        "WAIT_DONE_%=:\n\t}"
        :: "r"(addr), "r"(parity) : "memory");
}
__device__ __forceinline__ void bulk_g2s(uint32_t dst, const void* src,
                                         uint32_t bytes, uint32_t mbar) {
    asm volatile(
        "cp.async.bulk.shared::cluster.global.mbarrier::complete_tx::bytes "
        "[%0], [%1], %2, [%3];"
        :: "r"(dst), "l"(src), "r"(bytes), "r"(mbar) : "memory");
}
__device__ __forceinline__ void fence_proxy() {
    asm volatile("fence.proxy.async.shared::cta;" ::: "memory");
}
__device__ __forceinline__ void ldsm_x4(uint32_t* r, uint32_t addr) {
    asm volatile("ldmatrix.sync.aligned.m8n8.x4.shared.b16 {%0,%1,%2,%3}, [%4];"
        : "=r"(r[0]), "=r"(r[1]), "=r"(r[2]), "=r"(r[3]) : "r"(addr));
}
__device__ __forceinline__ void mma16816(float* c, const uint32_t* a, const uint32_t* b) {
    asm volatile(
        "mma.sync.aligned.m16n8k16.row.col.f32.bf16.bf16.f32 "
        "{%0,%1,%2,%3}, {%4,%5,%6,%7}, {%8,%9}, {%0,%1,%2,%3};"
        : "+f"(c[0]), "+f"(c[1]), "+f"(c[2]), "+f"(c[3])
        : "r"(a[0]), "r"(a[1]), "r"(a[2]), "r"(a[3]),
          "r"(b[0]), "r"(b[1]));
}

// ---------------------------------------------------------------------------
// Split kernels -> blocked layouts
// ---------------------------------------------------------------------------
__global__ __launch_bounds__(256) void split_x_blocked(const float* __restrict__ x) {
    const int mT = blockIdx.x, kc = blockIdx.y;
    const int t = threadIdx.x;
    const int r = t >> 1, hf = t & 1;
    const float* src = x + ((size_t)(mT * 128 + r)) * EE + kc * 16 + hf * 8;
    float4 v0 = *(const float4*)src;
    float4 v1 = *(const float4*)(src + 4);
    uint32_t h0, h1, h2, h3, l0, l1, l2, l3;
    split_pair(v0.x, v0.y, h0, l0);
    split_pair(v0.z, v0.w, h1, l1);
    split_pair(v1.x, v1.y, h2, l2);
    split_pair(v1.z, v1.w, h3, l3);
    char* blk = g_xb + ((size_t)mT * 64 + kc) * XBLK + r * 48 + hf * 16;
    *(uint4*)blk = make_uint4(h0, h1, h2, h3);
    *(uint4*)(blk + 6144) = make_uint4(l0, l1, l2, l3);
}
__global__ __launch_bounds__(512) void split_wq_blocked(const float* __restrict__ w) {
    const int fT = blockIdx.x, kc = blockIdx.y;
    const int t = threadIdx.x;
    const int r = t >> 1, hf = t & 1;
    const float* src = w + ((size_t)(fT * 256 + r)) * EE + kc * 16 + hf * 8;
    float4 v0 = *(const float4*)src;
    float4 v1 = *(const float4*)(src + 4);
    uint32_t h0, h1, h2, h3, l0, l1, l2, l3;
    split_pair(v0.x, v0.y, h0, l0);
    split_pair(v0.z, v0.w, h1, l1);
    split_pair(v1.x, v1.y, h2, l2);
    split_pair(v1.z, v1.w, h3, l3);
    char* blk = g_wqb + ((size_t)fT * 64 + kc) * WBLK + r * 48 + hf * 16;
    *(uint4*)blk = make_uint4(h0, h1, h2, h3);
    *(uint4*)(blk + 12288) = make_uint4(l0, l1, l2, l3);
}
__global__ __launch_bounds__(512) void split_wo_blocked(const float* __restrict__ w) {
    const int fT = blockIdx.x, kc = blockIdx.y;
    const int t = threadIdx.x;
    const int r = t >> 1, hf = t & 1;
    const float* src = w + ((size_t)(fT * 256 + r)) * EE + kc * 16 + hf * 8;
    float4 v0 = *(const float4*)src;
    float4 v1 = *(const float4*)(src + 4);
    uint32_t h0, h1, h2, h3, l0, l1, l2, l3;
    split_pair(v0.x, v0.y, h0, l0);
    split_pair(v0.z, v0.w, h1, l1);
    split_pair(v1.x, v1.y, h2, l2);
    split_pair(v1.z, v1.w, h3, l3);
    char* blk = g_wob + ((size_t)fT * 64 + kc) * WBLK + r * 48 + hf * 16;
    *(uint4*)blk = make_uint4(h0, h1, h2, h3);
    *(uint4*)(blk + 12288) = make_uint4(l0, l1, l2, l3);
}

// ---------------------------------------------------------------------------
// 3-split HMMA GEMM: CTA 128x256, 8 warps, warp tile 64x64.
// Stage = 2 K-chunks (72KB), 3 stages, 2 bulk ops / stage, 1 sync / 2 chunks.
// ---------------------------------------------------------------------------
#define A_W (128 * 12)
#define B_W (256 * 12)
#define G2A_B (2 * XBLK)                     // A two-chunk bytes = 24576
#define G2B_B (2 * WBLK)                     // B two-chunk bytes = 49152
#define G2STAGE_B (G2A_B + G2B_B)            // 73728
#define GEMM_SMEM (3 * G2STAGE_B + 64)       // 221248

__device__ __forceinline__ void hmma_mainloop256(
    uint32_t* sm, const char* aBlocks, const char* bBlocks, float (&acc)[4][8][4])
{
    const int tid = threadIdx.x;
    const int lane = tid & 31;
    const int wid = tid >> 5;
    const int wm = wid >> 2;
    const int wn = wid & 3;
    const uint32_t sb = smem_u32(sm);
    const uint32_t mb = sb + 3 * G2STAGE_B;

#pragma unroll
    for (int i = 0; i < 4; ++i)
#pragma unroll
        for (int j = 0; j < 8; ++j)
#pragma unroll
            for (int r = 0; r < 4; ++r) acc[i][j][r] = 0.f;

    const uint32_t aoffb = (uint32_t)((lane & 15) * 48 + (lane >> 4) * 16);
    const uint32_t boffb = (uint32_t)(((lane & 7) + (lane >> 4) * 8) * 48 + ((lane >> 3) & 1) * 16);

    if (tid == 0) {
#pragma unroll
        for (int s = 0; s < 3; ++s) mbar_init(mb + 8 * s, 1);
    }
    fence_proxy();
    __syncthreads();

    auto issue = [&](int it) {
        const int s = it % 3;
        const uint32_t m = mb + 8 * s;
        const uint32_t d = sb + (uint32_t)s * G2STAGE_B;
        mbar_expect(m, G2STAGE_B);
        bulk_g2s(d, aBlocks + (size_t)it * G2A_B, G2A_B, m);
        bulk_g2s(d + G2A_B, bBlocks + (size_t)it * G2B_B, G2B_B, m);
    };

    if (tid == 0) { issue(0); issue(1); }

    for (int it = 0; it < 32; ++it) {
        const int s = it % 3;
        __syncthreads();                 // all warps done with iteration it-1
        if (tid == 0 && it + 2 < 32) issue(it + 2);
        mbar_wait(mb + 8 * s, (it / 3) & 1);

        const uint32_t stb = sb + (uint32_t)s * G2STAGE_B;
#pragma unroll
        for (int c = 0; c < 2; ++c) {
            const uint32_t aHb = stb + (uint32_t)c * XBLK;
            const uint32_t aLb = aHb + 6144;
            const uint32_t bHb = stb + G2A_B + (uint32_t)c * WBLK;
            const uint32_t bLb = bHb + 12288;

            uint32_t bh[8][2], bl[8][2];
#pragma unroll
            for (int jp = 0; jp < 4; ++jp) {
                const uint32_t ar = (uint32_t)((wn * 64 + jp * 16) * 48) + boffb;
                uint32_t r4[4];
                ldsm_x4(r4, bHb + ar);
                bh[jp * 2][0] = r4[0]; bh[jp * 2][1] = r4[1];
                bh[jp * 2 + 1][0] = r4[2]; bh[jp * 2 + 1][1] = r4[3];
                ldsm_x4(r4, bLb + ar);
                bl[jp * 2][0] = r4[0]; bl[jp * 2][1] = r4[1];
                bl[jp * 2 + 1][0] = r4[2]; bl[jp * 2 + 1][1] = r4[3];
            }
#pragma unroll
            for (int i = 0; i < 4; ++i) {
                const uint32_t ao = (uint32_t)((wm * 64 + i * 16) * 48) + aoffb;
                uint32_t ah4[4], al4[4];
                ldsm_x4(ah4, aHb + ao);
                ldsm_x4(al4, aLb + ao);
#pragma unroll
                for (int j = 0; j < 8; ++j) mma16816(acc[i][j], ah4, bh[j]);
#pragma unroll
                for (int j = 0; j < 8; ++j) mma16816(acc[i][j], ah4, bl[j]);
#pragma unroll
                for (int j = 0; j < 8; ++j) mma16816(acc[i][j], al4, bh[j]);
            }
        }
    }
}

// ---------------------------------------------------------------------------
// QKV GEMM: epilogue writes Q (linear bf16 hi/lo) and blocked K/V (g_kvb)
// ---------------------------------------------------------------------------
__global__ __launch_bounds__(256, 1) void qkv_gemm_hmma() {
    extern __shared__ __align__(16) uint32_t smg[];
    const int mBase = blockIdx.y * 128;
    const int fBase = blockIdx.x * 256;
    float acc[4][8][4];
    hmma_mainloop256(smg, g_xb + (size_t)blockIdx.y * 64 * XBLK,
                     g_wqb + (size_t)blockIdx.x * 64 * WBLK, acc);

    const int tid = threadIdx.x;
    const int lane = tid & 31;
    const int wid = tid >> 5;
    const int wm = wid >> 2, wn = wid & 3;
    const int g = lane >> 2, cc = lane & 3;
    const int which = fBase >> 10;

    if (which == 2) {
#pragma unroll
        for (int i = 0; i < 4; ++i) {
            const int m0 = mBase + wm * 64 + i * 16 + g;
            const int b = m0 >> 11;
            const int n0 = m0 & (NN - 1);
#pragma unroll
            for (int j = 0; j < 8; ++j) {
                const int col = fBase + wn * 64 + j * 8 + cc * 2;
                const int h = (col >> 6) & (HH - 1);
                const int d0 = col & (DD - 1);
                char* blk = g_kvb + ((size_t)((b * HH + h) * 16) + (n0 >> 7)) * KVBLK + 36864;
#pragma unroll
                for (int r = 0; r < 4; ++r) {
                    const int dd = d0 + (r & 1);
                    const int nn = (n0 & 127) + (r >> 1) * 8;
                    float v = acc[i][j][r];
                    __nv_bfloat16 hh = __float2bfloat16(v);
                    __nv_bfloat16 ll = __float2bfloat16(v - __bfloat162float(hh));
                    *(__nv_bfloat16*)(blk + dd * 272 + nn * 2) = hh;
                    *(__nv_bfloat16*)(blk + 17408 + dd * 272 + nn * 2) = ll;
                }
            }
        }
    } else if (which == 1) {
#pragma unroll
        for (int i = 0; i < 4; ++i) {
            const int m0 = mBase + wm * 64 + i * 16 + g;
            const int b = m0 >> 11;
            const int n0 = m0 & (NN - 1);
#pragma unroll
            for (int j = 0; j < 8; ++j) {
                const int col = fBase + wn * 64 + j * 8 + cc * 2;
                const int h = (col >> 6) & (HH - 1);
                const int d0 = col & (DD - 1);
                char* blk = g_kvb + ((size_t)((b * HH + h) * 16) + (n0 >> 7)) * KVBLK;
                const int rr = n0 & 127;
                uint32_t hp0, lp0, hp1, lp1;
                split_pair(acc[i][j][0], acc[i][j][1], hp0, lp0);
                split_pair(acc[i][j][2], acc[i][j][3], hp1, lp1);
                *(uint32_t*)(blk + rr * 144 + d0 * 2) = hp0;
                *(uint32_t*)(blk + 18432 + rr * 144 + d0 * 2) = lp0;
                *(uint32_t*)(blk + (rr + 8) * 144 + d0 * 2) = hp1;
                *(uint32_t*)(blk + 18432 + (rr + 8) * 144 + d0 * 2) = lp1;
            }
        }
    } else {
        const float qs = 0.125f * 1.44269504f;
        uint32_t* ph_ = (uint32_t*)g_qh;
        uint32_t* pl_ = (uint32_t*)g_ql;
#pragma unroll
        for (int i = 0; i < 4; ++i) {
            const int m0 = mBase + wm * 64 + i * 16 + g;
            const int b = m0 >> 11;
            const int n0 = m0 & (NN - 1);
#pragma unroll
            for (int j = 0; j < 8; ++j) {
                const int col = fBase + wn * 64 + j * 8 + cc * 2;
                const int h = (col >> 6) & (HH - 1);
                const int d0 = col & (DD - 1);
                const size_t rowbase = (size_t)(b * HH + h) * NN;
                uint32_t hp0, lp0, hp1, lp1;
                split_pair(acc[i][j][0] * qs, acc[i][j][1] * qs, hp0, lp0);
                split_pair(acc[i][j][2] * qs, acc[i][j][3] * qs, hp1, lp1);
                ph_[(rowbase + n0) * 32 + (d0 >> 1)] = hp0;
                pl_[(rowbase + n0) * 32 + (d0 >> 1)] = lp0;
                ph_[(rowbase + n0 + 8) * 32 + (d0 >> 1)] = hp1;
                pl_[(rowbase + n0 + 8) * 32 + (d0 >> 1)] = lp1;
            }
        }
    }
}

// ---------------------------------------------------------------------------
// Output projection GEMM
// ---------------------------------------------------------------------------
__global__ __launch_bounds__(256, 1) void out_gemm_hmma(float* __restrict__ Cout) {
    extern __shared__ __align__(16) uint32_t smg[];
    const int mBase = blockIdx.y * 128;
    const int fBase = blockIdx.x * 256;
    float acc[4][8][4];
    hmma_mainloop256(smg, g_ab + (size_t)blockIdx.y * 64 * XBLK,
                     g_wob + (size_t)blockIdx.x * 64 * WBLK, acc);

    const int tid = threadIdx.x;
    const int lane = tid & 31;
    const int wid = tid >> 5;
    const int wm = wid >> 2, wn = wid & 3;
    const int g = lane >> 2, cc = lane & 3;

#pragma unroll
    for (int i = 0; i < 4; ++i) {
        const int m0 = mBase + wm * 64 + i * 16 + g;
#pragma unroll
        for (int j = 0; j < 8; ++j) {
            const int col = fBase + wn * 64 + j * 8 + cc * 2;
            float* d1 = Cout + (size_t)m0 * EE + col;
            float* d2 = Cout + (size_t)(m0 + 8) * EE + col;
            *(float2*)d1 = make_float2(acc[i][j][0], acc[i][j][1]);
            *(float2*)d2 = make_float2(acc[i][j][2], acc[i][j][3]);
        }
    }
}

// ---------------------------------------------------------------------------
// Flash attention with HMMA; bulk-copy KV chunks; epilogue -> g_ab blocked.
// ---------------------------------------------------------------------------
#define KROW 36
#define VROW 68
#define KWORDS (128 * KROW)
#define VWORDS (64 * VROW)
#define STAGEW (2 * KWORDS + 2 * VWORDS)
#define STAGEB (STAGEW * 4)                 // 71680 = KVBLK
#define ATTN_SMEM (2 * STAGEB + 64)
#define KBYTES (KWORDS * 4)                 // 18432
#define VBYTES (VWORDS * 4)                 // 17408

__global__ __launch_bounds__(256, 1) void attn_hmma() {
    extern __shared__ __align__(16) uint32_t smdyn[];

    const int bh = blockIdx.x;
    const int qt = blockIdx.y;
    const int tid = threadIdx.x;
    const int lane = tid & 31, wid = tid >> 5;
    const int g = lane >> 2, cc = lane & 3;

    const size_t qoff = (size_t)bh * NN * DD;
    const uint32_t* qhw = (const uint32_t*)g_qh + (qoff >> 1);
    const uint32_t* qlw = (const uint32_t*)g_ql + (qoff >> 1);
    const char* kvsrc = g_kvb + (size_t)bh * 16 * KVBLK;
    const uint32_t sb = smem_u32(smdyn);
    const uint32_t mb = sb + 2 * STAGEB;

    const int r0 = qt * 128 + wid * 16 + g;
    uint32_t qa[4][4], qb[4][4];
#pragma unroll
    for (int kc = 0; kc < 4; ++kc) {
        const int w0 = r0 * 32 + kc * 8 + cc;
        qa[kc][0] = qhw[w0];       qa[kc][1] = qhw[w0 + 256];
        qa[kc][2] = qhw[w0 + 4];   qa[kc][3] = qhw[w0 + 260];
        qb[kc][0] = qlw[w0];       qb[kc][1] = qlw[w0 + 256];
        qb[kc][2] = qlw[w0 + 4];   qb[kc][3] = qlw[w0 + 260];
    }

    float o[8][4];
#pragma unroll
    for (int j = 0; j < 8; ++j) { o[j][0] = o[j][1] = o[j][2] = o[j][3] = 0.f; }
    float m0 = -30000.f, m1 = -30000.f, l0 = 0.f, l1 = 0.f;

    if (tid == 0) { mbar_init(mb, 1); mbar_init(mb + 8, 1); }
    fence_proxy();
    __syncthreads();

    auto issue = [&](int kt) {
        const int s = kt & 1;
        const uint32_t m = mb + 8 * s;
        const uint32_t d = sb + (uint32_t)s * STAGEB;
        const char* src = kvsrc + (size_t)kt * KVBLK;
        mbar_expect(m, KVBLK);
        bulk_g2s(d, src, KBYTES, m);
        bulk_g2s(d + KBYTES, src + KBYTES, KBYTES, m);
        bulk_g2s(d + 2 * KBYTES, src + 2 * KBYTES, VBYTES, m);
        bulk_g2s(d + 2 * KBYTES + VBYTES, src + 2 * KBYTES + VBYTES, VBYTES, m);
    };

    if (tid == 0) issue(0);

    for (int ch = 0; ch < 16; ++ch) {
        const int s = ch & 1;
        __syncthreads();
        if (tid == 0 && ch + 1 < 16) issue(ch + 1);
        mbar_wait(mb + 8 * s, (ch >> 1) & 1);

        const uint32_t* sKh = smdyn + s * STAGEW;
        const uint32_t* sKl = sKh + KWORDS;
        const uint32_t* sVh = sKl + KWORDS;
        const uint32_t* sVl = sVh + VWORDS;

        float sc[16][4];
#pragma unroll
        for (int j = 0; j < 16; ++j) { sc[j][0] = sc[j][1] = sc[j][2] = sc[j][3] = 0.f; }
#pragma unroll
        for (int kc = 0; kc < 4; ++kc) {
            uint32_t kbh[16][2], kbl[16][2];
#pragma unroll
            for (int j = 0; j < 16; ++j) {
                const int bw = (j * 8 + g) * KROW + kc * 8 + cc;
                kbh[j][0] = sKh[bw]; kbh[j][1] = sKh[bw + 4];
                kbl[j][0] = sKl[bw]; kbl[j][1] = sKl[bw + 4];
            }
#pragma unroll
            for (int j = 0; j < 16; ++j) mma16816(sc[j], qa[kc], kbh[j]);
#pragma unroll
            for (int j = 0; j < 16; ++j) mma16816(sc[j], qa[kc], kbl[j]);
#pragma unroll
            for (int j = 0; j < 16; ++j) mma16816(sc[j], qb[kc], kbh[j]);
        }

        float cm0 = -30000.f, cm1 = -30000.f;
#pragma unroll
        for (int j = 0; j < 16; ++j) {
            cm0 = fmaxf(cm0, fmaxf(sc[j][0], sc[j][1]));
            cm1 = fmaxf(cm1, fmaxf(sc[j][2], sc[j][3]));
        }
        cm0 = fmaxf(cm0, __shfl_xor_sync(0xffffffffu, cm0, 1));
        cm0 = fmaxf(cm0, __shfl_xor_sync(0xffffffffu, cm0, 2));
        cm1 = fmaxf(cm1, __shfl_xor_sync(0xffffffffu, cm1, 1));
        cm1 = fmaxf(cm1, __shfl_xor_sync(0xffffffffu, cm1, 2));
        const float mn0 = fmaxf(m0, cm0), mn1 = fmaxf(m1, cm1);
        const float a0 = fast_exp2(m0 - mn0), a1 = fast_exp2(m1 - mn1);
        m0 = mn0; m1 = mn1;
#pragma unroll
        for (int j = 0; j < 8; ++j) {
            o[j][0] *= a0; o[j][1] *= a0; o[j][2] *= a1; o[j][3] *= a1;
        }

        float rs0 = 0.f, rs1 = 0.f;
#pragma unroll
        for (int kc2 = 0; kc2 < 8; ++kc2) {
            uint32_t pah[4], pal[4];
#pragma unroll
            for (int t = 0; t < 2; ++t) {
                const int j = kc2 * 2 + t;
                float p0 = fast_exp2(sc[j][0] - m0);
                float p1 = fast_exp2(sc[j][1] - m0);
                float p2 = fast_exp2(sc[j][2] - m1);
                float p3 = fast_exp2(sc[j][3] - m1);
                rs0 += p0 + p1; rs1 += p2 + p3;
                uint32_t h01, l01, h23, l23;
                split_pair(p0, p1, h01, l01);
                split_pair(p2, p3, h23, l23);
                pah[2 * t] = h01; pah[2 * t + 1] = h23;
                pal[2 * t] = l01; pal[2 * t + 1] = l23;
            }
            uint32_t vbh[8][2], vbl[8][2];
#pragma unroll
            for (int j = 0; j < 8; ++j) {
                const int bw = (j * 8 + g) * VROW + kc2 * 8 + cc;
                vbh[j][0] = sVh[bw]; vbh[j][1] = sVh[bw + 4];
                vbl[j][0] = sVl[bw]; vbl[j][1] = sVl[bw + 4];
            }
#pragma unroll
            for (int j = 0; j < 8; ++j) mma16816(o[j], pah, vbh[j]);
#pragma unroll
            for (int j = 0; j < 8; ++j) mma16816(o[j], pal, vbh[j]);
#pragma unroll
            for (int j = 0; j < 8; ++j) mma16816(o[j], pah, vbl[j]);
        }
        rs0 += __shfl_xor_sync(0xffffffffu, rs0, 1);
        rs0 += __shfl_xor_sync(0xffffffffu, rs0, 2);
        rs1 += __shfl_xor_sync(0xffffffffu, rs1, 1);
        rs1 += __shfl_xor_sync(0xffffffffu, rs1, 2);
        l0 = l0 * a0 + rs0;
        l1 = l1 * a1 + rs1;
    }

    // Epilogue: bf16 hi/lo attention output -> g_ab blocked (out-proj A operand)
    const float i0 = 1.f / l0, i1 = 1.f / l1;
    const int b = bh >> 4, h = bh & (HH - 1);
    const int mg = b * NN + r0;
    const int mT = mg >> 7;
    const int rr = mg & 127;
#pragma unroll
    for (int j = 0; j < 8; ++j) {
        const int w = h * 32 + j * 4 + cc;
        uint32_t hp0, lp0, hp1, lp1;
        split_pair(o[j][0] * i0, o[j][1] * i0, hp0, lp0);
        split_pair(o[j][2] * i1, o[j][3] * i1, hp1, lp1);
        char* blk = g_ab + ((size_t)mT * 64 + (w >> 3)) * XBLK;
        const int off = (w & 7) * 4;
        *(uint32_t*)(blk + rr * 48 + off) = hp0;
        *(uint32_t*)(blk + 6144 + rr * 48 + off) = lp0;
        *(uint32_t*)(blk + (rr + 8) * 48 + off) = hp1;
        *(uint32_t*)(blk + 6144 + (rr + 8) * 48 + off) = lp1;
    }
}

// ---------------------------------------------------------------------------
extern "C" void kernel_launch(void* const* d_in, const int* in_sizes, int n_in,
                              void* d_out, int out_size)
{
    const float* x     = (const float*)d_in[0];
    const float* w_qkv = (const float*)d_in[1];
    const float* w_out = (const float*)d_in[2];
    float* out = (float*)d_out;

    cudaFuncSetAttribute(attn_hmma,
                         cudaFuncAttributeMaxDynamicSharedMemorySize, ATTN_SMEM);
    cudaFuncSetAttribute(qkv_gemm_hmma,
                         cudaFuncAttributeMaxDynamicSharedMemorySize, GEMM_SMEM);
    cudaFuncSetAttribute(out_gemm_hmma,
                         cudaFuncAttributeMaxDynamicSharedMemorySize, GEMM_SMEM);

    split_x_blocked<<<dim3(64, 64), 256>>>(x);
    split_wq_blocked<<<dim3(12, 64), 512>>>(w_qkv);
    split_wo_blocked<<<dim3(4, 64), 512>>>(w_out);

    {
        dim3 grid(FQKV / 256, MM / 128);   // (12, 64)
        qkv_gemm_hmma<<<grid, 256, GEMM_SMEM>>>();
    }
    {
        dim3 grid(BB * HH, NN / 128);      // (64, 16)
        attn_hmma<<<grid, 256, ATTN_SMEM>>>();
    }
    {
        dim3 grid(EE / 256, MM / 128);     // (4, 64)
        out_gemm_hmma<<<grid, 256, GEMM_SMEM>>>(out);
    }
}

// round 12
// speedup vs baseline: 4.1605x; 1.0246x over previous
#include <cuda_runtime.h>
#include <cuda_bf16.h>
#include <cstdint>

// Problem constants
#define BB 4
#define NN 2048
#define EE 1024
#define HH 16
#define DD 64
#define MM (BB * NN)        // 8192
#define FQKV (3 * EE)       // 3072
#define BHND (64 * 2048 * 64)

// Blocked-layout block sizes (bytes)
#define XBLK 12288          // A block: [hi 128x48][lo 128x48]
#define WBLK 24576          // W block: [hi 256x48][lo 256x48]  (round-10 layout)
#define KVBLK 71680         // attn chunk: [Kh 18432][Kl 18432][Vh 17408][Vl 17408]

// ---------------------------------------------------------------------------
// Scratch (__device__ globals; allocation-free rule)
// ---------------------------------------------------------------------------
__device__ __nv_bfloat16 g_qh[BHND], g_ql[BHND];      // [bh][n][d], prescaled (linear)

__device__ __align__(16) char g_xb[64 * 64 * XBLK];    // X blocked  [mT][kc]
__device__ __align__(16) char g_ab[64 * 64 * XBLK];    // attn-out blocked [mT][kc]
__device__ __align__(16) char g_wqb[12 * 64 * WBLK];   // Wqkv blocked [fT256][kc]
__device__ __align__(16) char g_wob[4 * 64 * WBLK];    // Wout blocked [fT256][kc]
__device__ __align__(16) char g_kvb[64 * 16 * KVBLK];  // K/V blocked  [bh][chunk]

__device__ __forceinline__ float fast_exp2(float x) {
    float y;
    asm("ex2.approx.ftz.f32 %0, %1;" : "=f"(y) : "f"(x));
    return y;
}
__device__ __forceinline__ uint32_t pack_bf2(float lo, float hi) {
    __nv_bfloat162 t = __floats2bfloat162_rn(lo, hi);
    uint32_t r; r = *reinterpret_cast<uint32_t*>(&t); return r;
}
__device__ __forceinline__ void split_pair(float a, float b, uint32_t& hw, uint32_t& lw) {
    hw = pack_bf2(a, b);
    float fa = __int_as_float(hw << 16);
    float fb = __int_as_float(hw & 0xFFFF0000u);
    lw = pack_bf2(a - fa, b - fb);
}
__device__ __forceinline__ uint32_t smem_u32(const void* p) {
    uint32_t a;
    asm("{ .reg .u64 t; cvta.to.shared.u64 t, %1; cvt.u32.u64 %0, t; }"
        : "=r"(a) : "l"(p));
    return a;
}
__device__ __forceinline__ void mbar_init(uint32_t a, uint32_t cnt) {
    asm volatile("mbarrier.init.shared.b64 [%0], %1;" :: "r"(a), "r"(cnt) : "memory");
}
__device__ __forceinline__ void mbar_expect(uint32_t a, uint32_t bytes) {
    asm volatile("mbarrier.arrive.expect_tx.shared.b64 _, [%0], %1;"
                 :: "r"(a), "r"(bytes) : "memory");
}
__device__ __forceinline__ void mbar_wait(uint32_t addr, uint32_t parity) {
    asm volatile(
        "{\n\t.reg .pred P1;\n\t"
        "WAIT_LOOP_%=:\n\t"
        "mbarrier.try_wait.parity.acquire.cta.shared::cta.b64 P1, [%0], %1, 0x989680;\n\t"
        "@P1 bra.uni WAIT_DONE_%=;\n\t"
        "bra.uni WAIT_LOOP_%=;\n\t"
        "WAIT_DONE_%=:\n\t}"
        :: "r"(addr), "r"(parity) : "memory");
}
__device__ __forceinline__ void bulk_g2s(uint32_t dst, const void* src,
                                         uint32_t bytes, uint32_t mbar) {
    asm volatile(
        "cp.async.bulk.shared::cluster.global.mbarrier::complete_tx::bytes "
        "[%0], [%1], %2, [%3];"
        :: "r"(dst), "l"(src), "r"(bytes), "r"(mbar) : "memory");
}
__device__ __forceinline__ void fence_proxy() {
    asm volatile("fence.proxy.async.shared::cta;" ::: "memory");
}
__device__ __forceinline__ void ldsm_x4(uint32_t* r, uint32_t addr) {
    asm volatile("ldmatrix.sync.aligned.m8n8.x4.shared.b16 {%0,%1,%2,%3}, [%4];"
        : "=r"(r[0]), "=r"(r[1]), "=r"(r[2]), "=r"(r[3]) : "r"(addr));
}
__device__ __forceinline__ void mma16816(float* c, const uint32_t* a, const uint32_t* b) {
    asm volatile(
        "mma.sync.aligned.m16n8k16.row.col.f32.bf16.bf16.f32 "
        "{%0,%1,%2,%3}, {%4,%5,%6,%7}, {%8,%9}, {%0,%1,%2,%3};"
        : "+f"(c[0]), "+f"(c[1]), "+f"(c[2]), "+f"(c[3])
        : "r"(a[0]), "r"(a[1]), "r"(a[2]), "r"(a[3]),
          "r"(b[0]), "r"(b[1]));
}

// ---------------------------------------------------------------------------
// Split kernels -> blocked layouts (VERBATIM round 10, verified)
// ---------------------------------------------------------------------------
__global__ __launch_bounds__(256) void split_x_blocked(const float* __restrict__ x) {
    const int mT = blockIdx.x, kc = blockIdx.y;
    const int t = threadIdx.x;
    const int r = t >> 1, hf = t & 1;
    const float* src = x + ((size_t)(mT * 128 + r)) * EE + kc * 16 + hf * 8;
    float4 v0 = *(const float4*)src;
    float4 v1 = *(const float4*)(src + 4);
    uint32_t h0, h1, h2, h3, l0, l1, l2, l3;
    split_pair(v0.x, v0.y, h0, l0);
    split_pair(v0.z, v0.w, h1, l1);
    split_pair(v1.x, v1.y, h2, l2);
    split_pair(v1.z, v1.w, h3, l3);
    char* blk = g_xb + ((size_t)mT * 64 + kc) * XBLK + r * 48 + hf * 16;
    *(uint4*)blk = make_uint4(h0, h1, h2, h3);
    *(uint4*)(blk + 6144) = make_uint4(l0, l1, l2, l3);
}
__global__ __launch_bounds__(512) void split_wq_blocked(const float* __restrict__ w) {
    const int fT = blockIdx.x, kc = blockIdx.y;
    const int t = threadIdx.x;
    const int r = t >> 1, hf = t & 1;
    const float* src = w + ((size_t)(fT * 256 + r)) * EE + kc * 16 + hf * 8;
    float4 v0 = *(const float4*)src;
    float4 v1 = *(const float4*)(src + 4);
    uint32_t h0, h1, h2, h3, l0, l1, l2, l3;
    split_pair(v0.x, v0.y, h0, l0);
    split_pair(v0.z, v0.w, h1, l1);
    split_pair(v1.x, v1.y, h2, l2);
    split_pair(v1.z, v1.w, h3, l3);
    char* blk = g_wqb + ((size_t)fT * 64 + kc) * WBLK + r * 48 + hf * 16;
    *(uint4*)blk = make_uint4(h0, h1, h2, h3);
    *(uint4*)(blk + 12288) = make_uint4(l0, l1, l2, l3);
}
__global__ __launch_bounds__(512) void split_wo_blocked(const float* __restrict__ w) {
    const int fT = blockIdx.x, kc = blockIdx.y;
    const int t = threadIdx.x;
    const int r = t >> 1, hf = t & 1;
    const float* src = w + ((size_t)(fT * 256 + r)) * EE + kc * 16 + hf * 8;
    float4 v0 = *(const float4*)src;
    float4 v1 = *(const float4*)(src + 4);
    uint32_t h0, h1, h2, h3, l0, l1, l2, l3;
    split_pair(v0.x, v0.y, h0, l0);
    split_pair(v0.z, v0.w, h1, l1);
    split_pair(v1.x, v1.y, h2, l2);
    split_pair(v1.z, v1.w, h3, l3);
    char* blk = g_wob + ((size_t)fT * 64 + kc) * WBLK + r * 48 + hf * 16;
    *(uint4*)blk = make_uint4(h0, h1, h2, h3);
    *(uint4*)(blk + 12288) = make_uint4(l0, l1, l2, l3);
}

// ---------------------------------------------------------------------------
// 3-split HMMA GEMM: CTA 128x128, 4 warps (2x2), warp tile 64x64.
// Round-9-shaped pipeline: 4 stages x 1 K-chunk, issue(ch+3), parity (ch>>2)&1.
// Stage = [A 12KB][Bhi 6KB][Blo 6KB] = 24KB. 2 CTAs/SM.
// B read from round-10 WBLK blocks: this CTA's 128-row half at half*6144.
// ---------------------------------------------------------------------------
#define GSTG 24576
#define GSTAGES 4
#define GEMM_SMEM (GSTAGES * GSTG + 64)      // 98368

__device__ __forceinline__ void hmma_mainloop128(
    uint32_t* sm, const char* aBlocks, const char* bBase, float (&acc)[4][8][4])
{
    const int tid = threadIdx.x;
    const int lane = tid & 31;
    const int wid = tid >> 5;
    const int wm = wid >> 1;           // 0..1
    const int wn = wid & 1;            // 0..1
    const uint32_t sb = smem_u32(sm);
    const uint32_t mb = sb + GSTAGES * GSTG;

#pragma unroll
    for (int i = 0; i < 4; ++i)
#pragma unroll
        for (int j = 0; j < 8; ++j)
#pragma unroll
            for (int r = 0; r < 4; ++r) acc[i][j][r] = 0.f;

    const uint32_t aoffb = (uint32_t)((lane & 15) * 48 + (lane >> 4) * 16);
    const uint32_t boffb = (uint32_t)(((lane & 7) + (lane >> 4) * 8) * 48 + ((lane >> 3) & 1) * 16);

    if (tid == 0) {
#pragma unroll
        for (int s = 0; s < GSTAGES; ++s) mbar_init(mb + 8 * s, 1);
    }
    fence_proxy();
    __syncthreads();

    auto issue = [&](int ch) {
        const int s = ch & 3;
        const uint32_t m = mb + 8 * s;
        const uint32_t d = sb + (uint32_t)s * GSTG;
        mbar_expect(m, GSTG);
        bulk_g2s(d, aBlocks + (size_t)ch * XBLK, XBLK, m);
        bulk_g2s(d + XBLK, bBase + (size_t)ch * WBLK, 6144, m);
        bulk_g2s(d + XBLK + 6144, bBase + (size_t)ch * WBLK + 12288, 6144, m);
    };

    if (tid == 0) { issue(0); issue(1); issue(2); }

    for (int ch = 0; ch < 64; ++ch) {
        const int s = ch & 3;
        __syncthreads();                 // all warps done reading stage (ch-1)&3
        if (tid == 0 && ch + 3 < 64) issue(ch + 3);
        mbar_wait(mb + 8 * s, (ch >> 2) & 1);

        const uint32_t stb = sb + (uint32_t)s * GSTG;
        const uint32_t aHb = stb;
        const uint32_t aLb = stb + 6144;
        const uint32_t bHb = stb + 12288;
        const uint32_t bLb = stb + 18432;

        uint32_t bh[8][2], bl[8][2];
#pragma unroll
        for (int jp = 0; jp < 4; ++jp) {
            const uint32_t ar = (uint32_t)((wn * 64 + jp * 16) * 48) + boffb;
            uint32_t r4[4];
            ldsm_x4(r4, bHb + ar);
            bh[jp * 2][0] = r4[0]; bh[jp * 2][1] = r4[1];
            bh[jp * 2 + 1][0] = r4[2]; bh[jp * 2 + 1][1] = r4[3];
            ldsm_x4(r4, bLb + ar);
            bl[jp * 2][0] = r4[0]; bl[jp * 2][1] = r4[1];
            bl[jp * 2 + 1][0] = r4[2]; bl[jp * 2 + 1][1] = r4[3];
        }
#pragma unroll
        for (int i = 0; i < 4; ++i) {
            const uint32_t ao = (uint32_t)((wm * 64 + i * 16) * 48) + aoffb;
            uint32_t ah4[4], al4[4];
            ldsm_x4(ah4, aHb + ao);
            ldsm_x4(al4, aLb + ao);
#pragma unroll
            for (int j = 0; j < 8; ++j) mma16816(acc[i][j], ah4, bh[j]);
#pragma unroll
            for (int j = 0; j < 8; ++j) mma16816(acc[i][j], ah4, bl[j]);
#pragma unroll
            for (int j = 0; j < 8; ++j) mma16816(acc[i][j], al4, bh[j]);
        }
    }
}

// ---------------------------------------------------------------------------
// QKV GEMM: epilogue writes Q (linear bf16 hi/lo) and blocked K/V (g_kvb)
// ---------------------------------------------------------------------------
__global__ __launch_bounds__(128) void qkv_gemm_hmma() {
    extern __shared__ __align__(16) uint32_t smg[];
    const int mBase = blockIdx.y * 128;
    const int fBase = blockIdx.x * 128;
    float acc[4][8][4];
    const char* aBlocks = g_xb + (size_t)blockIdx.y * 64 * XBLK;
    const char* bBase = g_wqb + (size_t)(blockIdx.x >> 1) * 64 * WBLK
                      + (size_t)(blockIdx.x & 1) * 6144;
    hmma_mainloop128(smg, aBlocks, bBase, acc);

    const int tid = threadIdx.x;
    const int lane = tid & 31;
    const int wid = tid >> 5;
    const int wm = wid >> 1, wn = wid & 1;
    const int g = lane >> 2, cc = lane & 3;
    const int which = fBase >> 10;     // uniform per CTA

    if (which == 2) {
#pragma unroll
        for (int i = 0; i < 4; ++i) {
            const int m0 = mBase + wm * 64 + i * 16 + g;
            const int b = m0 >> 11;
            const int n0 = m0 & (NN - 1);
#pragma unroll
            for (int j = 0; j < 8; ++j) {
                const int col = fBase + wn * 64 + j * 8 + cc * 2;
                const int h = (col >> 6) & (HH - 1);
                const int d0 = col & (DD - 1);
                char* blk = g_kvb + ((size_t)((b * HH + h) * 16) + (n0 >> 7)) * KVBLK + 36864;
#pragma unroll
                for (int r = 0; r < 4; ++r) {
                    const int dd = d0 + (r & 1);
                    const int nn = (n0 & 127) + (r >> 1) * 8;
                    float v = acc[i][j][r];
                    __nv_bfloat16 hh = __float2bfloat16(v);
                    __nv_bfloat16 ll = __float2bfloat16(v - __bfloat162float(hh));
                    *(__nv_bfloat16*)(blk + dd * 272 + nn * 2) = hh;
                    *(__nv_bfloat16*)(blk + 17408 + dd * 272 + nn * 2) = ll;
                }
            }
        }
    } else if (which == 1) {
#pragma unroll
        for (int i = 0; i < 4; ++i) {
            const int m0 = mBase + wm * 64 + i * 16 + g;
            const int b = m0 >> 11;
            const int n0 = m0 & (NN - 1);
#pragma unroll
            for (int j = 0; j < 8; ++j) {
                const int col = fBase + wn * 64 + j * 8 + cc * 2;
                const int h = (col >> 6) & (HH - 1);
                const int d0 = col & (DD - 1);
                char* blk = g_kvb + ((size_t)((b * HH + h) * 16) + (n0 >> 7)) * KVBLK;
                const int rr = n0 & 127;
                uint32_t hp0, lp0, hp1, lp1;
                split_pair(acc[i][j][0], acc[i][j][1], hp0, lp0);
                split_pair(acc[i][j][2], acc[i][j][3], hp1, lp1);
                *(uint32_t*)(blk + rr * 144 + d0 * 2) = hp0;
                *(uint32_t*)(blk + 18432 + rr * 144 + d0 * 2) = lp0;
                *(uint32_t*)(blk + (rr + 8) * 144 + d0 * 2) = hp1;
                *(uint32_t*)(blk + 18432 + (rr + 8) * 144 + d0 * 2) = lp1;
            }
        }
    } else {
        const float qs = 0.125f * 1.44269504f;
        uint32_t* ph_ = (uint32_t*)g_qh;
        uint32_t* pl_ = (uint32_t*)g_ql;
#pragma unroll
        for (int i = 0; i < 4; ++i) {
            const int m0 = mBase + wm * 64 + i * 16 + g;
            const int b = m0 >> 11;
            const int n0 = m0 & (NN - 1);
#pragma unroll
            for (int j = 0; j < 8; ++j) {
                const int col = fBase + wn * 64 + j * 8 + cc * 2;
                const int h = (col >> 6) & (HH - 1);
                const int d0 = col & (DD - 1);
                const size_t rowbase = (size_t)(b * HH + h) * NN;
                uint32_t hp0, lp0, hp1, lp1;
                split_pair(acc[i][j][0] * qs, acc[i][j][1] * qs, hp0, lp0);
                split_pair(acc[i][j][2] * qs, acc[i][j][3] * qs, hp1, lp1);
                ph_[(rowbase + n0) * 32 + (d0 >> 1)] = hp0;
                pl_[(rowbase + n0) * 32 + (d0 >> 1)] = lp0;
                ph_[(rowbase + n0 + 8) * 32 + (d0 >> 1)] = hp1;
                pl_[(rowbase + n0 + 8) * 32 + (d0 >> 1)] = lp1;
            }
        }
    }
}

// ---------------------------------------------------------------------------
// Output projection GEMM
// ---------------------------------------------------------------------------
__global__ __launch_bounds__(128) void out_gemm_hmma(float* __restrict__ Cout) {
    extern __shared__ __align__(16) uint32_t smg[];
    const int mBase = blockIdx.y * 128;
    const int fBase = blockIdx.x * 128;
    float acc[4][8][4];
    const char* aBlocks = g_ab + (size_t)blockIdx.y * 64 * XBLK;
    const char* bBase = g_wob + (size_t)(blockIdx.x >> 1) * 64 * WBLK
                      + (size_t)(blockIdx.x & 1) * 6144;
    hmma_mainloop128(smg, aBlocks, bBase, acc);

    const int tid = threadIdx.x;
    const int lane = tid & 31;
    const int wid = tid >> 5;
    const int wm = wid >> 1, wn = wid & 1;
    const int g = lane >> 2, cc = lane & 3;

#pragma unroll
    for (int i = 0; i < 4; ++i) {
        const int m0 = mBase + wm * 64 + i * 16 + g;
#pragma unroll
        for (int j = 0; j < 8; ++j) {
            const int col = fBase + wn * 64 + j * 8 + cc * 2;
            float* d1 = Cout + (size_t)m0 * EE + col;
            float* d2 = Cout + (size_t)(m0 + 8) * EE + col;
            *(float2*)d1 = make_float2(acc[i][j][0], acc[i][j][1]);
            *(float2*)d2 = make_float2(acc[i][j][2], acc[i][j][3]);
        }
    }
}

// ---------------------------------------------------------------------------
// Flash attention with HMMA (VERBATIM round 10, verified)
// ---------------------------------------------------------------------------
#define KROW 36
#define VROW 68
#define KWORDS (128 * KROW)
#define VWORDS (64 * VROW)
#define STAGEW (2 * KWORDS + 2 * VWORDS)
#define STAGEB (STAGEW * 4)                 // 71680 = KVBLK
#define ATTN_SMEM (2 * STAGEB + 64)
#define KBYTES (KWORDS * 4)                 // 18432
#define VBYTES (VWORDS * 4)                 // 17408

__global__ __launch_bounds__(256, 1) void attn_hmma() {
    extern __shared__ __align__(16) uint32_t smdyn[];

    const int bh = blockIdx.x;
    const int qt = blockIdx.y;
    const int tid = threadIdx.x;
    const int lane = tid & 31, wid = tid >> 5;
    const int g = lane >> 2, cc = lane & 3;

    const size_t qoff = (size_t)bh * NN * DD;
    const uint32_t* qhw = (const uint32_t*)g_qh + (qoff >> 1);
    const uint32_t* qlw = (const uint32_t*)g_ql + (qoff >> 1);
    const char* kvsrc = g_kvb + (size_t)bh * 16 * KVBLK;
    const uint32_t sb = smem_u32(smdyn);
    const uint32_t mb = sb + 2 * STAGEB;

    const int r0 = qt * 128 + wid * 16 + g;
    uint32_t qa[4][4], qb[4][4];
#pragma unroll
    for (int kc = 0; kc < 4; ++kc) {
        const int w0 = r0 * 32 + kc * 8 + cc;
        qa[kc][0] = qhw[w0];       qa[kc][1] = qhw[w0 + 256];
        qa[kc][2] = qhw[w0 + 4];   qa[kc][3] = qhw[w0 + 260];
        qb[kc][0] = qlw[w0];       qb[kc][1] = qlw[w0 + 256];
        qb[kc][2] = qlw[w0 + 4];   qb[kc][3] = qlw[w0 + 260];
    }

    float o[8][4];
#pragma unroll
    for (int j = 0; j < 8; ++j) { o[j][0] = o[j][1] = o[j][2] = o[j][3] = 0.f; }
    float m0 = -30000.f, m1 = -30000.f, l0 = 0.f, l1 = 0.f;

    if (tid == 0) { mbar_init(mb, 1); mbar_init(mb + 8, 1); }
    fence_proxy();
    __syncthreads();

    auto issue = [&](int kt) {
        const int s = kt & 1;
        const uint32_t m = mb + 8 * s;
        const uint32_t d = sb + (uint32_t)s * STAGEB;
        const char* src = kvsrc + (size_t)kt * KVBLK;
        mbar_expect(m, KVBLK);
        bulk_g2s(d, src, KBYTES, m);
        bulk_g2s(d + KBYTES, src + KBYTES, KBYTES, m);
        bulk_g2s(d + 2 * KBYTES, src + 2 * KBYTES, VBYTES, m);
        bulk_g2s(d + 2 * KBYTES + VBYTES, src + 2 * KBYTES + VBYTES, VBYTES, m);
    };

    if (tid == 0) issue(0);

    for (int ch = 0; ch < 16; ++ch) {
        const int s = ch & 1;
        __syncthreads();
        if (tid == 0 && ch + 1 < 16) issue(ch + 1);
        mbar_wait(mb + 8 * s, (ch >> 1) & 1);

        const uint32_t* sKh = smdyn + s * STAGEW;
        const uint32_t* sKl = sKh + KWORDS;
        const uint32_t* sVh = sKl + KWORDS;
        const uint32_t* sVl = sVh + VWORDS;

        float sc[16][4];
#pragma unroll
        for (int j = 0; j < 16; ++j) { sc[j][0] = sc[j][1] = sc[j][2] = sc[j][3] = 0.f; }
#pragma unroll
        for (int kc = 0; kc < 4; ++kc) {
            uint32_t kbh[16][2], kbl[16][2];
#pragma unroll
            for (int j = 0; j < 16; ++j) {
                const int bw = (j * 8 + g) * KROW + kc * 8 + cc;
                kbh[j][0] = sKh[bw]; kbh[j][1] = sKh[bw + 4];
                kbl[j][0] = sKl[bw]; kbl[j][1] = sKl[bw + 4];
            }
#pragma unroll
            for (int j = 0; j < 16; ++j) mma16816(sc[j], qa[kc], kbh[j]);
#pragma unroll
            for (int j = 0; j < 16; ++j) mma16816(sc[j], qa[kc], kbl[j]);
#pragma unroll
            for (int j = 0; j < 16; ++j) mma16816(sc[j], qb[kc], kbh[j]);
        }

        float cm0 = -30000.f, cm1 = -30000.f;
#pragma unroll
        for (int j = 0; j < 16; ++j) {
            cm0 = fmaxf(cm0, fmaxf(sc[j][0], sc[j][1]));
            cm1 = fmaxf(cm1, fmaxf(sc[j][2], sc[j][3]));
        }
        cm0 = fmaxf(cm0, __shfl_xor_sync(0xffffffffu, cm0, 1));
        cm0 = fmaxf(cm0, __shfl_xor_sync(0xffffffffu, cm0, 2));
        cm1 = fmaxf(cm1, __shfl_xor_sync(0xffffffffu, cm1, 1));
        cm1 = fmaxf(cm1, __shfl_xor_sync(0xffffffffu, cm1, 2));
        const float mn0 = fmaxf(m0, cm0), mn1 = fmaxf(m1, cm1);
        const float a0 = fast_exp2(m0 - mn0), a1 = fast_exp2(m1 - mn1);
        m0 = mn0; m1 = mn1;
#pragma unroll
        for (int j = 0; j < 8; ++j) {
            o[j][0] *= a0; o[j][1] *= a0; o[j][2] *= a1; o[j][3] *= a1;
        }

        float rs0 = 0.f, rs1 = 0.f;
#pragma unroll
        for (int kc2 = 0; kc2 < 8; ++kc2) {
            uint32_t pah[4], pal[4];
#pragma unroll
            for (int t = 0; t < 2; ++t) {
                const int j = kc2 * 2 + t;
                float p0 = fast_exp2(sc[j][0] - m0);
                float p1 = fast_exp2(sc[j][1] - m0);
                float p2 = fast_exp2(sc[j][2] - m1);
                float p3 = fast_exp2(sc[j][3] - m1);
                rs0 += p0 + p1; rs1 += p2 + p3;
                uint32_t h01, l01, h23, l23;
                split_pair(p0, p1, h01, l01);
                split_pair(p2, p3, h23, l23);
                pah[2 * t] = h01; pah[2 * t + 1] = h23;
                pal[2 * t] = l01; pal[2 * t + 1] = l23;
            }
            uint32_t vbh[8][2], vbl[8][2];
#pragma unroll
            for (int j = 0; j < 8; ++j) {
                const int bw = (j * 8 + g) * VROW + kc2 * 8 + cc;
                vbh[j][0] = sVh[bw]; vbh[j][1] = sVh[bw + 4];
                vbl[j][0] = sVl[bw]; vbl[j][1] = sVl[bw + 4];
            }
#pragma unroll
            for (int j = 0; j < 8; ++j) mma16816(o[j], pah, vbh[j]);
#pragma unroll
            for (int j = 0; j < 8; ++j) mma16816(o[j], pal, vbh[j]);
#pragma unroll
            for (int j = 0; j < 8; ++j) mma16816(o[j], pah, vbl[j]);
        }
        rs0 += __shfl_xor_sync(0xffffffffu, rs0, 1);
        rs0 += __shfl_xor_sync(0xffffffffu, rs0, 2);
        rs1 += __shfl_xor_sync(0xffffffffu, rs1, 1);
        rs1 += __shfl_xor_sync(0xffffffffu, rs1, 2);
        l0 = l0 * a0 + rs0;
        l1 = l1 * a1 + rs1;
    }

    const float i0 = 1.f / l0, i1 = 1.f / l1;
    const int b = bh >> 4, h = bh & (HH - 1);
    const int mg = b * NN + r0;
    const int mT = mg >> 7;
    const int rr = mg & 127;
#pragma unroll
    for (int j = 0; j < 8; ++j) {
        const int w = h * 32 + j * 4 + cc;
        uint32_t hp0, lp0, hp1, lp1;
        split_pair(o[j][0] * i0, o[j][1] * i0, hp0, lp0);
        split_pair(o[j][2] * i1, o[j][3] * i1, hp1, lp1);
        char* blk = g_ab + ((size_t)mT * 64 + (w >> 3)) * XBLK;
        const int off = (w & 7) * 4;
        *(uint32_t*)(blk + rr * 48 + off) = hp0;
        *(uint32_t*)(blk + 6144 + rr * 48 + off) = lp0;
        *(uint32_t*)(blk + (rr + 8) * 48 + off) = hp1;
        *(uint32_t*)(blk + 6144 + (rr + 8) * 48 + off) = lp1;
    }
}

// ---------------------------------------------------------------------------
extern "C" void kernel_launch(void* const* d_in, const int* in_sizes, int n_in,
                              void* d_out, int out_size)
{
    const float* x     = (const float*)d_in[0];
    const float* w_qkv = (const float*)d_in[1];
    const float* w_out = (const float*)d_in[2];
    float* out = (float*)d_out;

    cudaFuncSetAttribute(attn_hmma,
                         cudaFuncAttributeMaxDynamicSharedMemorySize, ATTN_SMEM);
    cudaFuncSetAttribute(qkv_gemm_hmma,
                         cudaFuncAttributeMaxDynamicSharedMemorySize, GEMM_SMEM);
    cudaFuncSetAttribute(out_gemm_hmma,
                         cudaFuncAttributeMaxDynamicSharedMemorySize, GEMM_SMEM);

    split_x_blocked<<<dim3(64, 64), 256>>>(x);
    split_wq_blocked<<<dim3(12, 64), 512>>>(w_qkv);
    split_wo_blocked<<<dim3(4, 64), 512>>>(w_out);

    {
        dim3 grid(FQKV / 128, MM / 128);   // (24, 64)
        qkv_gemm_hmma<<<grid, 128, GEMM_SMEM>>>();
    }
    {
        dim3 grid(BB * HH, NN / 128);      // (64, 16)
        attn_hmma<<<grid, 256, ATTN_SMEM>>>();
    }
    {
        dim3 grid(EE / 128, MM / 128);     // (8, 64)
        out_gemm_hmma<<<grid, 128, GEMM_SMEM>>>(out);
    }
}

// round 13
// speedup vs baseline: 4.1997x; 1.0094x over previous
#include <cuda_runtime.h>
#include <cuda_bf16.h>
#include <cstdint>

// Problem constants
#define BB 4
#define NN 2048
#define EE 1024
#define HH 16
#define DD 64
#define MM (BB * NN)        // 8192
#define FQKV (3 * EE)       // 3072
#define BHND (64 * 2048 * 64)

// Blocked-layout block sizes (bytes)
#define XBLK 12288          // A block: [hi 128x48][lo 128x48]
#define WBLK 24576          // W block: [hi 256x48][lo 256x48]
#define KVBLK 71680         // attn chunk: [Kh 18432][Kl 18432][Vh 17408][Vl 17408]

// ---------------------------------------------------------------------------
// Scratch (__device__ globals; allocation-free rule)
// ---------------------------------------------------------------------------
__device__ __nv_bfloat16 g_qh[BHND], g_ql[BHND];      // [bh][n][d], prescaled (linear)

__device__ __align__(16) char g_xb[64 * 64 * XBLK];    // X blocked  [mT][kc]
__device__ __align__(16) char g_ab[64 * 64 * XBLK];    // attn-out blocked [mT][kc]
__device__ __align__(16) char g_wqb[12 * 64 * WBLK];   // Wqkv blocked [fT256][kc]
__device__ __align__(16) char g_wob[4 * 64 * WBLK];    // Wout blocked [fT256][kc]
__device__ __align__(16) char g_kvb[64 * 16 * KVBLK];  // K/V blocked  [bh][chunk]

__device__ __forceinline__ float fast_exp2(float x) {
    float y;
    asm("ex2.approx.ftz.f32 %0, %1;" : "=f"(y) : "f"(x));
    return y;
}
__device__ __forceinline__ uint32_t pack_bf2(float lo, float hi) {
    __nv_bfloat162 t = __floats2bfloat162_rn(lo, hi);
    uint32_t r; r = *reinterpret_cast<uint32_t*>(&t); return r;
}
__device__ __forceinline__ void split_pair(float a, float b, uint32_t& hw, uint32_t& lw) {
    hw = pack_bf2(a, b);
    float fa = __int_as_float(hw << 16);
    float fb = __int_as_float(hw & 0xFFFF0000u);
    lw = pack_bf2(a - fa, b - fb);
}
__device__ __forceinline__ uint32_t smem_u32(const void* p) {
    uint32_t a;
    asm("{ .reg .u64 t; cvta.to.shared.u64 t, %1; cvt.u32.u64 %0, t; }"
        : "=r"(a) : "l"(p));
    return a;
}
__device__ __forceinline__ void mbar_init(uint32_t a, uint32_t cnt) {
    asm volatile("mbarrier.init.shared.b64 [%0], %1;" :: "r"(a), "r"(cnt) : "memory");
}
__device__ __forceinline__ void mbar_expect(uint32_t a, uint32_t bytes) {
    asm volatile("mbarrier.arrive.expect_tx.shared.b64 _, [%0], %1;"
                 :: "r"(a), "r"(bytes) : "memory");
}
__device__ __forceinline__ void mbar_wait(uint32_t addr, uint32_t parity) {
    asm volatile(
        "{\n\t.reg .pred P1;\n\t"
        "WAIT_LOOP_%=:\n\t"
        "mbarrier.try_wait.parity.acquire.cta.shared::cta.b64 P1, [%0], %1, 0x989680;\n\t"
        "@P1 bra.uni WAIT_DONE_%=;\n\t"
        "bra.uni WAIT_LOOP_%=;\n\t"
        "WAIT_DONE_%=:\n\t}"
        :: "r"(addr), "r"(parity) : "memory");
}
__device__ __forceinline__ void bulk_g2s(uint32_t dst, const void* src,
                                         uint32_t bytes, uint32_t mbar) {
    asm volatile(
        "cp.async.bulk.shared::cluster.global.mbarrier::complete_tx::bytes "
        "[%0], [%1], %2, [%3];"
        :: "r"(dst), "l"(src), "r"(bytes), "r"(mbar) : "memory");
}
__device__ __forceinline__ void fence_proxy() {
    asm volatile("fence.proxy.async.shared::cta;" ::: "memory");
}
__device__ __forceinline__ void ldsm_x4(uint32_t* r, uint32_t addr) {
    asm volatile("ldmatrix.sync.aligned.m8n8.x4.shared.b16 {%0,%1,%2,%3}, [%4];"
        : "=r"(r[0]), "=r"(r[1]), "=r"(r[2]), "=r"(r[3]) : "r"(addr));
}
__device__ __forceinline__ void mma16816(float* c, const uint32_t* a, const uint32_t* b) {
    asm volatile(
        "mma.sync.aligned.m16n8k16.row.col.f32.bf16.bf16.f32 "
        "{%0,%1,%2,%3}, {%4,%5,%6,%7}, {%8,%9}, {%0,%1,%2,%3};"
        : "+f"(c[0]), "+f"(c[1]), "+f"(c[2]), "+f"(c[3])
        : "r"(a[0]), "r"(a[1]), "r"(a[2]), "r"(a[3]),
          "r"(b[0]), "r"(b[1]));
}

// ---------------------------------------------------------------------------
// Split kernels -> blocked layouts (VERBATIM, verified)
// ---------------------------------------------------------------------------
__global__ __launch_bounds__(256) void split_x_blocked(const float* __restrict__ x) {
    const int mT = blockIdx.x, kc = blockIdx.y;
    const int t = threadIdx.x;
    const int r = t >> 1, hf = t & 1;
    const float* src = x + ((size_t)(mT * 128 + r)) * EE + kc * 16 + hf * 8;
    float4 v0 = *(const float4*)src;
    float4 v1 = *(const float4*)(src + 4);
    uint32_t h0, h1, h2, h3, l0, l1, l2, l3;
    split_pair(v0.x, v0.y, h0, l0);
    split_pair(v0.z, v0.w, h1, l1);
    split_pair(v1.x, v1.y, h2, l2);
    split_pair(v1.z, v1.w, h3, l3);
    char* blk = g_xb + ((size_t)mT * 64 + kc) * XBLK + r * 48 + hf * 16;
    *(uint4*)blk = make_uint4(h0, h1, h2, h3);
    *(uint4*)(blk + 6144) = make_uint4(l0, l1, l2, l3);
}
__global__ __launch_bounds__(512) void split_wq_blocked(const float* __restrict__ w) {
    const int fT = blockIdx.x, kc = blockIdx.y;
    const int t = threadIdx.x;
    const int r = t >> 1, hf = t & 1;
    const float* src = w + ((size_t)(fT * 256 + r)) * EE + kc * 16 + hf * 8;
    float4 v0 = *(const float4*)src;
    float4 v1 = *(const float4*)(src + 4);
    uint32_t h0, h1, h2, h3, l0, l1, l2, l3;
    split_pair(v0.x, v0.y, h0, l0);
    split_pair(v0.z, v0.w, h1, l1);
    split_pair(v1.x, v1.y, h2, l2);
    split_pair(v1.z, v1.w, h3, l3);
    char* blk = g_wqb + ((size_t)fT * 64 + kc) * WBLK + r * 48 + hf * 16;
    *(uint4*)blk = make_uint4(h0, h1, h2, h3);
    *(uint4*)(blk + 12288) = make_uint4(l0, l1, l2, l3);
}
__global__ __launch_bounds__(512) void split_wo_blocked(const float* __restrict__ w) {
    const int fT = blockIdx.x, kc = blockIdx.y;
    const int t = threadIdx.x;
    const int r = t >> 1, hf = t & 1;
    const float* src = w + ((size_t)(fT * 256 + r)) * EE + kc * 16 + hf * 8;
    float4 v0 = *(const float4*)src;
    float4 v1 = *(const float4*)(src + 4);
    uint32_t h0, h1, h2, h3, l0, l1, l2, l3;
    split_pair(v0.x, v0.y, h0, l0);
    split_pair(v0.z, v0.w, h1, l1);
    split_pair(v1.x, v1.y, h2, l2);
    split_pair(v1.z, v1.w, h3, l3);
    char* blk = g_wob + ((size_t)fT * 64 + kc) * WBLK + r * 48 + hf * 16;
    *(uint4*)blk = make_uint4(h0, h1, h2, h3);
    *(uint4*)(blk + 12288) = make_uint4(l0, l1, l2, l3);
}

// ---------------------------------------------------------------------------
// 3-split HMMA GEMM (VERBATIM round 12, verified): CTA 128x128, 4 warps,
// 4 stages x 1 K-chunk, 2 CTAs/SM.
// ---------------------------------------------------------------------------
#define GSTG 24576
#define GSTAGES 4
#define GEMM_SMEM (GSTAGES * GSTG + 64)      // 98368

__device__ __forceinline__ void hmma_mainloop128(
    uint32_t* sm, const char* aBlocks, const char* bBase, float (&acc)[4][8][4])
{
    const int tid = threadIdx.x;
    const int lane = tid & 31;
    const int wid = tid >> 5;
    const int wm = wid >> 1;
    const int wn = wid & 1;
    const uint32_t sb = smem_u32(sm);
    const uint32_t mb = sb + GSTAGES * GSTG;

#pragma unroll
    for (int i = 0; i < 4; ++i)
#pragma unroll
        for (int j = 0; j < 8; ++j)
#pragma unroll
            for (int r = 0; r < 4; ++r) acc[i][j][r] = 0.f;

    const uint32_t aoffb = (uint32_t)((lane & 15) * 48 + (lane >> 4) * 16);
    const uint32_t boffb = (uint32_t)(((lane & 7) + (lane >> 4) * 8) * 48 + ((lane >> 3) & 1) * 16);

    if (tid == 0) {
#pragma unroll
        for (int s = 0; s < GSTAGES; ++s) mbar_init(mb + 8 * s, 1);
    }
    fence_proxy();
    __syncthreads();

    auto issue = [&](int ch) {
        const int s = ch & 3;
        const uint32_t m = mb + 8 * s;
        const uint32_t d = sb + (uint32_t)s * GSTG;
        mbar_expect(m, GSTG);
        bulk_g2s(d, aBlocks + (size_t)ch * XBLK, XBLK, m);
        bulk_g2s(d + XBLK, bBase + (size_t)ch * WBLK, 6144, m);
        bulk_g2s(d + XBLK + 6144, bBase + (size_t)ch * WBLK + 12288, 6144, m);
    };

    if (tid == 0) { issue(0); issue(1); issue(2); }

    for (int ch = 0; ch < 64; ++ch) {
        const int s = ch & 3;
        __syncthreads();
        if (tid == 0 && ch + 3 < 64) issue(ch + 3);
        mbar_wait(mb + 8 * s, (ch >> 2) & 1);

        const uint32_t stb = sb + (uint32_t)s * GSTG;
        const uint32_t aHb = stb;
        const uint32_t aLb = stb + 6144;
        const uint32_t bHb = stb + 12288;
        const uint32_t bLb = stb + 18432;

        uint32_t bh[8][2], bl[8][2];
#pragma unroll
        for (int jp = 0; jp < 4; ++jp) {
            const uint32_t ar = (uint32_t)((wn * 64 + jp * 16) * 48) + boffb;
            uint32_t r4[4];
            ldsm_x4(r4, bHb + ar);
            bh[jp * 2][0] = r4[0]; bh[jp * 2][1] = r4[1];
            bh[jp * 2 + 1][0] = r4[2]; bh[jp * 2 + 1][1] = r4[3];
            ldsm_x4(r4, bLb + ar);
            bl[jp * 2][0] = r4[0]; bl[jp * 2][1] = r4[1];
            bl[jp * 2 + 1][0] = r4[2]; bl[jp * 2 + 1][1] = r4[3];
        }
#pragma unroll
        for (int i = 0; i < 4; ++i) {
            const uint32_t ao = (uint32_t)((wm * 64 + i * 16) * 48) + aoffb;
            uint32_t ah4[4], al4[4];
            ldsm_x4(ah4, aHb + ao);
            ldsm_x4(al4, aLb + ao);
#pragma unroll
            for (int j = 0; j < 8; ++j) mma16816(acc[i][j], ah4, bh[j]);
#pragma unroll
            for (int j = 0; j < 8; ++j) mma16816(acc[i][j], ah4, bl[j]);
#pragma unroll
            for (int j = 0; j < 8; ++j) mma16816(acc[i][j], al4, bh[j]);
        }
    }
}

// ---------------------------------------------------------------------------
// QKV GEMM (VERBATIM round 12, verified)
// ---------------------------------------------------------------------------
__global__ __launch_bounds__(128) void qkv_gemm_hmma() {
    extern __shared__ __align__(16) uint32_t smg[];
    const int mBase = blockIdx.y * 128;
    const int fBase = blockIdx.x * 128;
    float acc[4][8][4];
    const char* aBlocks = g_xb + (size_t)blockIdx.y * 64 * XBLK;
    const char* bBase = g_wqb + (size_t)(blockIdx.x >> 1) * 64 * WBLK
                      + (size_t)(blockIdx.x & 1) * 6144;
    hmma_mainloop128(smg, aBlocks, bBase, acc);

    const int tid = threadIdx.x;
    const int lane = tid & 31;
    const int wid = tid >> 5;
    const int wm = wid >> 1, wn = wid & 1;
    const int g = lane >> 2, cc = lane & 3;
    const int which = fBase >> 10;

    if (which == 2) {
#pragma unroll
        for (int i = 0; i < 4; ++i) {
            const int m0 = mBase + wm * 64 + i * 16 + g;
            const int b = m0 >> 11;
            const int n0 = m0 & (NN - 1);
#pragma unroll
            for (int j = 0; j < 8; ++j) {
                const int col = fBase + wn * 64 + j * 8 + cc * 2;
                const int h = (col >> 6) & (HH - 1);
                const int d0 = col & (DD - 1);
                char* blk = g_kvb + ((size_t)((b * HH + h) * 16) + (n0 >> 7)) * KVBLK + 36864;
#pragma unroll
                for (int r = 0; r < 4; ++r) {
                    const int dd = d0 + (r & 1);
                    const int nn = (n0 & 127) + (r >> 1) * 8;
                    float v = acc[i][j][r];
                    __nv_bfloat16 hh = __float2bfloat16(v);
                    __nv_bfloat16 ll = __float2bfloat16(v - __bfloat162float(hh));
                    *(__nv_bfloat16*)(blk + dd * 272 + nn * 2) = hh;
                    *(__nv_bfloat16*)(blk + 17408 + dd * 272 + nn * 2) = ll;
                }
            }
        }
    } else if (which == 1) {
#pragma unroll
        for (int i = 0; i < 4; ++i) {
            const int m0 = mBase + wm * 64 + i * 16 + g;
            const int b = m0 >> 11;
            const int n0 = m0 & (NN - 1);
#pragma unroll
            for (int j = 0; j < 8; ++j) {
                const int col = fBase + wn * 64 + j * 8 + cc * 2;
                const int h = (col >> 6) & (HH - 1);
                const int d0 = col & (DD - 1);
                char* blk = g_kvb + ((size_t)((b * HH + h) * 16) + (n0 >> 7)) * KVBLK;
                const int rr = n0 & 127;
                uint32_t hp0, lp0, hp1, lp1;
                split_pair(acc[i][j][0], acc[i][j][1], hp0, lp0);
                split_pair(acc[i][j][2], acc[i][j][3], hp1, lp1);
                *(uint32_t*)(blk + rr * 144 + d0 * 2) = hp0;
                *(uint32_t*)(blk + 18432 + rr * 144 + d0 * 2) = lp0;
                *(uint32_t*)(blk + (rr + 8) * 144 + d0 * 2) = hp1;
                *(uint32_t*)(blk + 18432 + (rr + 8) * 144 + d0 * 2) = lp1;
            }
        }
    } else {
        const float qs = 0.125f * 1.44269504f;
        uint32_t* ph_ = (uint32_t*)g_qh;
        uint32_t* pl_ = (uint32_t*)g_ql;
#pragma unroll
        for (int i = 0; i < 4; ++i) {
            const int m0 = mBase + wm * 64 + i * 16 + g;
            const int b = m0 >> 11;
            const int n0 = m0 & (NN - 1);
#pragma unroll
            for (int j = 0; j < 8; ++j) {
                const int col = fBase + wn * 64 + j * 8 + cc * 2;
                const int h = (col >> 6) & (HH - 1);
                const int d0 = col & (DD - 1);
                const size_t rowbase = (size_t)(b * HH + h) * NN;
                uint32_t hp0, lp0, hp1, lp1;
                split_pair(acc[i][j][0] * qs, acc[i][j][1] * qs, hp0, lp0);
                split_pair(acc[i][j][2] * qs, acc[i][j][3] * qs, hp1, lp1);
                ph_[(rowbase + n0) * 32 + (d0 >> 1)] = hp0;
                pl_[(rowbase + n0) * 32 + (d0 >> 1)] = lp0;
                ph_[(rowbase + n0 + 8) * 32 + (d0 >> 1)] = hp1;
                pl_[(rowbase + n0 + 8) * 32 + (d0 >> 1)] = lp1;
            }
        }
    }
}

// ---------------------------------------------------------------------------
// Output projection GEMM (VERBATIM round 12, verified)
// ---------------------------------------------------------------------------
__global__ __launch_bounds__(128) void out_gemm_hmma(float* __restrict__ Cout) {
    extern __shared__ __align__(16) uint32_t smg[];
    const int mBase = blockIdx.y * 128;
    const int fBase = blockIdx.x * 128;
    float acc[4][8][4];
    const char* aBlocks = g_ab + (size_t)blockIdx.y * 64 * XBLK;
    const char* bBase = g_wob + (size_t)(blockIdx.x >> 1) * 64 * WBLK
                      + (size_t)(blockIdx.x & 1) * 6144;
    hmma_mainloop128(smg, aBlocks, bBase, acc);

    const int tid = threadIdx.x;
    const int lane = tid & 31;
    const int wid = tid >> 5;
    const int wm = wid >> 1, wn = wid & 1;
    const int g = lane >> 2, cc = lane & 3;

#pragma unroll
    for (int i = 0; i < 4; ++i) {
        const int m0 = mBase + wm * 64 + i * 16 + g;
#pragma unroll
        for (int j = 0; j < 8; ++j) {
            const int col = fBase + wn * 64 + j * 8 + cc * 2;
            float* d1 = Cout + (size_t)m0 * EE + col;
            float* d2 = Cout + (size_t)(m0 + 8) * EE + col;
            *(float2*)d1 = make_float2(acc[i][j][0], acc[i][j][1]);
            *(float2*)d2 = make_float2(acc[i][j][2], acc[i][j][3]);
        }
    }
}

// ---------------------------------------------------------------------------
// Flash attention: 128 threads (4 warps), q-tile 64, 2 CTAs/SM.
// K double-buffered (2x36KB), V single-buffered (34.8KB, issued post-PV).
// Per-warp math identical to verified round-12 attention.
// ---------------------------------------------------------------------------
#define KROW 36
#define VROW 68
#define KWORDS (128 * KROW)
#define VWORDS (64 * VROW)
#define KBYTES (KWORDS * 4)                 // 18432
#define VBYTES (VWORDS * 4)                 // 17408
#define KSTG_B (2 * KBYTES)                 // 36864 (Kh + Kl)
#define VSTG_B (2 * VBYTES)                 // 34816 (Vh + Vl contiguous)
#define ATTN_SMEM (2 * KSTG_B + VSTG_B + 64)  // 108608

__global__ __launch_bounds__(128) void attn_hmma() {
    extern __shared__ __align__(16) uint32_t smdyn[];

    const int bh = blockIdx.x;
    const int qt = blockIdx.y;                 // 0..31 (q-tile of 64)
    const int tid = threadIdx.x;
    const int lane = tid & 31, wid = tid >> 5; // wid 0..3
    const int g = lane >> 2, cc = lane & 3;

    const size_t qoff = (size_t)bh * NN * DD;
    const uint32_t* qhw = (const uint32_t*)g_qh + (qoff >> 1);
    const uint32_t* qlw = (const uint32_t*)g_ql + (qoff >> 1);
    const char* kvsrc = g_kvb + (size_t)bh * 16 * KVBLK;
    const uint32_t sb = smem_u32(smdyn);
    const uint32_t mb = sb + 2 * KSTG_B + VSTG_B;   // mbars: k0, k1, v

    const int r0 = qt * 64 + wid * 16 + g;
    uint32_t qa[4][4], qb[4][4];
#pragma unroll
    for (int kc = 0; kc < 4; ++kc) {
        const int w0 = r0 * 32 + kc * 8 + cc;
        qa[kc][0] = qhw[w0];       qa[kc][1] = qhw[w0 + 256];
        qa[kc][2] = qhw[w0 + 4];   qa[kc][3] = qhw[w0 + 260];
        qb[kc][0] = qlw[w0];       qb[kc][1] = qlw[w0 + 256];
        qb[kc][2] = qlw[w0 + 4];   qb[kc][3] = qlw[w0 + 260];
    }

    float o[8][4];
#pragma unroll
    for (int j = 0; j < 8; ++j) { o[j][0] = o[j][1] = o[j][2] = o[j][3] = 0.f; }
    float m0 = -30000.f, m1 = -30000.f, l0 = 0.f, l1 = 0.f;

    if (tid == 0) { mbar_init(mb, 1); mbar_init(mb + 8, 1); mbar_init(mb + 16, 1); }
    fence_proxy();
    __syncthreads();

    auto issue_k = [&](int kt) {
        const int s = kt & 1;
        const uint32_t m = mb + 8 * s;
        const uint32_t d = sb + (uint32_t)s * KSTG_B;
        const char* src = kvsrc + (size_t)kt * KVBLK;
        mbar_expect(m, KSTG_B);
        bulk_g2s(d, src, KBYTES, m);
        bulk_g2s(d + KBYTES, src + KBYTES, KBYTES, m);
    };
    auto issue_v = [&](int kt) {
        const uint32_t m = mb + 16;
        const uint32_t d = sb + 2 * KSTG_B;
        const char* src = kvsrc + (size_t)kt * KVBLK + 2 * KBYTES;
        mbar_expect(m, VSTG_B);
        bulk_g2s(d, src, VSTG_B, m);
    };

    if (tid == 0) { issue_k(0); issue_v(0); issue_k(1); }

    for (int ch = 0; ch < 16; ++ch) {
        const int s = ch & 1;
        mbar_wait(mb + 8 * s, (ch >> 1) & 1);

        const uint32_t* sKh = smdyn + (size_t)s * (KSTG_B / 4);
        const uint32_t* sKl = sKh + KWORDS;
        const uint32_t* sVh = smdyn + 2 * (KSTG_B / 4);
        const uint32_t* sVl = sVh + VWORDS;

        float sc[16][4];
#pragma unroll
        for (int j = 0; j < 16; ++j) { sc[j][0] = sc[j][1] = sc[j][2] = sc[j][3] = 0.f; }
#pragma unroll
        for (int kc = 0; kc < 4; ++kc) {
            uint32_t kbh[16][2], kbl[16][2];
#pragma unroll
            for (int j = 0; j < 16; ++j) {
                const int bw = (j * 8 + g) * KROW + kc * 8 + cc;
                kbh[j][0] = sKh[bw]; kbh[j][1] = sKh[bw + 4];
                kbl[j][0] = sKl[bw]; kbl[j][1] = sKl[bw + 4];
            }
#pragma unroll
            for (int j = 0; j < 16; ++j) mma16816(sc[j], qa[kc], kbh[j]);
#pragma unroll
            for (int j = 0; j < 16; ++j) mma16816(sc[j], qa[kc], kbl[j]);
#pragma unroll
            for (int j = 0; j < 16; ++j) mma16816(sc[j], qb[kc], kbh[j]);
        }

        float cm0 = -30000.f, cm1 = -30000.f;
#pragma unroll
        for (int j = 0; j < 16; ++j) {
            cm0 = fmaxf(cm0, fmaxf(sc[j][0], sc[j][1]));
            cm1 = fmaxf(cm1, fmaxf(sc[j][2], sc[j][3]));
        }
        cm0 = fmaxf(cm0, __shfl_xor_sync(0xffffffffu, cm0, 1));
        cm0 = fmaxf(cm0, __shfl_xor_sync(0xffffffffu, cm0, 2));
        cm1 = fmaxf(cm1, __shfl_xor_sync(0xffffffffu, cm1, 1));
        cm1 = fmaxf(cm1, __shfl_xor_sync(0xffffffffu, cm1, 2));
        const float mn0 = fmaxf(m0, cm0), mn1 = fmaxf(m1, cm1);
        const float a0 = fast_exp2(m0 - mn0), a1 = fast_exp2(m1 - mn1);
        m0 = mn0; m1 = mn1;
#pragma unroll
        for (int j = 0; j < 8; ++j) {
            o[j][0] *= a0; o[j][1] *= a0; o[j][2] *= a1; o[j][3] *= a1;
        }

        // V for this chunk must be resident
        mbar_wait(mb + 16, ch & 1);

        float rs0 = 0.f, rs1 = 0.f;
#pragma unroll
        for (int kc2 = 0; kc2 < 8; ++kc2) {
            uint32_t pah[4], pal[4];
#pragma unroll
            for (int t = 0; t < 2; ++t) {
                const int j = kc2 * 2 + t;
                float p0 = fast_exp2(sc[j][0] - m0);
                float p1 = fast_exp2(sc[j][1] - m0);
                float p2 = fast_exp2(sc[j][2] - m1);
                float p3 = fast_exp2(sc[j][3] - m1);
                rs0 += p0 + p1; rs1 += p2 + p3;
                uint32_t h01, l01, h23, l23;
                split_pair(p0, p1, h01, l01);
                split_pair(p2, p3, h23, l23);
                pah[2 * t] = h01; pah[2 * t + 1] = h23;
                pal[2 * t] = l01; pal[2 * t + 1] = l23;
            }
            uint32_t vbh[8][2], vbl[8][2];
#pragma unroll
            for (int j = 0; j < 8; ++j) {
                const int bw = (j * 8 + g) * VROW + kc2 * 8 + cc;
                vbh[j][0] = sVh[bw]; vbh[j][1] = sVh[bw + 4];
                vbl[j][0] = sVl[bw]; vbl[j][1] = sVl[bw + 4];
            }
#pragma unroll
            for (int j = 0; j < 8; ++j) mma16816(o[j], pah, vbh[j]);
#pragma unroll
            for (int j = 0; j < 8; ++j) mma16816(o[j], pal, vbh[j]);
#pragma unroll
            for (int j = 0; j < 8; ++j) mma16816(o[j], pah, vbl[j]);
        }
        rs0 += __shfl_xor_sync(0xffffffffu, rs0, 1);
        rs0 += __shfl_xor_sync(0xffffffffu, rs0, 2);
        rs1 += __shfl_xor_sync(0xffffffffu, rs1, 1);
        rs1 += __shfl_xor_sync(0xffffffffu, rs1, 2);
        l0 = l0 * a0 + rs0;
        l1 = l1 * a1 + rs1;

        // All warps done with V (and K stage s); refill V and prefetch K.
        __syncthreads();
        if (tid == 0) {
            if (ch + 1 < 16) issue_v(ch + 1);
            if (ch + 2 < 16) issue_k(ch + 2);
        }
    }

    // Epilogue: bf16 hi/lo attention output -> g_ab blocked
    const float i0 = 1.f / l0, i1 = 1.f / l1;
    const int b = bh >> 4, h = bh & (HH - 1);
    const int mg = b * NN + r0;
    const int mT = mg >> 7;
    const int rr = mg & 127;
#pragma unroll
    for (int j = 0; j < 8; ++j) {
        const int w = h * 32 + j * 4 + cc;
        uint32_t hp0, lp0, hp1, lp1;
        split_pair(o[j][0] * i0, o[j][1] * i0, hp0, lp0);
        split_pair(o[j][2] * i1, o[j][3] * i1, hp1, lp1);
        char* blk = g_ab + ((size_t)mT * 64 + (w >> 3)) * XBLK;
        const int off = (w & 7) * 4;
        *(uint32_t*)(blk + rr * 48 + off) = hp0;
        *(uint32_t*)(blk + 6144 + rr * 48 + off) = lp0;
        *(uint32_t*)(blk + (rr + 8) * 48 + off) = hp1;
        *(uint32_t*)(blk + 6144 + (rr + 8) * 48 + off) = lp1;
    }
}

// ---------------------------------------------------------------------------
extern "C" void kernel_launch(void* const* d_in, const int* in_sizes, int n_in,
                              void* d_out, int out_size)
{
    const float* x     = (const float*)d_in[0];
    const float* w_qkv = (const float*)d_in[1];
    const float* w_out = (const float*)d_in[2];
    float* out = (float*)d_out;

    cudaFuncSetAttribute(attn_hmma,
                         cudaFuncAttributeMaxDynamicSharedMemorySize, ATTN_SMEM);
    cudaFuncSetAttribute(qkv_gemm_hmma,
                         cudaFuncAttributeMaxDynamicSharedMemorySize, GEMM_SMEM);
    cudaFuncSetAttribute(out_gemm_hmma,
                         cudaFuncAttributeMaxDynamicSharedMemorySize, GEMM_SMEM);

    split_x_blocked<<<dim3(64, 64), 256>>>(x);
    split_wq_blocked<<<dim3(12, 64), 512>>>(w_qkv);
    split_wo_blocked<<<dim3(4, 64), 512>>>(w_out);

    {
        dim3 grid(FQKV / 128, MM / 128);   // (24, 64)
        qkv_gemm_hmma<<<grid, 128, GEMM_SMEM>>>();
    }
    {
        dim3 grid(BB * HH, NN / 64);       // (64, 32)
        attn_hmma<<<grid, 128, ATTN_SMEM>>>();
    }
    {
        dim3 grid(EE / 128, MM / 128);     // (8, 64)
        out_gemm_hmma<<<grid, 128, GEMM_SMEM>>>(out);
    }
}

// round 14
// speedup vs baseline: 4.3560x; 1.0372x over previous
#include <cuda_runtime.h>
#include <cuda_bf16.h>
#include <cstdint>

// Problem constants
#define BB 4
#define NN 2048
#define EE 1024
#define HH 16
#define DD 64
#define MM (BB * NN)        // 8192
#define FQKV (3 * EE)       // 3072
#define BHND (64 * 2048 * 64)

// Blocked-layout block sizes (bytes)
#define XBLK 12288          // A block: [hi 128x48][lo 128x48]
#define WBLK 24576          // W block: [hi 256x48][lo 256x48]
#define KVBLK 71680         // attn chunk: [Kh 18432][Kl 18432][Vh 17408][Vl 17408]

// ---------------------------------------------------------------------------
// Scratch (__device__ globals; allocation-free rule)
// ---------------------------------------------------------------------------
__device__ __nv_bfloat16 g_qh[BHND], g_ql[BHND];      // [bh][n][d], prescaled (linear)

__device__ __align__(16) char g_xb[64 * 64 * XBLK];    // X blocked  [mT][kc]
__device__ __align__(16) char g_ab[64 * 64 * XBLK];    // attn-out blocked [mT][kc]
__device__ __align__(16) char g_wqb[12 * 64 * WBLK];   // Wqkv blocked [fT256][kc]
__device__ __align__(16) char g_wob[4 * 64 * WBLK];    // Wout blocked [fT256][kc]
__device__ __align__(16) char g_kvb[64 * 16 * KVBLK];  // K/V blocked  [bh][chunk]

__device__ __forceinline__ float fast_exp2(float x) {
    float y;
    asm("ex2.approx.ftz.f32 %0, %1;" : "=f"(y) : "f"(x));
    return y;
}
__device__ __forceinline__ uint32_t pack_bf2(float lo, float hi) {
    __nv_bfloat162 t = __floats2bfloat162_rn(lo, hi);
    uint32_t r; r = *reinterpret_cast<uint32_t*>(&t); return r;
}
__device__ __forceinline__ void split_pair(float a, float b, uint32_t& hw, uint32_t& lw) {
    hw = pack_bf2(a, b);
    float fa = __int_as_float(hw << 16);
    float fb = __int_as_float(hw & 0xFFFF0000u);
    lw = pack_bf2(a - fa, b - fb);
}
__device__ __forceinline__ uint32_t smem_u32(const void* p) {
    uint32_t a;
    asm("{ .reg .u64 t; cvta.to.shared.u64 t, %1; cvt.u32.u64 %0, t; }"
        : "=r"(a) : "l"(p));
    return a;
}
__device__ __forceinline__ void mbar_init(uint32_t a, uint32_t cnt) {
    asm volatile("mbarrier.init.shared.b64 [%0], %1;" :: "r"(a), "r"(cnt) : "memory");
}
__device__ __forceinline__ void mbar_expect(uint32_t a, uint32_t bytes) {
    asm volatile("mbarrier.arrive.expect_tx.shared.b64 _, [%0], %1;"
                 :: "r"(a), "r"(bytes) : "memory");
}
__device__ __forceinline__ void mbar_wait(uint32_t addr, uint32_t parity) {
    asm volatile(
        "{\n\t.reg .pred P1;\n\t"
        "WAIT_LOOP_%=:\n\t"
        "mbarrier.try_wait.parity.acquire.cta.shared::cta.b64 P1, [%0], %1, 0x989680;\n\t"
        "@P1 bra.uni WAIT_DONE_%=;\n\t"
        "bra.uni WAIT_LOOP_%=;\n\t"
        "WAIT_DONE_%=:\n\t}"
        :: "r"(addr), "r"(parity) : "memory");
}
__device__ __forceinline__ void bulk_g2s(uint32_t dst, const void* src,
                                         uint32_t bytes, uint32_t mbar) {
    asm volatile(
        "cp.async.bulk.shared::cluster.global.mbarrier::complete_tx::bytes "
        "[%0], [%1], %2, [%3];"
        :: "r"(dst), "l"(src), "r"(bytes), "r"(mbar) : "memory");
}
__device__ __forceinline__ void fence_proxy() {
    asm volatile("fence.proxy.async.shared::cta;" ::: "memory");
}
__device__ __forceinline__ void ldsm_x4(uint32_t* r, uint32_t addr) {
    asm volatile("ldmatrix.sync.aligned.m8n8.x4.shared.b16 {%0,%1,%2,%3}, [%4];"
        : "=r"(r[0]), "=r"(r[1]), "=r"(r[2]), "=r"(r[3]) : "r"(addr));
}
__device__ __forceinline__ void mma16816(float* c, const uint32_t* a, const uint32_t* b) {
    asm volatile(
        "mma.sync.aligned.m16n8k16.row.col.f32.bf16.bf16.f32 "
        "{%0,%1,%2,%3}, {%4,%5,%6,%7}, {%8,%9}, {%0,%1,%2,%3};"
        : "+f"(c[0]), "+f"(c[1]), "+f"(c[2]), "+f"(c[3])
        : "r"(a[0]), "r"(a[1]), "r"(a[2]), "r"(a[3]),
          "r"(b[0]), "r"(b[1]));
}

// ---------------------------------------------------------------------------
// Split kernels -> blocked layouts (VERBATIM, verified)
// ---------------------------------------------------------------------------
__global__ __launch_bounds__(256) void split_x_blocked(const float* __restrict__ x) {
    const int mT = blockIdx.x, kc = blockIdx.y;
    const int t = threadIdx.x;
    const int r = t >> 1, hf = t & 1;
    const float* src = x + ((size_t)(mT * 128 + r)) * EE + kc * 16 + hf * 8;
    float4 v0 = *(const float4*)src;
    float4 v1 = *(const float4*)(src + 4);
    uint32_t h0, h1, h2, h3, l0, l1, l2, l3;
    split_pair(v0.x, v0.y, h0, l0);
    split_pair(v0.z, v0.w, h1, l1);
    split_pair(v1.x, v1.y, h2, l2);
    split_pair(v1.z, v1.w, h3, l3);
    char* blk = g_xb + ((size_t)mT * 64 + kc) * XBLK + r * 48 + hf * 16;
    *(uint4*)blk = make_uint4(h0, h1, h2, h3);
    *(uint4*)(blk + 6144) = make_uint4(l0, l1, l2, l3);
}
__global__ __launch_bounds__(512) void split_wq_blocked(const float* __restrict__ w) {
    const int fT = blockIdx.x, kc = blockIdx.y;
    const int t = threadIdx.x;
    const int r = t >> 1, hf = t & 1;
    const float* src = w + ((size_t)(fT * 256 + r)) * EE + kc * 16 + hf * 8;
    float4 v0 = *(const float4*)src;
    float4 v1 = *(const float4*)(src + 4);
    uint32_t h0, h1, h2, h3, l0, l1, l2, l3;
    split_pair(v0.x, v0.y, h0, l0);
    split_pair(v0.z, v0.w, h1, l1);
    split_pair(v1.x, v1.y, h2, l2);
    split_pair(v1.z, v1.w, h3, l3);
    char* blk = g_wqb + ((size_t)fT * 64 + kc) * WBLK + r * 48 + hf * 16;
    *(uint4*)blk = make_uint4(h0, h1, h2, h3);
    *(uint4*)(blk + 12288) = make_uint4(l0, l1, l2, l3);
}
__global__ __launch_bounds__(512) void split_wo_blocked(const float* __restrict__ w) {
    const int fT = blockIdx.x, kc = blockIdx.y;
    const int t = threadIdx.x;
    const int r = t >> 1, hf = t & 1;
    const float* src = w + ((size_t)(fT * 256 + r)) * EE + kc * 16 + hf * 8;
    float4 v0 = *(const float4*)src;
    float4 v1 = *(const float4*)(src + 4);
    uint32_t h0, h1, h2, h3, l0, l1, l2, l3;
    split_pair(v0.x, v0.y, h0, l0);
    split_pair(v0.z, v0.w, h1, l1);
    split_pair(v1.x, v1.y, h2, l2);
    split_pair(v1.z, v1.w, h3, l3);
    char* blk = g_wob + ((size_t)fT * 64 + kc) * WBLK + r * 48 + hf * 16;
    *(uint4*)blk = make_uint4(h0, h1, h2, h3);
    *(uint4*)(blk + 12288) = make_uint4(l0, l1, l2, l3);
}

// ---------------------------------------------------------------------------
// 3-split HMMA GEMM: CTA 128x128, 8 warps (2x4), warp tile 64x32.
// 4 stages x 1 K-chunk (verified pipeline), 2 CTAs/SM, <=128 regs/thread.
// ---------------------------------------------------------------------------
#define GSTG 24576
#define GSTAGES 4
#define GEMM_SMEM (GSTAGES * GSTG + 64)      // 98368

__device__ __forceinline__ void hmma_mainloop256(
    uint32_t* sm, const char* aBlocks, const char* bBase, float (&acc)[4][4][4])
{
    const int tid = threadIdx.x;
    const int lane = tid & 31;
    const int wid = tid >> 5;
    const int wm = wid >> 2;           // 0..1
    const int wn = wid & 3;            // 0..3
    const uint32_t sb = smem_u32(sm);
    const uint32_t mb = sb + GSTAGES * GSTG;

#pragma unroll
    for (int i = 0; i < 4; ++i)
#pragma unroll
        for (int j = 0; j < 4; ++j)
#pragma unroll
            for (int r = 0; r < 4; ++r) acc[i][j][r] = 0.f;

    const uint32_t aoffb = (uint32_t)((lane & 15) * 48 + (lane >> 4) * 16);
    const uint32_t boffb = (uint32_t)(((lane & 7) + (lane >> 4) * 8) * 48 + ((lane >> 3) & 1) * 16);

    if (tid == 0) {
#pragma unroll
        for (int s = 0; s < GSTAGES; ++s) mbar_init(mb + 8 * s, 1);
    }
    fence_proxy();
    __syncthreads();

    auto issue = [&](int ch) {
        const int s = ch & 3;
        const uint32_t m = mb + 8 * s;
        const uint32_t d = sb + (uint32_t)s * GSTG;
        mbar_expect(m, GSTG);
        bulk_g2s(d, aBlocks + (size_t)ch * XBLK, XBLK, m);
        bulk_g2s(d + XBLK, bBase + (size_t)ch * WBLK, 6144, m);
        bulk_g2s(d + XBLK + 6144, bBase + (size_t)ch * WBLK + 12288, 6144, m);
    };

    if (tid == 0) { issue(0); issue(1); issue(2); }

    for (int ch = 0; ch < 64; ++ch) {
        const int s = ch & 3;
        __syncthreads();                 // all warps done reading stage (ch-1)&3
        if (tid == 0 && ch + 3 < 64) issue(ch + 3);
        mbar_wait(mb + 8 * s, (ch >> 2) & 1);

        const uint32_t stb = sb + (uint32_t)s * GSTG;
        const uint32_t aHb = stb;
        const uint32_t aLb = stb + 6144;
        const uint32_t bHb = stb + 12288;
        const uint32_t bLb = stb + 18432;

        uint32_t bh[4][2], bl[4][2];
#pragma unroll
        for (int jp = 0; jp < 2; ++jp) {
            const uint32_t ar = (uint32_t)((wn * 32 + jp * 16) * 48) + boffb;
            uint32_t r4[4];
            ldsm_x4(r4, bHb + ar);
            bh[jp * 2][0] = r4[0]; bh[jp * 2][1] = r4[1];
            bh[jp * 2 + 1][0] = r4[2]; bh[jp * 2 + 1][1] = r4[3];
            ldsm_x4(r4, bLb + ar);
            bl[jp * 2][0] = r4[0]; bl[jp * 2][1] = r4[1];
            bl[jp * 2 + 1][0] = r4[2]; bl[jp * 2 + 1][1] = r4[3];
        }
#pragma unroll
        for (int i = 0; i < 4; ++i) {
            const uint32_t ao = (uint32_t)((wm * 64 + i * 16) * 48) + aoffb;
            uint32_t ah4[4], al4[4];
            ldsm_x4(ah4, aHb + ao);
            ldsm_x4(al4, aLb + ao);
#pragma unroll
            for (int j = 0; j < 4; ++j) mma16816(acc[i][j], ah4, bh[j]);
#pragma unroll
            for (int j = 0; j < 4; ++j) mma16816(acc[i][j], ah4, bl[j]);
#pragma unroll
            for (int j = 0; j < 4; ++j) mma16816(acc[i][j], al4, bh[j]);
        }
    }
}

// ---------------------------------------------------------------------------
// QKV GEMM: epilogue writes Q (linear bf16 hi/lo) and blocked K/V (g_kvb)
// ---------------------------------------------------------------------------
__global__ __launch_bounds__(256, 2) void qkv_gemm_hmma() {
    extern __shared__ __align__(16) uint32_t smg[];
    const int mBase = blockIdx.y * 128;
    const int fBase = blockIdx.x * 128;
    float acc[4][4][4];
    const char* aBlocks = g_xb + (size_t)blockIdx.y * 64 * XBLK;
    const char* bBase = g_wqb + (size_t)(blockIdx.x >> 1) * 64 * WBLK
                      + (size_t)(blockIdx.x & 1) * 6144;
    hmma_mainloop256(smg, aBlocks, bBase, acc);

    const int tid = threadIdx.x;
    const int lane = tid & 31;
    const int wid = tid >> 5;
    const int wm = wid >> 2, wn = wid & 3;
    const int g = lane >> 2, cc = lane & 3;
    const int which = fBase >> 10;     // uniform per CTA

    if (which == 2) {
#pragma unroll
        for (int i = 0; i < 4; ++i) {
            const int m0 = mBase + wm * 64 + i * 16 + g;
            const int b = m0 >> 11;
            const int n0 = m0 & (NN - 1);
#pragma unroll
            for (int j = 0; j < 4; ++j) {
                const int col = fBase + wn * 32 + j * 8 + cc * 2;
                const int h = (col >> 6) & (HH - 1);
                const int d0 = col & (DD - 1);
                char* blk = g_kvb + ((size_t)((b * HH + h) * 16) + (n0 >> 7)) * KVBLK + 36864;
#pragma unroll
                for (int r = 0; r < 4; ++r) {
                    const int dd = d0 + (r & 1);
                    const int nn = (n0 & 127) + (r >> 1) * 8;
                    float v = acc[i][j][r];
                    __nv_bfloat16 hh = __float2bfloat16(v);
                    __nv_bfloat16 ll = __float2bfloat16(v - __bfloat162float(hh));
                    *(__nv_bfloat16*)(blk + dd * 272 + nn * 2) = hh;
                    *(__nv_bfloat16*)(blk + 17408 + dd * 272 + nn * 2) = ll;
                }
            }
        }
    } else if (which == 1) {
#pragma unroll
        for (int i = 0; i < 4; ++i) {
            const int m0 = mBase + wm * 64 + i * 16 + g;
            const int b = m0 >> 11;
            const int n0 = m0 & (NN - 1);
#pragma unroll
            for (int j = 0; j < 4; ++j) {
                const int col = fBase + wn * 32 + j * 8 + cc * 2;
                const int h = (col >> 6) & (HH - 1);
                const int d0 = col & (DD - 1);
                char* blk = g_kvb + ((size_t)((b * HH + h) * 16) + (n0 >> 7)) * KVBLK;
                const int rr = n0 & 127;
                uint32_t hp0, lp0, hp1, lp1;
                split_pair(acc[i][j][0], acc[i][j][1], hp0, lp0);
                split_pair(acc[i][j][2], acc[i][j][3], hp1, lp1);
                *(uint32_t*)(blk + rr * 144 + d0 * 2) = hp0;
                *(uint32_t*)(blk + 18432 + rr * 144 + d0 * 2) = lp0;
                *(uint32_t*)(blk + (rr + 8) * 144 + d0 * 2) = hp1;
                *(uint32_t*)(blk + 18432 + (rr + 8) * 144 + d0 * 2) = lp1;
            }
        }
    } else {
        const float qs = 0.125f * 1.44269504f;
        uint32_t* ph_ = (uint32_t*)g_qh;
        uint32_t* pl_ = (uint32_t*)g_ql;
#pragma unroll
        for (int i = 0; i < 4; ++i) {
            const int m0 = mBase + wm * 64 + i * 16 + g;
            const int b = m0 >> 11;
            const int n0 = m0 & (NN - 1);
#pragma unroll
            for (int j = 0; j < 4; ++j) {
                const int col = fBase + wn * 32 + j * 8 + cc * 2;
                const int h = (col >> 6) & (HH - 1);
                const int d0 = col & (DD - 1);
                const size_t rowbase = (size_t)(b * HH + h) * NN;
                uint32_t hp0, lp0, hp1, lp1;
                split_pair(acc[i][j][0] * qs, acc[i][j][1] * qs, hp0, lp0);
                split_pair(acc[i][j][2] * qs, acc[i][j][3] * qs, hp1, lp1);
                ph_[(rowbase + n0) * 32 + (d0 >> 1)] = hp0;
                pl_[(rowbase + n0) * 32 + (d0 >> 1)] = lp0;
                ph_[(rowbase + n0 + 8) * 32 + (d0 >> 1)] = hp1;
                pl_[(rowbase + n0 + 8) * 32 + (d0 >> 1)] = lp1;
            }
        }
    }
}

// ---------------------------------------------------------------------------
// Output projection GEMM
// ---------------------------------------------------------------------------
__global__ __launch_bounds__(256, 2) void out_gemm_hmma(float* __restrict__ Cout) {
    extern __shared__ __align__(16) uint32_t smg[];
    const int mBase = blockIdx.y * 128;
    const int fBase = blockIdx.x * 128;
    float acc[4][4][4];
    const char* aBlocks = g_ab + (size_t)blockIdx.y * 64 * XBLK;
    const char* bBase = g_wob + (size_t)(blockIdx.x >> 1) * 64 * WBLK
                      + (size_t)(blockIdx.x & 1) * 6144;
    hmma_mainloop256(smg, aBlocks, bBase, acc);

    const int tid = threadIdx.x;
    const int lane = tid & 31;
    const int wid = tid >> 5;
    const int wm = wid >> 2, wn = wid & 3;
    const int g = lane >> 2, cc = lane & 3;

#pragma unroll
    for (int i = 0; i < 4; ++i) {
        const int m0 = mBase + wm * 64 + i * 16 + g;
#pragma unroll
        for (int j = 0; j < 4; ++j) {
            const int col = fBase + wn * 32 + j * 8 + cc * 2;
            float* d1 = Cout + (size_t)m0 * EE + col;
            float* d2 = Cout + (size_t)(m0 + 8) * EE + col;
            *(float2*)d1 = make_float2(acc[i][j][0], acc[i][j][1]);
            *(float2*)d2 = make_float2(acc[i][j][2], acc[i][j][3]);
        }
    }
}

// ---------------------------------------------------------------------------
// Flash attention (VERBATIM round 13, verified): 128 threads, q-tile 64,
// K double-buffered, V single-buffered, 2 CTAs/SM target.
// ---------------------------------------------------------------------------
#define KROW 36
#define VROW 68
#define KWORDS (128 * KROW)
#define VWORDS (64 * VROW)
#define KBYTES (KWORDS * 4)                 // 18432
#define VBYTES (VWORDS * 4)                 // 17408
#define KSTG_B (2 * KBYTES)                 // 36864
#define VSTG_B (2 * VBYTES)                 // 34816
#define ATTN_SMEM (2 * KSTG_B + VSTG_B + 64)  // 108608

__global__ __launch_bounds__(128) void attn_hmma() {
    extern __shared__ __align__(16) uint32_t smdyn[];

    const int bh = blockIdx.x;
    const int qt = blockIdx.y;
    const int tid = threadIdx.x;
    const int lane = tid & 31, wid = tid >> 5;
    const int g = lane >> 2, cc = lane & 3;

    const size_t qoff = (size_t)bh * NN * DD;
    const uint32_t* qhw = (const uint32_t*)g_qh + (qoff >> 1);
    const uint32_t* qlw = (const uint32_t*)g_ql + (qoff >> 1);
    const char* kvsrc = g_kvb + (size_t)bh * 16 * KVBLK;
    const uint32_t sb = smem_u32(smdyn);
    const uint32_t mb = sb + 2 * KSTG_B + VSTG_B;

    const int r0 = qt * 64 + wid * 16 + g;
    uint32_t qa[4][4], qb[4][4];
#pragma unroll
    for (int kc = 0; kc < 4; ++kc) {
        const int w0 = r0 * 32 + kc * 8 + cc;
        qa[kc][0] = qhw[w0];       qa[kc][1] = qhw[w0 + 256];
        qa[kc][2] = qhw[w0 + 4];   qa[kc][3] = qhw[w0 + 260];
        qb[kc][0] = qlw[w0];       qb[kc][1] = qlw[w0 + 256];
        qb[kc][2] = qlw[w0 + 4];   qb[kc][3] = qlw[w0 + 260];
    }

    float o[8][4];
#pragma unroll
    for (int j = 0; j < 8; ++j) { o[j][0] = o[j][1] = o[j][2] = o[j][3] = 0.f; }
    float m0 = -30000.f, m1 = -30000.f, l0 = 0.f, l1 = 0.f;

    if (tid == 0) { mbar_init(mb, 1); mbar_init(mb + 8, 1); mbar_init(mb + 16, 1); }
    fence_proxy();
    __syncthreads();

    auto issue_k = [&](int kt) {
        const int s = kt & 1;
        const uint32_t m = mb + 8 * s;
        const uint32_t d = sb + (uint32_t)s * KSTG_B;
        const char* src = kvsrc + (size_t)kt * KVBLK;
        mbar_expect(m, KSTG_B);
        bulk_g2s(d, src, KBYTES, m);
        bulk_g2s(d + KBYTES, src + KBYTES, KBYTES, m);
    };
    auto issue_v = [&](int kt) {
        const uint32_t m = mb + 16;
        const uint32_t d = sb + 2 * KSTG_B;
        const char* src = kvsrc + (size_t)kt * KVBLK + 2 * KBYTES;
        mbar_expect(m, VSTG_B);
        bulk_g2s(d, src, VSTG_B, m);
    };

    if (tid == 0) { issue_k(0); issue_v(0); issue_k(1); }

    for (int ch = 0; ch < 16; ++ch) {
        const int s = ch & 1;
        mbar_wait(mb + 8 * s, (ch >> 1) & 1);

        const uint32_t* sKh = smdyn + (size_t)s * (KSTG_B / 4);
        const uint32_t* sKl = sKh + KWORDS;
        const uint32_t* sVh = smdyn + 2 * (KSTG_B / 4);
        const uint32_t* sVl = sVh + VWORDS;

        float sc[16][4];
#pragma unroll
        for (int j = 0; j < 16; ++j) { sc[j][0] = sc[j][1] = sc[j][2] = sc[j][3] = 0.f; }
#pragma unroll
        for (int kc = 0; kc < 4; ++kc) {
            uint32_t kbh[16][2], kbl[16][2];
#pragma unroll
            for (int j = 0; j < 16; ++j) {
                const int bw = (j * 8 + g) * KROW + kc * 8 + cc;
                kbh[j][0] = sKh[bw]; kbh[j][1] = sKh[bw + 4];
                kbl[j][0] = sKl[bw]; kbl[j][1] = sKl[bw + 4];
            }
#pragma unroll
            for (int j = 0; j < 16; ++j) mma16816(sc[j], qa[kc], kbh[j]);
#pragma unroll
            for (int j = 0; j < 16; ++j) mma16816(sc[j], qa[kc], kbl[j]);
#pragma unroll
            for (int j = 0; j < 16; ++j) mma16816(sc[j], qb[kc], kbh[j]);
        }

        float cm0 = -30000.f, cm1 = -30000.f;
#pragma unroll
        for (int j = 0; j < 16; ++j) {
            cm0 = fmaxf(cm0, fmaxf(sc[j][0], sc[j][1]));
            cm1 = fmaxf(cm1, fmaxf(sc[j][2], sc[j][3]));
        }
        cm0 = fmaxf(cm0, __shfl_xor_sync(0xffffffffu, cm0, 1));
        cm0 = fmaxf(cm0, __shfl_xor_sync(0xffffffffu, cm0, 2));
        cm1 = fmaxf(cm1, __shfl_xor_sync(0xffffffffu, cm1, 1));
        cm1 = fmaxf(cm1, __shfl_xor_sync(0xffffffffu, cm1, 2));
        const float mn0 = fmaxf(m0, cm0), mn1 = fmaxf(m1, cm1);
        const float a0 = fast_exp2(m0 - mn0), a1 = fast_exp2(m1 - mn1);
        m0 = mn0; m1 = mn1;
#pragma unroll
        for (int j = 0; j < 8; ++j) {
            o[j][0] *= a0; o[j][1] *= a0; o[j][2] *= a1; o[j][3] *= a1;
        }

        mbar_wait(mb + 16, ch & 1);

        float rs0 = 0.f, rs1 = 0.f;
#pragma unroll
        for (int kc2 = 0; kc2 < 8; ++kc2) {
            uint32_t pah[4], pal[4];
#pragma unroll
            for (int t = 0; t < 2; ++t) {
                const int j = kc2 * 2 + t;
                float p0 = fast_exp2(sc[j][0] - m0);
                float p1 = fast_exp2(sc[j][1] - m0);
                float p2 = fast_exp2(sc[j][2] - m1);
                float p3 = fast_exp2(sc[j][3] - m1);
                rs0 += p0 + p1; rs1 += p2 + p3;
                uint32_t h01, l01, h23, l23;
                split_pair(p0, p1, h01, l01);
                split_pair(p2, p3, h23, l23);
                pah[2 * t] = h01; pah[2 * t + 1] = h23;
                pal[2 * t] = l01; pal[2 * t + 1] = l23;
            }
            uint32_t vbh[8][2], vbl[8][2];
#pragma unroll
            for (int j = 0; j < 8; ++j) {
                const int bw = (j * 8 + g) * VROW + kc2 * 8 + cc;
                vbh[j][0] = sVh[bw]; vbh[j][1] = sVh[bw + 4];
                vbl[j][0] = sVl[bw]; vbl[j][1] = sVl[bw + 4];
            }
#pragma unroll
            for (int j = 0; j < 8; ++j) mma16816(o[j], pah, vbh[j]);
#pragma unroll
            for (int j = 0; j < 8; ++j) mma16816(o[j], pal, vbh[j]);
#pragma unroll
            for (int j = 0; j < 8; ++j) mma16816(o[j], pah, vbl[j]);
        }
        rs0 += __shfl_xor_sync(0xffffffffu, rs0, 1);
        rs0 += __shfl_xor_sync(0xffffffffu, rs0, 2);
        rs1 += __shfl_xor_sync(0xffffffffu, rs1, 1);
        rs1 += __shfl_xor_sync(0xffffffffu, rs1, 2);
        l0 = l0 * a0 + rs0;
        l1 = l1 * a1 + rs1;

        __syncthreads();
        if (tid == 0) {
            if (ch + 1 < 16) issue_v(ch + 1);
            if (ch + 2 < 16) issue_k(ch + 2);
        }
    }

    const float i0 = 1.f / l0, i1 = 1.f / l1;
    const int b = bh >> 4, h = bh & (HH - 1);
    const int mg = b * NN + r0;
    const int mT = mg >> 7;
    const int rr = mg & 127;
#pragma unroll
    for (int j = 0; j < 8; ++j) {
        const int w = h * 32 + j * 4 + cc;
        uint32_t hp0, lp0, hp1, lp1;
        split_pair(o[j][0] * i0, o[j][1] * i0, hp0, lp0);
        split_pair(o[j][2] * i1, o[j][3] * i1, hp1, lp1);
        char* blk = g_ab + ((size_t)mT * 64 + (w >> 3)) * XBLK;
        const int off = (w & 7) * 4;
        *(uint32_t*)(blk + rr * 48 + off) = hp0;
        *(uint32_t*)(blk + 6144 + rr * 48 + off) = lp0;
        *(uint32_t*)(blk + (rr + 8) * 48 + off) = hp1;
        *(uint32_t*)(blk + 6144 + (rr + 8) * 48 + off) = lp1;
    }
}

// ---------------------------------------------------------------------------
extern "C" void kernel_launch(void* const* d_in, const int* in_sizes, int n_in,
                              void* d_out, int out_size)
{
    const float* x     = (const float*)d_in[0];
    const float* w_qkv = (const float*)d_in[1];
    const float* w_out = (const float*)d_in[2];
    float* out = (float*)d_out;

    cudaFuncSetAttribute(attn_hmma,
                         cudaFuncAttributeMaxDynamicSharedMemorySize, ATTN_SMEM);
    cudaFuncSetAttribute(qkv_gemm_hmma,
                         cudaFuncAttributeMaxDynamicSharedMemorySize, GEMM_SMEM);
    cudaFuncSetAttribute(out_gemm_hmma,
                         cudaFuncAttributeMaxDynamicSharedMemorySize, GEMM_SMEM);

    split_x_blocked<<<dim3(64, 64), 256>>>(x);
    split_wq_blocked<<<dim3(12, 64), 512>>>(w_qkv);
    split_wo_blocked<<<dim3(4, 64), 512>>>(w_out);

    {
        dim3 grid(FQKV / 128, MM / 128);   // (24, 64)
        qkv_gemm_hmma<<<grid, 256, GEMM_SMEM>>>();
    }
    {
        dim3 grid(BB * HH, NN / 64);       // (64, 32)
        attn_hmma<<<grid, 128, ATTN_SMEM>>>();
    }
    {
        dim3 grid(EE / 128, MM / 128);     // (8, 64)
        out_gemm_hmma<<<grid, 256, GEMM_SMEM>>>(out);
    }
}

// round 15
// speedup vs baseline: 5.1677x; 1.1864x over previous
#include <cuda_runtime.h>
#include <cuda_bf16.h>
#include <cuda_fp16.h>
#include <cstdint>

// Problem constants
#define BB 4
#define NN 2048
#define EE 1024
#define HH 16
#define DD 64
#define MM (BB * NN)        // 8192
#define FQKV (3 * EE)       // 3072
#define BHND (64 * 2048 * 64)

// Blocked-layout block sizes (bytes)
#define XBLK 12288          // A block: [hi 128x48][lo 128x48]
#define WBLK 24576          // W block: [hi 256x48][lo 256x48]
#define KVBLK 71680         // attn chunk: [Kh 18432][Kl 18432][Vf16 17408][pad 17408]

// ---------------------------------------------------------------------------
// Scratch (__device__ globals; allocation-free rule)
// ---------------------------------------------------------------------------
__device__ __nv_bfloat16 g_qh[BHND], g_ql[BHND];      // [bh][n][d], prescaled (linear)

__device__ __align__(16) char g_xb[64 * 64 * XBLK];    // X blocked  [mT][kc]
__device__ __align__(16) char g_ab[64 * 64 * XBLK];    // attn-out blocked [mT][kc]
__device__ __align__(16) char g_wqb[12 * 64 * WBLK];   // Wqkv blocked [fT256][kc]
__device__ __align__(16) char g_wob[4 * 64 * WBLK];    // Wout blocked [fT256][kc]
__device__ __align__(16) char g_kvb[64 * 16 * KVBLK];  // K/V blocked  [bh][chunk]

__device__ __forceinline__ float fast_exp2(float x) {
    float y;
    asm("ex2.approx.ftz.f32 %0, %1;" : "=f"(y) : "f"(x));
    return y;
}
__device__ __forceinline__ uint32_t pack_bf2(float lo, float hi) {
    __nv_bfloat162 t = __floats2bfloat162_rn(lo, hi);
    uint32_t r; r = *reinterpret_cast<uint32_t*>(&t); return r;
}
__device__ __forceinline__ uint32_t pack_h2(float lo, float hi) {
    __half2 t = __floats2half2_rn(lo, hi);
    uint32_t r; r = *reinterpret_cast<uint32_t*>(&t); return r;
}
__device__ __forceinline__ void split_pair(float a, float b, uint32_t& hw, uint32_t& lw) {
    hw = pack_bf2(a, b);
    float fa = __int_as_float(hw << 16);
    float fb = __int_as_float(hw & 0xFFFF0000u);
    lw = pack_bf2(a - fa, b - fb);
}
__device__ __forceinline__ uint32_t smem_u32(const void* p) {
    uint32_t a;
    asm("{ .reg .u64 t; cvta.to.shared.u64 t, %1; cvt.u32.u64 %0, t; }"
        : "=r"(a) : "l"(p));
    return a;
}
__device__ __forceinline__ void mbar_init(uint32_t a, uint32_t cnt) {
    asm volatile("mbarrier.init.shared.b64 [%0], %1;" :: "r"(a), "r"(cnt) : "memory");
}
__device__ __forceinline__ void mbar_expect(uint32_t a, uint32_t bytes) {
    asm volatile("mbarrier.arrive.expect_tx.shared.b64 _, [%0], %1;"
                 :: "r"(a), "r"(bytes) : "memory");
}
__device__ __forceinline__ void mbar_wait(uint32_t addr, uint32_t parity) {
    asm volatile(
        "{\n\t.reg .pred P1;\n\t"
        "WAIT_LOOP_%=:\n\t"
        "mbarrier.try_wait.parity.acquire.cta.shared::cta.b64 P1, [%0], %1, 0x989680;\n\t"
        "@P1 bra.uni WAIT_DONE_%=;\n\t"
        "bra.uni WAIT_LOOP_%=;\n\t"
        "WAIT_DONE_%=:\n\t}"
        :: "r"(addr), "r"(parity) : "memory");
}
__device__ __forceinline__ void bulk_g2s(uint32_t dst, const void* src,
                                         uint32_t bytes, uint32_t mbar) {
    asm volatile(
        "cp.async.bulk.shared::cluster.global.mbarrier::complete_tx::bytes "
        "[%0], [%1], %2, [%3];"
        :: "r"(dst), "l"(src), "r"(bytes), "r"(mbar) : "memory");
}
__device__ __forceinline__ void fence_proxy() {
    asm volatile("fence.proxy.async.shared::cta;" ::: "memory");
}
__device__ __forceinline__ void ldsm_x4(uint32_t* r, uint32_t addr) {
    asm volatile("ldmatrix.sync.aligned.m8n8.x4.shared.b16 {%0,%1,%2,%3}, [%4];"
        : "=r"(r[0]), "=r"(r[1]), "=r"(r[2]), "=r"(r[3]) : "r"(addr));
}
__device__ __forceinline__ void mma16816(float* c, const uint32_t* a, const uint32_t* b) {
    asm volatile(
        "mma.sync.aligned.m16n8k16.row.col.f32.bf16.bf16.f32 "
        "{%0,%1,%2,%3}, {%4,%5,%6,%7}, {%8,%9}, {%0,%1,%2,%3};"
        : "+f"(c[0]), "+f"(c[1]), "+f"(c[2]), "+f"(c[3])
        : "r"(a[0]), "r"(a[1]), "r"(a[2]), "r"(a[3]),
          "r"(b[0]), "r"(b[1]));
}
__device__ __forceinline__ void mma16816f(float* c, const uint32_t* a, const uint32_t* b) {
    asm volatile(
        "mma.sync.aligned.m16n8k16.row.col.f32.f16.f16.f32 "
        "{%0,%1,%2,%3}, {%4,%5,%6,%7}, {%8,%9}, {%0,%1,%2,%3};"
        : "+f"(c[0]), "+f"(c[1]), "+f"(c[2]), "+f"(c[3])
        : "r"(a[0]), "r"(a[1]), "r"(a[2]), "r"(a[3]),
          "r"(b[0]), "r"(b[1]));
}

// ---------------------------------------------------------------------------
// Split kernels -> blocked layouts (VERBATIM, verified)
// ---------------------------------------------------------------------------
__global__ __launch_bounds__(256) void split_x_blocked(const float* __restrict__ x) {
    const int mT = blockIdx.x, kc = blockIdx.y;
    const int t = threadIdx.x;
    const int r = t >> 1, hf = t & 1;
    const float* src = x + ((size_t)(mT * 128 + r)) * EE + kc * 16 + hf * 8;
    float4 v0 = *(const float4*)src;
    float4 v1 = *(const float4*)(src + 4);
    uint32_t h0, h1, h2, h3, l0, l1, l2, l3;
    split_pair(v0.x, v0.y, h0, l0);
    split_pair(v0.z, v0.w, h1, l1);
    split_pair(v1.x, v1.y, h2, l2);
    split_pair(v1.z, v1.w, h3, l3);
    char* blk = g_xb + ((size_t)mT * 64 + kc) * XBLK + r * 48 + hf * 16;
    *(uint4*)blk = make_uint4(h0, h1, h2, h3);
    *(uint4*)(blk + 6144) = make_uint4(l0, l1, l2, l3);
}
__global__ __launch_bounds__(512) void split_wq_blocked(const float* __restrict__ w) {
    const int fT = blockIdx.x, kc = blockIdx.y;
    const int t = threadIdx.x;
    const int r = t >> 1, hf = t & 1;
    const float* src = w + ((size_t)(fT * 256 + r)) * EE + kc * 16 + hf * 8;
    float4 v0 = *(const float4*)src;
    float4 v1 = *(const float4*)(src + 4);
    uint32_t h0, h1, h2, h3, l0, l1, l2, l3;
    split_pair(v0.x, v0.y, h0, l0);
    split_pair(v0.z, v0.w, h1, l1);
    split_pair(v1.x, v1.y, h2, l2);
    split_pair(v1.z, v1.w, h3, l3);
    char* blk = g_wqb + ((size_t)fT * 64 + kc) * WBLK + r * 48 + hf * 16;
    *(uint4*)blk = make_uint4(h0, h1, h2, h3);
    *(uint4*)(blk + 12288) = make_uint4(l0, l1, l2, l3);
}
__global__ __launch_bounds__(512) void split_wo_blocked(const float* __restrict__ w) {
    const int fT = blockIdx.x, kc = blockIdx.y;
    const int t = threadIdx.x;
    const int r = t >> 1, hf = t & 1;
    const float* src = w + ((size_t)(fT * 256 + r)) * EE + kc * 16 + hf * 8;
    float4 v0 = *(const float4*)src;
    float4 v1 = *(const float4*)(src + 4);
    uint32_t h0, h1, h2, h3, l0, l1, l2, l3;
    split_pair(v0.x, v0.y, h0, l0);
    split_pair(v0.z, v0.w, h1, l1);
    split_pair(v1.x, v1.y, h2, l2);
    split_pair(v1.z, v1.w, h3, l3);
    char* blk = g_wob + ((size_t)fT * 64 + kc) * WBLK + r * 48 + hf * 16;
    *(uint4*)blk = make_uint4(h0, h1, h2, h3);
    *(uint4*)(blk + 12288) = make_uint4(l0, l1, l2, l3);
}

// ---------------------------------------------------------------------------
// 3-split HMMA GEMM (VERBATIM round 14, verified): CTA 128x128, 8 warps (2x4),
// warp tile 64x32, 4 stages, 2 CTAs/SM, <=128 regs.
// ---------------------------------------------------------------------------
#define GSTG 24576
#define GSTAGES 4
#define GEMM_SMEM (GSTAGES * GSTG + 64)      // 98368

__device__ __forceinline__ void hmma_mainloop256(
    uint32_t* sm, const char* aBlocks, const char* bBase, float (&acc)[4][4][4])
{
    const int tid = threadIdx.x;
    const int lane = tid & 31;
    const int wid = tid >> 5;
    const int wm = wid >> 2;
    const int wn = wid & 3;
    const uint32_t sb = smem_u32(sm);
    const uint32_t mb = sb + GSTAGES * GSTG;

#pragma unroll
    for (int i = 0; i < 4; ++i)
#pragma unroll
        for (int j = 0; j < 4; ++j)
#pragma unroll
            for (int r = 0; r < 4; ++r) acc[i][j][r] = 0.f;

    const uint32_t aoffb = (uint32_t)((lane & 15) * 48 + (lane >> 4) * 16);
    const uint32_t boffb = (uint32_t)(((lane & 7) + (lane >> 4) * 8) * 48 + ((lane >> 3) & 1) * 16);

    if (tid == 0) {
#pragma unroll
        for (int s = 0; s < GSTAGES; ++s) mbar_init(mb + 8 * s, 1);
    }
    fence_proxy();
    __syncthreads();

    auto issue = [&](int ch) {
        const int s = ch & 3;
        const uint32_t m = mb + 8 * s;
        const uint32_t d = sb + (uint32_t)s * GSTG;
        mbar_expect(m, GSTG);
        bulk_g2s(d, aBlocks + (size_t)ch * XBLK, XBLK, m);
        bulk_g2s(d + XBLK, bBase + (size_t)ch * WBLK, 6144, m);
        bulk_g2s(d + XBLK + 6144, bBase + (size_t)ch * WBLK + 12288, 6144, m);
    };

    if (tid == 0) { issue(0); issue(1); issue(2); }

    for (int ch = 0; ch < 64; ++ch) {
        const int s = ch & 3;
        __syncthreads();
        if (tid == 0 && ch + 3 < 64) issue(ch + 3);
        mbar_wait(mb + 8 * s, (ch >> 2) & 1);

        const uint32_t stb = sb + (uint32_t)s * GSTG;
        const uint32_t aHb = stb;
        const uint32_t aLb = stb + 6144;
        const uint32_t bHb = stb + 12288;
        const uint32_t bLb = stb + 18432;

        uint32_t bh[4][2], bl[4][2];
#pragma unroll
        for (int jp = 0; jp < 2; ++jp) {
            const uint32_t ar = (uint32_t)((wn * 32 + jp * 16) * 48) + boffb;
            uint32_t r4[4];
            ldsm_x4(r4, bHb + ar);
            bh[jp * 2][0] = r4[0]; bh[jp * 2][1] = r4[1];
            bh[jp * 2 + 1][0] = r4[2]; bh[jp * 2 + 1][1] = r4[3];
            ldsm_x4(r4, bLb + ar);
            bl[jp * 2][0] = r4[0]; bl[jp * 2][1] = r4[1];
            bl[jp * 2 + 1][0] = r4[2]; bl[jp * 2 + 1][1] = r4[3];
        }
#pragma unroll
        for (int i = 0; i < 4; ++i) {
            const uint32_t ao = (uint32_t)((wm * 64 + i * 16) * 48) + aoffb;
            uint32_t ah4[4], al4[4];
            ldsm_x4(ah4, aHb + ao);
            ldsm_x4(al4, aLb + ao);
#pragma unroll
            for (int j = 0; j < 4; ++j) mma16816(acc[i][j], ah4, bh[j]);
#pragma unroll
            for (int j = 0; j < 4; ++j) mma16816(acc[i][j], ah4, bl[j]);
#pragma unroll
            for (int j = 0; j < 4; ++j) mma16816(acc[i][j], al4, bh[j]);
        }
    }
}

// ---------------------------------------------------------------------------
// QKV GEMM: epilogue writes Q (linear bf16 hi/lo), K (bf16 hi/lo blocked),
// V (fp16, hi slot only).
// ---------------------------------------------------------------------------
__global__ __launch_bounds__(256, 2) void qkv_gemm_hmma() {
    extern __shared__ __align__(16) uint32_t smg[];
    const int mBase = blockIdx.y * 128;
    const int fBase = blockIdx.x * 128;
    float acc[4][4][4];
    const char* aBlocks = g_xb + (size_t)blockIdx.y * 64 * XBLK;
    const char* bBase = g_wqb + (size_t)(blockIdx.x >> 1) * 64 * WBLK
                      + (size_t)(blockIdx.x & 1) * 6144;
    hmma_mainloop256(smg, aBlocks, bBase, acc);

    const int tid = threadIdx.x;
    const int lane = tid & 31;
    const int wid = tid >> 5;
    const int wm = wid >> 2, wn = wid & 3;
    const int g = lane >> 2, cc = lane & 3;
    const int which = fBase >> 10;

    if (which == 2) {
        // V -> fp16 in g_kvb (hi slot only; lo slot unused)
#pragma unroll
        for (int i = 0; i < 4; ++i) {
            const int m0 = mBase + wm * 64 + i * 16 + g;
            const int b = m0 >> 11;
            const int n0 = m0 & (NN - 1);
#pragma unroll
            for (int j = 0; j < 4; ++j) {
                const int col = fBase + wn * 32 + j * 8 + cc * 2;
                const int h = (col >> 6) & (HH - 1);
                const int d0 = col & (DD - 1);
                char* blk = g_kvb + ((size_t)((b * HH + h) * 16) + (n0 >> 7)) * KVBLK + 36864;
#pragma unroll
                for (int r = 0; r < 4; ++r) {
                    const int dd = d0 + (r & 1);
                    const int nn = (n0 & 127) + (r >> 1) * 8;
                    *(__half*)(blk + dd * 272 + nn * 2) = __float2half_rn(acc[i][j][r]);
                }
            }
        }
    } else if (which == 1) {
#pragma unroll
        for (int i = 0; i < 4; ++i) {
            const int m0 = mBase + wm * 64 + i * 16 + g;
            const int b = m0 >> 11;
            const int n0 = m0 & (NN - 1);
#pragma unroll
            for (int j = 0; j < 4; ++j) {
                const int col = fBase + wn * 32 + j * 8 + cc * 2;
                const int h = (col >> 6) & (HH - 1);
                const int d0 = col & (DD - 1);
                char* blk = g_kvb + ((size_t)((b * HH + h) * 16) + (n0 >> 7)) * KVBLK;
                const int rr = n0 & 127;
                uint32_t hp0, lp0, hp1, lp1;
                split_pair(acc[i][j][0], acc[i][j][1], hp0, lp0);
                split_pair(acc[i][j][2], acc[i][j][3], hp1, lp1);
                *(uint32_t*)(blk + rr * 144 + d0 * 2) = hp0;
                *(uint32_t*)(blk + 18432 + rr * 144 + d0 * 2) = lp0;
                *(uint32_t*)(blk + (rr + 8) * 144 + d0 * 2) = hp1;
                *(uint32_t*)(blk + 18432 + (rr + 8) * 144 + d0 * 2) = lp1;
            }
        }
    } else {
        const float qs = 0.125f * 1.44269504f;
        uint32_t* ph_ = (uint32_t*)g_qh;
        uint32_t* pl_ = (uint32_t*)g_ql;
#pragma unroll
        for (int i = 0; i < 4; ++i) {
            const int m0 = mBase + wm * 64 + i * 16 + g;
            const int b = m0 >> 11;
            const int n0 = m0 & (NN - 1);
#pragma unroll
            for (int j = 0; j < 4; ++j) {
                const int col = fBase + wn * 32 + j * 8 + cc * 2;
                const int h = (col >> 6) & (HH - 1);
                const int d0 = col & (DD - 1);
                const size_t rowbase = (size_t)(b * HH + h) * NN;
                uint32_t hp0, lp0, hp1, lp1;
                split_pair(acc[i][j][0] * qs, acc[i][j][1] * qs, hp0, lp0);
                split_pair(acc[i][j][2] * qs, acc[i][j][3] * qs, hp1, lp1);
                ph_[(rowbase + n0) * 32 + (d0 >> 1)] = hp0;
                pl_[(rowbase + n0) * 32 + (d0 >> 1)] = lp0;
                ph_[(rowbase + n0 + 8) * 32 + (d0 >> 1)] = hp1;
                pl_[(rowbase + n0 + 8) * 32 + (d0 >> 1)] = lp1;
            }
        }
    }
}

// ---------------------------------------------------------------------------
// Output projection GEMM (VERBATIM round 14, verified)
// ---------------------------------------------------------------------------
__global__ __launch_bounds__(256, 2) void out_gemm_hmma(float* __restrict__ Cout) {
    extern __shared__ __align__(16) uint32_t smg[];
    const int mBase = blockIdx.y * 128;
    const int fBase = blockIdx.x * 128;
    float acc[4][4][4];
    const char* aBlocks = g_ab + (size_t)blockIdx.y * 64 * XBLK;
    const char* bBase = g_wob + (size_t)(blockIdx.x >> 1) * 64 * WBLK
                      + (size_t)(blockIdx.x & 1) * 6144;
    hmma_mainloop256(smg, aBlocks, bBase, acc);

    const int tid = threadIdx.x;
    const int lane = tid & 31;
    const int wid = tid >> 5;
    const int wm = wid >> 2, wn = wid & 3;
    const int g = lane >> 2, cc = lane & 3;

#pragma unroll
    for (int i = 0; i < 4; ++i) {
        const int m0 = mBase + wm * 64 + i * 16 + g;
#pragma unroll
        for (int j = 0; j < 4; ++j) {
            const int col = fBase + wn * 32 + j * 8 + cc * 2;
            float* d1 = Cout + (size_t)m0 * EE + col;
            float* d2 = Cout + (size_t)(m0 + 8) * EE + col;
            *(float2*)d1 = make_float2(acc[i][j][0], acc[i][j][1]);
            *(float2*)d2 = make_float2(acc[i][j][2], acc[i][j][3]);
        }
    }
}

// ---------------------------------------------------------------------------
// Flash attention: 128 threads, q-tile 64, K double-buffered (bf16 split),
// V single-buffered fp16. PV = single fp16 mma pass.
// ---------------------------------------------------------------------------
#define KROW 36
#define VROW 68
#define KWORDS (128 * KROW)
#define VWORDS (64 * VROW)
#define KBYTES (KWORDS * 4)                 // 18432
#define VBYTES (VWORDS * 4)                 // 17408
#define KSTG_B (2 * KBYTES)                 // 36864
#define ATTN_SMEM (2 * KSTG_B + VBYTES + 64)  // 91200

__global__ __launch_bounds__(128) void attn_hmma() {
    extern __shared__ __align__(16) uint32_t smdyn[];

    const int bh = blockIdx.x;
    const int qt = blockIdx.y;
    const int tid = threadIdx.x;
    const int lane = tid & 31, wid = tid >> 5;
    const int g = lane >> 2, cc = lane & 3;

    const size_t qoff = (size_t)bh * NN * DD;
    const uint32_t* qhw = (const uint32_t*)g_qh + (qoff >> 1);
    const uint32_t* qlw = (const uint32_t*)g_ql + (qoff >> 1);
    const char* kvsrc = g_kvb + (size_t)bh * 16 * KVBLK;
    const uint32_t sb = smem_u32(smdyn);
    const uint32_t mb = sb + 2 * KSTG_B + VBYTES;

    const int r0 = qt * 64 + wid * 16 + g;
    uint32_t qa[4][4], qb[4][4];
#pragma unroll
    for (int kc = 0; kc < 4; ++kc) {
        const int w0 = r0 * 32 + kc * 8 + cc;
        qa[kc][0] = qhw[w0];       qa[kc][1] = qhw[w0 + 256];
        qa[kc][2] = qhw[w0 + 4];   qa[kc][3] = qhw[w0 + 260];
        qb[kc][0] = qlw[w0];       qb[kc][1] = qlw[w0 + 256];
        qb[kc][2] = qlw[w0 + 4];   qb[kc][3] = qlw[w0 + 260];
    }

    float o[8][4];
#pragma unroll
    for (int j = 0; j < 8; ++j) { o[j][0] = o[j][1] = o[j][2] = o[j][3] = 0.f; }
    float m0 = -30000.f, m1 = -30000.f, l0 = 0.f, l1 = 0.f;

    if (tid == 0) { mbar_init(mb, 1); mbar_init(mb + 8, 1); mbar_init(mb + 16, 1); }
    fence_proxy();
    __syncthreads();

    auto issue_k = [&](int kt) {
        const int s = kt & 1;
        const uint32_t m = mb + 8 * s;
        const uint32_t d = sb + (uint32_t)s * KSTG_B;
        const char* src = kvsrc + (size_t)kt * KVBLK;
        mbar_expect(m, KSTG_B);
        bulk_g2s(d, src, KBYTES, m);
        bulk_g2s(d + KBYTES, src + KBYTES, KBYTES, m);
    };
    auto issue_v = [&](int kt) {
        const uint32_t m = mb + 16;
        const uint32_t d = sb + 2 * KSTG_B;
        const char* src = kvsrc + (size_t)kt * KVBLK + 2 * KBYTES;
        mbar_expect(m, VBYTES);
        bulk_g2s(d, src, VBYTES, m);
    };

    if (tid == 0) { issue_k(0); issue_v(0); issue_k(1); }

    for (int ch = 0; ch < 16; ++ch) {
        const int s = ch & 1;
        mbar_wait(mb + 8 * s, (ch >> 1) & 1);

        const uint32_t* sKh = smdyn + (size_t)s * (KSTG_B / 4);
        const uint32_t* sKl = sKh + KWORDS;
        const uint32_t* sVh = smdyn + 2 * (KSTG_B / 4);

        float sc[16][4];
#pragma unroll
        for (int j = 0; j < 16; ++j) { sc[j][0] = sc[j][1] = sc[j][2] = sc[j][3] = 0.f; }
#pragma unroll
        for (int kc = 0; kc < 4; ++kc) {
            uint32_t kbh[16][2], kbl[16][2];
#pragma unroll
            for (int j = 0; j < 16; ++j) {
                const int bw = (j * 8 + g) * KROW + kc * 8 + cc;
                kbh[j][0] = sKh[bw]; kbh[j][1] = sKh[bw + 4];
                kbl[j][0] = sKl[bw]; kbl[j][1] = sKl[bw + 4];
            }
#pragma unroll
            for (int j = 0; j < 16; ++j) mma16816(sc[j], qa[kc], kbh[j]);
#pragma unroll
            for (int j = 0; j < 16; ++j) mma16816(sc[j], qa[kc], kbl[j]);
#pragma unroll
            for (int j = 0; j < 16; ++j) mma16816(sc[j], qb[kc], kbh[j]);
        }

        float cm0 = -30000.f, cm1 = -30000.f;
#pragma unroll
        for (int j = 0; j < 16; ++j) {
            cm0 = fmaxf(cm0, fmaxf(sc[j][0], sc[j][1]));
            cm1 = fmaxf(cm1, fmaxf(sc[j][2], sc[j][3]));
        }
        cm0 = fmaxf(cm0, __shfl_xor_sync(0xffffffffu, cm0, 1));
        cm0 = fmaxf(cm0, __shfl_xor_sync(0xffffffffu, cm0, 2));
        cm1 = fmaxf(cm1, __shfl_xor_sync(0xffffffffu, cm1, 1));
        cm1 = fmaxf(cm1, __shfl_xor_sync(0xffffffffu, cm1, 2));
        const float mn0 = fmaxf(m0, cm0), mn1 = fmaxf(m1, cm1);
        const float a0 = fast_exp2(m0 - mn0), a1 = fast_exp2(m1 - mn1);
        m0 = mn0; m1 = mn1;
#pragma unroll
        for (int j = 0; j < 8; ++j) {
            o[j][0] *= a0; o[j][1] *= a0; o[j][2] *= a1; o[j][3] *= a1;
        }

        mbar_wait(mb + 16, ch & 1);

        float rs0 = 0.f, rs1 = 0.f;
#pragma unroll
        for (int kc2 = 0; kc2 < 8; ++kc2) {
            uint32_t pah[4];
#pragma unroll
            for (int t = 0; t < 2; ++t) {
                const int j = kc2 * 2 + t;
                float p0 = fast_exp2(sc[j][0] - m0);
                float p1 = fast_exp2(sc[j][1] - m0);
                float p2 = fast_exp2(sc[j][2] - m1);
                float p3 = fast_exp2(sc[j][3] - m1);
                rs0 += p0 + p1; rs1 += p2 + p3;
                pah[2 * t] = pack_h2(p0, p1);
                pah[2 * t + 1] = pack_h2(p2, p3);
            }
            uint32_t vbh[8][2];
#pragma unroll
            for (int j = 0; j < 8; ++j) {
                const int bw = (j * 8 + g) * VROW + kc2 * 8 + cc;
                vbh[j][0] = sVh[bw]; vbh[j][1] = sVh[bw + 4];
            }
#pragma unroll
            for (int j = 0; j < 8; ++j) mma16816f(o[j], pah, vbh[j]);
        }
        rs0 += __shfl_xor_sync(0xffffffffu, rs0, 1);
        rs0 += __shfl_xor_sync(0xffffffffu, rs0, 2);
        rs1 += __shfl_xor_sync(0xffffffffu, rs1, 1);
        rs1 += __shfl_xor_sync(0xffffffffu, rs1, 2);
        l0 = l0 * a0 + rs0;
        l1 = l1 * a1 + rs1;

        __syncthreads();
        if (tid == 0) {
            if (ch + 1 < 16) issue_v(ch + 1);
            if (ch + 2 < 16) issue_k(ch + 2);
        }
    }

    // Epilogue: bf16 hi/lo attention output -> g_ab blocked
    const float i0 = 1.f / l0, i1 = 1.f / l1;
    const int b = bh >> 4, h = bh & (HH - 1);
    const int mg = b * NN + r0;
    const int mT = mg >> 7;
    const int rr = mg & 127;
#pragma unroll
    for (int j = 0; j < 8; ++j) {
        const int w = h * 32 + j * 4 + cc;
        uint32_t hp0, lp0, hp1, lp1;
        split_pair(o[j][0] * i0, o[j][1] * i0, hp0, lp0);
        split_pair(o[j][2] * i1, o[j][3] * i1, hp1, lp1);
        char* blk = g_ab + ((size_t)mT * 64 + (w >> 3)) * XBLK;
        const int off = (w & 7) * 4;
        *(uint32_t*)(blk + rr * 48 + off) = hp0;
        *(uint32_t*)(blk + 6144 + rr * 48 + off) = lp0;
        *(uint32_t*)(blk + (rr + 8) * 48 + off) = hp1;
        *(uint32_t*)(blk + 6144 + (rr + 8) * 48 + off) = lp1;
    }
}

// ---------------------------------------------------------------------------
extern "C" void kernel_launch(void* const* d_in, const int* in_sizes, int n_in,
                              void* d_out, int out_size)
{
    const float* x     = (const float*)d_in[0];
    const float* w_qkv = (const float*)d_in[1];
    const float* w_out = (const float*)d_in[2];
    float* out = (float*)d_out;

    cudaFuncSetAttribute(attn_hmma,
                         cudaFuncAttributeMaxDynamicSharedMemorySize, ATTN_SMEM);
    cudaFuncSetAttribute(qkv_gemm_hmma,
                         cudaFuncAttributeMaxDynamicSharedMemorySize, GEMM_SMEM);
    cudaFuncSetAttribute(out_gemm_hmma,
                         cudaFuncAttributeMaxDynamicSharedMemorySize, GEMM_SMEM);

    split_x_blocked<<<dim3(64, 64), 256>>>(x);
    split_wq_blocked<<<dim3(12, 64), 512>>>(w_qkv);
    split_wo_blocked<<<dim3(4, 64), 512>>>(w_out);

    {
        dim3 grid(FQKV / 128, MM / 128);   // (24, 64)
        qkv_gemm_hmma<<<grid, 256, GEMM_SMEM>>>();
    }
    {
        dim3 grid(BB * HH, NN / 64);       // (64, 32)
        attn_hmma<<<grid, 128, ATTN_SMEM>>>();
    }
    {
        dim3 grid(EE / 128, MM / 128);     // (8, 64)
        out_gemm_hmma<<<grid, 256, GEMM_SMEM>>>(out);
    }
}

// round 16
// speedup vs baseline: 5.7079x; 1.1045x over previous
#include <cuda_runtime.h>
#include <cuda_bf16.h>
#include <cuda_fp16.h>
#include <cstdint>

// Problem constants
#define BB 4
#define NN 2048
#define EE 1024
#define HH 16
#define DD 64
#define MM (BB * NN)        // 8192
#define FQKV (3 * EE)       // 3072
#define BHND (64 * 2048 * 64)

// Blocked-layout block sizes (bytes)
#define XBLK 12288          // A block: [hi 128x48][lo 128x48]
#define WBLK 24576          // W block: [hi 256x48][lo 256x48]
#define KVBLK 71680         // attn chunk: [Kf16 18432][unused 18432][Vf16 17408][pad]

// ---------------------------------------------------------------------------
// Scratch (__device__ globals; allocation-free rule)
// ---------------------------------------------------------------------------
__device__ __nv_bfloat16 g_qh[BHND], g_ql[BHND];      // fp16 hi / fp16 residual (bit storage)

__device__ __align__(16) char g_xb[64 * 64 * XBLK];    // X blocked  [mT][kc]
__device__ __align__(16) char g_ab[64 * 64 * XBLK];    // attn-out blocked [mT][kc]
__device__ __align__(16) char g_wqb[12 * 64 * WBLK];   // Wqkv blocked [fT256][kc]
__device__ __align__(16) char g_wob[4 * 64 * WBLK];    // Wout blocked [fT256][kc]
__device__ __align__(16) char g_kvb[64 * 16 * KVBLK];  // K/V blocked  [bh][chunk]

__device__ __forceinline__ float fast_exp2(float x) {
    float y;
    asm("ex2.approx.ftz.f32 %0, %1;" : "=f"(y) : "f"(x));
    return y;
}
__device__ __forceinline__ uint32_t pack_bf2(float lo, float hi) {
    __nv_bfloat162 t = __floats2bfloat162_rn(lo, hi);
    uint32_t r; r = *reinterpret_cast<uint32_t*>(&t); return r;
}
__device__ __forceinline__ uint32_t pack_h2(float lo, float hi) {
    __half2 t = __floats2half2_rn(lo, hi);
    uint32_t r; r = *reinterpret_cast<uint32_t*>(&t); return r;
}
__device__ __forceinline__ void split_pair(float a, float b, uint32_t& hw, uint32_t& lw) {
    hw = pack_bf2(a, b);
    float fa = __int_as_float(hw << 16);
    float fb = __int_as_float(hw & 0xFFFF0000u);
    lw = pack_bf2(a - fa, b - fb);
}
__device__ __forceinline__ void split_pair_h(float a, float b, uint32_t& hw, uint32_t& lw) {
    __half2 t = __floats2half2_rn(a, b);
    hw = *reinterpret_cast<uint32_t*>(&t);
    float fa = __half2float(__low2half(t));
    float fb = __half2float(__high2half(t));
    lw = pack_h2(a - fa, b - fb);
}
__device__ __forceinline__ uint32_t smem_u32(const void* p) {
    uint32_t a;
    asm("{ .reg .u64 t; cvta.to.shared.u64 t, %1; cvt.u32.u64 %0, t; }"
        : "=r"(a) : "l"(p));
    return a;
}
__device__ __forceinline__ void mbar_init(uint32_t a, uint32_t cnt) {
    asm volatile("mbarrier.init.shared.b64 [%0], %1;" :: "r"(a), "r"(cnt) : "memory");
}
__device__ __forceinline__ void mbar_expect(uint32_t a, uint32_t bytes) {
    asm volatile("mbarrier.arrive.expect_tx.shared.b64 _, [%0], %1;"
                 :: "r"(a), "r"(bytes) : "memory");
}
__device__ __forceinline__ void mbar_wait(uint32_t addr, uint32_t parity) {
    asm volatile(
        "{\n\t.reg .pred P1;\n\t"
        "WAIT_LOOP_%=:\n\t"
        "mbarrier.try_wait.parity.acquire.cta.shared::cta.b64 P1, [%0], %1, 0x989680;\n\t"
        "@P1 bra.uni WAIT_DONE_%=;\n\t"
        "bra.uni WAIT_LOOP_%=;\n\t"
        "WAIT_DONE_%=:\n\t}"
        :: "r"(addr), "r"(parity) : "memory");
}
__device__ __forceinline__ void bulk_g2s(uint32_t dst, const void* src,
                                         uint32_t bytes, uint32_t mbar) {
    asm volatile(
        "cp.async.bulk.shared::cluster.global.mbarrier::complete_tx::bytes "
        "[%0], [%1], %2, [%3];"
        :: "r"(dst), "l"(src), "r"(bytes), "r"(mbar) : "memory");
}
__device__ __forceinline__ void fence_proxy() {
    asm volatile("fence.proxy.async.shared::cta;" ::: "memory");
}
__device__ __forceinline__ void ldsm_x4(uint32_t* r, uint32_t addr) {
    asm volatile("ldmatrix.sync.aligned.m8n8.x4.shared.b16 {%0,%1,%2,%3}, [%4];"
        : "=r"(r[0]), "=r"(r[1]), "=r"(r[2]), "=r"(r[3]) : "r"(addr));
}
__device__ __forceinline__ void mma16816(float* c, const uint32_t* a, const uint32_t* b) {
    asm volatile(
        "mma.sync.aligned.m16n8k16.row.col.f32.bf16.bf16.f32 "
        "{%0,%1,%2,%3}, {%4,%5,%6,%7}, {%8,%9}, {%0,%1,%2,%3};"
        : "+f"(c[0]), "+f"(c[1]), "+f"(c[2]), "+f"(c[3])
        : "r"(a[0]), "r"(a[1]), "r"(a[2]), "r"(a[3]),
          "r"(b[0]), "r"(b[1]));
}
__device__ __forceinline__ void mma16816f(float* c, const uint32_t* a, const uint32_t* b) {
    asm volatile(
        "mma.sync.aligned.m16n8k16.row.col.f32.f16.f16.f32 "
        "{%0,%1,%2,%3}, {%4,%5,%6,%7}, {%8,%9}, {%0,%1,%2,%3};"
        : "+f"(c[0]), "+f"(c[1]), "+f"(c[2]), "+f"(c[3])
        : "r"(a[0]), "r"(a[1]), "r"(a[2]), "r"(a[3]),
          "r"(b[0]), "r"(b[1]));
}

// ---------------------------------------------------------------------------
// Split kernels -> blocked layouts (VERBATIM, verified)
// ---------------------------------------------------------------------------
__global__ __launch_bounds__(256) void split_x_blocked(const float* __restrict__ x) {
    const int mT = blockIdx.x, kc = blockIdx.y;
    const int t = threadIdx.x;
    const int r = t >> 1, hf = t & 1;
    const float* src = x + ((size_t)(mT * 128 + r)) * EE + kc * 16 + hf * 8;
    float4 v0 = *(const float4*)src;
    float4 v1 = *(const float4*)(src + 4);
    uint32_t h0, h1, h2, h3, l0, l1, l2, l3;
    split_pair(v0.x, v0.y, h0, l0);
    split_pair(v0.z, v0.w, h1, l1);
    split_pair(v1.x, v1.y, h2, l2);
    split_pair(v1.z, v1.w, h3, l3);
    char* blk = g_xb + ((size_t)mT * 64 + kc) * XBLK + r * 48 + hf * 16;
    *(uint4*)blk = make_uint4(h0, h1, h2, h3);
    *(uint4*)(blk + 6144) = make_uint4(l0, l1, l2, l3);
}
__global__ __launch_bounds__(512) void split_wq_blocked(const float* __restrict__ w) {
    const int fT = blockIdx.x, kc = blockIdx.y;
    const int t = threadIdx.x;
    const int r = t >> 1, hf = t & 1;
    const float* src = w + ((size_t)(fT * 256 + r)) * EE + kc * 16 + hf * 8;
    float4 v0 = *(const float4*)src;
    float4 v1 = *(const float4*)(src + 4);
    uint32_t h0, h1, h2, h3, l0, l1, l2, l3;
    split_pair(v0.x, v0.y, h0, l0);
    split_pair(v0.z, v0.w, h1, l1);
    split_pair(v1.x, v1.y, h2, l2);
    split_pair(v1.z, v1.w, h3, l3);
    char* blk = g_wqb + ((size_t)fT * 64 + kc) * WBLK + r * 48 + hf * 16;
    *(uint4*)blk = make_uint4(h0, h1, h2, h3);
    *(uint4*)(blk + 12288) = make_uint4(l0, l1, l2, l3);
}
__global__ __launch_bounds__(512) void split_wo_blocked(const float* __restrict__ w) {
    const int fT = blockIdx.x, kc = blockIdx.y;
    const int t = threadIdx.x;
    const int r = t >> 1, hf = t & 1;
    const float* src = w + ((size_t)(fT * 256 + r)) * EE + kc * 16 + hf * 8;
    float4 v0 = *(const float4*)src;
    float4 v1 = *(const float4*)(src + 4);
    uint32_t h0, h1, h2, h3, l0, l1, l2, l3;
    split_pair(v0.x, v0.y, h0, l0);
    split_pair(v0.z, v0.w, h1, l1);
    split_pair(v1.x, v1.y, h2, l2);
    split_pair(v1.z, v1.w, h3, l3);
    char* blk = g_wob + ((size_t)fT * 64 + kc) * WBLK + r * 48 + hf * 16;
    *(uint4*)blk = make_uint4(h0, h1, h2, h3);
    *(uint4*)(blk + 12288) = make_uint4(l0, l1, l2, l3);
}

// ---------------------------------------------------------------------------
// 3-split HMMA GEMM (VERBATIM round 14/15, verified)
// ---------------------------------------------------------------------------
#define GSTG 24576
#define GSTAGES 4
#define GEMM_SMEM (GSTAGES * GSTG + 64)      // 98368

__device__ __forceinline__ void hmma_mainloop256(
    uint32_t* sm, const char* aBlocks, const char* bBase, float (&acc)[4][4][4])
{
    const int tid = threadIdx.x;
    const int lane = tid & 31;
    const int wid = tid >> 5;
    const int wm = wid >> 2;
    const int wn = wid & 3;
    const uint32_t sb = smem_u32(sm);
    const uint32_t mb = sb + GSTAGES * GSTG;

#pragma unroll
    for (int i = 0; i < 4; ++i)
#pragma unroll
        for (int j = 0; j < 4; ++j)
#pragma unroll
            for (int r = 0; r < 4; ++r) acc[i][j][r] = 0.f;

    const uint32_t aoffb = (uint32_t)((lane & 15) * 48 + (lane >> 4) * 16);
    const uint32_t boffb = (uint32_t)(((lane & 7) + (lane >> 4) * 8) * 48 + ((lane >> 3) & 1) * 16);

    if (tid == 0) {
#pragma unroll
        for (int s = 0; s < GSTAGES; ++s) mbar_init(mb + 8 * s, 1);
    }
    fence_proxy();
    __syncthreads();

    auto issue = [&](int ch) {
        const int s = ch & 3;
        const uint32_t m = mb + 8 * s;
        const uint32_t d = sb + (uint32_t)s * GSTG;
        mbar_expect(m, GSTG);
        bulk_g2s(d, aBlocks + (size_t)ch * XBLK, XBLK, m);
        bulk_g2s(d + XBLK, bBase + (size_t)ch * WBLK, 6144, m);
        bulk_g2s(d + XBLK + 6144, bBase + (size_t)ch * WBLK + 12288, 6144, m);
    };

    if (tid == 0) { issue(0); issue(1); issue(2); }

    for (int ch = 0; ch < 64; ++ch) {
        const int s = ch & 3;
        __syncthreads();
        if (tid == 0 && ch + 3 < 64) issue(ch + 3);
        mbar_wait(mb + 8 * s, (ch >> 2) & 1);

        const uint32_t stb = sb + (uint32_t)s * GSTG;
        const uint32_t aHb = stb;
        const uint32_t aLb = stb + 6144;
        const uint32_t bHb = stb + 12288;
        const uint32_t bLb = stb + 18432;

        uint32_t bh[4][2], bl[4][2];
#pragma unroll
        for (int jp = 0; jp < 2; ++jp) {
            const uint32_t ar = (uint32_t)((wn * 32 + jp * 16) * 48) + boffb;
            uint32_t r4[4];
            ldsm_x4(r4, bHb + ar);
            bh[jp * 2][0] = r4[0]; bh[jp * 2][1] = r4[1];
            bh[jp * 2 + 1][0] = r4[2]; bh[jp * 2 + 1][1] = r4[3];
            ldsm_x4(r4, bLb + ar);
            bl[jp * 2][0] = r4[0]; bl[jp * 2][1] = r4[1];
            bl[jp * 2 + 1][0] = r4[2]; bl[jp * 2 + 1][1] = r4[3];
        }
#pragma unroll
        for (int i = 0; i < 4; ++i) {
            const uint32_t ao = (uint32_t)((wm * 64 + i * 16) * 48) + aoffb;
            uint32_t ah4[4], al4[4];
            ldsm_x4(ah4, aHb + ao);
            ldsm_x4(al4, aLb + ao);
#pragma unroll
            for (int j = 0; j < 4; ++j) mma16816(acc[i][j], ah4, bh[j]);
#pragma unroll
            for (int j = 0; j < 4; ++j) mma16816(acc[i][j], ah4, bl[j]);
#pragma unroll
            for (int j = 0; j < 4; ++j) mma16816(acc[i][j], al4, bh[j]);
        }
    }
}

// ---------------------------------------------------------------------------
// QKV GEMM: epilogue writes Q (fp16 hi + fp16 residual, linear),
// K (fp16 blocked, hi slot only), V (fp16 blocked).
// ---------------------------------------------------------------------------
__global__ __launch_bounds__(256, 2) void qkv_gemm_hmma() {
    extern __shared__ __align__(16) uint32_t smg[];
    const int mBase = blockIdx.y * 128;
    const int fBase = blockIdx.x * 128;
    float acc[4][4][4];
    const char* aBlocks = g_xb + (size_t)blockIdx.y * 64 * XBLK;
    const char* bBase = g_wqb + (size_t)(blockIdx.x >> 1) * 64 * WBLK
                      + (size_t)(blockIdx.x & 1) * 6144;
    hmma_mainloop256(smg, aBlocks, bBase, acc);

    const int tid = threadIdx.x;
    const int lane = tid & 31;
    const int wid = tid >> 5;
    const int wm = wid >> 2, wn = wid & 3;
    const int g = lane >> 2, cc = lane & 3;
    const int which = fBase >> 10;

    if (which == 2) {
        // V -> fp16 in g_kvb
#pragma unroll
        for (int i = 0; i < 4; ++i) {
            const int m0 = mBase + wm * 64 + i * 16 + g;
            const int b = m0 >> 11;
            const int n0 = m0 & (NN - 1);
#pragma unroll
            for (int j = 0; j < 4; ++j) {
                const int col = fBase + wn * 32 + j * 8 + cc * 2;
                const int h = (col >> 6) & (HH - 1);
                const int d0 = col & (DD - 1);
                char* blk = g_kvb + ((size_t)((b * HH + h) * 16) + (n0 >> 7)) * KVBLK + 36864;
#pragma unroll
                for (int r = 0; r < 4; ++r) {
                    const int dd = d0 + (r & 1);
                    const int nn = (n0 & 127) + (r >> 1) * 8;
                    *(__half*)(blk + dd * 272 + nn * 2) = __float2half_rn(acc[i][j][r]);
                }
            }
        }
    } else if (which == 1) {
        // K -> fp16 blocked (hi slot only)
#pragma unroll
        for (int i = 0; i < 4; ++i) {
            const int m0 = mBase + wm * 64 + i * 16 + g;
            const int b = m0 >> 11;
            const int n0 = m0 & (NN - 1);
#pragma unroll
            for (int j = 0; j < 4; ++j) {
                const int col = fBase + wn * 32 + j * 8 + cc * 2;
                const int h = (col >> 6) & (HH - 1);
                const int d0 = col & (DD - 1);
                char* blk = g_kvb + ((size_t)((b * HH + h) * 16) + (n0 >> 7)) * KVBLK;
                const int rr = n0 & 127;
                *(uint32_t*)(blk + rr * 144 + d0 * 2) = pack_h2(acc[i][j][0], acc[i][j][1]);
                *(uint32_t*)(blk + (rr + 8) * 144 + d0 * 2) = pack_h2(acc[i][j][2], acc[i][j][3]);
            }
        }
    } else {
        // Q -> fp16 hi + fp16 residual, prescaled
        const float qs = 0.125f * 1.44269504f;
        uint32_t* ph_ = (uint32_t*)g_qh;
        uint32_t* pl_ = (uint32_t*)g_ql;
#pragma unroll
        for (int i = 0; i < 4; ++i) {
            const int m0 = mBase + wm * 64 + i * 16 + g;
            const int b = m0 >> 11;
            const int n0 = m0 & (NN - 1);
#pragma unroll
            for (int j = 0; j < 4; ++j) {
                const int col = fBase + wn * 32 + j * 8 + cc * 2;
                const int h = (col >> 6) & (HH - 1);
                const int d0 = col & (DD - 1);
                const size_t rowbase = (size_t)(b * HH + h) * NN;
                uint32_t hp0, lp0, hp1, lp1;
                split_pair_h(acc[i][j][0] * qs, acc[i][j][1] * qs, hp0, lp0);
                split_pair_h(acc[i][j][2] * qs, acc[i][j][3] * qs, hp1, lp1);
                ph_[(rowbase + n0) * 32 + (d0 >> 1)] = hp0;
                pl_[(rowbase + n0) * 32 + (d0 >> 1)] = lp0;
                ph_[(rowbase + n0 + 8) * 32 + (d0 >> 1)] = hp1;
                pl_[(rowbase + n0 + 8) * 32 + (d0 >> 1)] = lp1;
            }
        }
    }
}

// ---------------------------------------------------------------------------
// Output projection GEMM (VERBATIM round 14/15, verified)
// ---------------------------------------------------------------------------
__global__ __launch_bounds__(256, 2) void out_gemm_hmma(float* __restrict__ Cout) {
    extern __shared__ __align__(16) uint32_t smg[];
    const int mBase = blockIdx.y * 128;
    const int fBase = blockIdx.x * 128;
    float acc[4][4][4];
    const char* aBlocks = g_ab + (size_t)blockIdx.y * 64 * XBLK;
    const char* bBase = g_wob + (size_t)(blockIdx.x >> 1) * 64 * WBLK
                      + (size_t)(blockIdx.x & 1) * 6144;
    hmma_mainloop256(smg, aBlocks, bBase, acc);

    const int tid = threadIdx.x;
    const int lane = tid & 31;
    const int wid = tid >> 5;
    const int wm = wid >> 2, wn = wid & 3;
    const int g = lane >> 2, cc = lane & 3;

#pragma unroll
    for (int i = 0; i < 4; ++i) {
        const int m0 = mBase + wm * 64 + i * 16 + g;
#pragma unroll
        for (int j = 0; j < 4; ++j) {
            const int col = fBase + wn * 32 + j * 8 + cc * 2;
            float* d1 = Cout + (size_t)m0 * EE + col;
            float* d2 = Cout + (size_t)(m0 + 8) * EE + col;
            *(float2*)d1 = make_float2(acc[i][j][0], acc[i][j][1]);
            *(float2*)d2 = make_float2(acc[i][j][2], acc[i][j][3]);
        }
    }
}

// ---------------------------------------------------------------------------
// Flash attention: 128 threads, q-tile 64. K fp16 single (double-buffered),
// V fp16 single-buffered. QK^T = 2 fp16 passes (Qhi, Qlo-residual);
// PV = 1 fp16 pass.
// ---------------------------------------------------------------------------
#define KROW 36
#define VROW 68
#define KWORDS (128 * KROW)
#define VWORDS (64 * VROW)
#define KBYTES (KWORDS * 4)                 // 18432
#define VBYTES (VWORDS * 4)                 // 17408
#define ATTN_SMEM (2 * KBYTES + VBYTES + 64)  // 54336

__global__ __launch_bounds__(128) void attn_hmma() {
    extern __shared__ __align__(16) uint32_t smdyn[];

    const int bh = blockIdx.x;
    const int qt = blockIdx.y;
    const int tid = threadIdx.x;
    const int lane = tid & 31, wid = tid >> 5;
    const int g = lane >> 2, cc = lane & 3;

    const size_t qoff = (size_t)bh * NN * DD;
    const uint32_t* qhw = (const uint32_t*)g_qh + (qoff >> 1);
    const uint32_t* qlw = (const uint32_t*)g_ql + (qoff >> 1);
    const char* kvsrc = g_kvb + (size_t)bh * 16 * KVBLK;
    const uint32_t sb = smem_u32(smdyn);
    const uint32_t mb = sb + 2 * KBYTES + VBYTES;

    const int r0 = qt * 64 + wid * 16 + g;
    uint32_t qa[4][4], qb[4][4];
#pragma unroll
    for (int kc = 0; kc < 4; ++kc) {
        const int w0 = r0 * 32 + kc * 8 + cc;
        qa[kc][0] = qhw[w0];       qa[kc][1] = qhw[w0 + 256];
        qa[kc][2] = qhw[w0 + 4];   qa[kc][3] = qhw[w0 + 260];
        qb[kc][0] = qlw[w0];       qb[kc][1] = qlw[w0 + 256];
        qb[kc][2] = qlw[w0 + 4];   qb[kc][3] = qlw[w0 + 260];
    }

    float o[8][4];
#pragma unroll
    for (int j = 0; j < 8; ++j) { o[j][0] = o[j][1] = o[j][2] = o[j][3] = 0.f; }
    float m0 = -30000.f, m1 = -30000.f, l0 = 0.f, l1 = 0.f;

    if (tid == 0) { mbar_init(mb, 1); mbar_init(mb + 8, 1); mbar_init(mb + 16, 1); }
    fence_proxy();
    __syncthreads();

    auto issue_k = [&](int kt) {
        const int s = kt & 1;
        const uint32_t m = mb + 8 * s;
        const uint32_t d = sb + (uint32_t)s * KBYTES;
        const char* src = kvsrc + (size_t)kt * KVBLK;
        mbar_expect(m, KBYTES);
        bulk_g2s(d, src, KBYTES, m);
    };
    auto issue_v = [&](int kt) {
        const uint32_t m = mb + 16;
        const uint32_t d = sb + 2 * KBYTES;
        const char* src = kvsrc + (size_t)kt * KVBLK + 2 * KBYTES;
        mbar_expect(m, VBYTES);
        bulk_g2s(d, src, VBYTES, m);
    };

    if (tid == 0) { issue_k(0); issue_v(0); issue_k(1); }

    for (int ch = 0; ch < 16; ++ch) {
        const int s = ch & 1;
        mbar_wait(mb + 8 * s, (ch >> 1) & 1);

        const uint32_t* sK = smdyn + (size_t)s * (KBYTES / 4);
        const uint32_t* sVh = smdyn + 2 * (KBYTES / 4);

        float sc[16][4];
#pragma unroll
        for (int j = 0; j < 16; ++j) { sc[j][0] = sc[j][1] = sc[j][2] = sc[j][3] = 0.f; }
#pragma unroll
        for (int kc = 0; kc < 4; ++kc) {
            uint32_t kb[16][2];
#pragma unroll
            for (int j = 0; j < 16; ++j) {
                const int bw = (j * 8 + g) * KROW + kc * 8 + cc;
                kb[j][0] = sK[bw]; kb[j][1] = sK[bw + 4];
            }
#pragma unroll
            for (int j = 0; j < 16; ++j) mma16816f(sc[j], qa[kc], kb[j]);
#pragma unroll
            for (int j = 0; j < 16; ++j) mma16816f(sc[j], qb[kc], kb[j]);
        }

        float cm0 = -30000.f, cm1 = -30000.f;
#pragma unroll
        for (int j = 0; j < 16; ++j) {
            cm0 = fmaxf(cm0, fmaxf(sc[j][0], sc[j][1]));
            cm1 = fmaxf(cm1, fmaxf(sc[j][2], sc[j][3]));
        }
        cm0 = fmaxf(cm0, __shfl_xor_sync(0xffffffffu, cm0, 1));
        cm0 = fmaxf(cm0, __shfl_xor_sync(0xffffffffu, cm0, 2));
        cm1 = fmaxf(cm1, __shfl_xor_sync(0xffffffffu, cm1, 1));
        cm1 = fmaxf(cm1, __shfl_xor_sync(0xffffffffu, cm1, 2));
        const float mn0 = fmaxf(m0, cm0), mn1 = fmaxf(m1, cm1);
        const float a0 = fast_exp2(m0 - mn0), a1 = fast_exp2(m1 - mn1);
        m0 = mn0; m1 = mn1;
#pragma unroll
        for (int j = 0; j < 8; ++j) {
            o[j][0] *= a0; o[j][1] *= a0; o[j][2] *= a1; o[j][3] *= a1;
        }

        mbar_wait(mb + 16, ch & 1);

        float rs0 = 0.f, rs1 = 0.f;
#pragma unroll
        for (int kc2 = 0; kc2 < 8; ++kc2) {
            uint32_t pah[4];
#pragma unroll
            for (int t = 0; t < 2; ++t) {
                const int j = kc2 * 2 + t;
                float p0 = fast_exp2(sc[j][0] - m0);
                float p1 = fast_exp2(sc[j][1] - m0);
                float p2 = fast_exp2(sc[j][2] - m1);
                float p3 = fast_exp2(sc[j][3] - m1);
                rs0 += p0 + p1; rs1 += p2 + p3;
                pah[2 * t] = pack_h2(p0, p1);
                pah[2 * t + 1] = pack_h2(p2, p3);
            }
            uint32_t vbh[8][2];
#pragma unroll
            for (int j = 0; j < 8; ++j) {
                const int bw = (j * 8 + g) * VROW + kc2 * 8 + cc;
                vbh[j][0] = sVh[bw]; vbh[j][1] = sVh[bw + 4];
            }
#pragma unroll
            for (int j = 0; j < 8; ++j) mma16816f(o[j], pah, vbh[j]);
        }
        rs0 += __shfl_xor_sync(0xffffffffu, rs0, 1);
        rs0 += __shfl_xor_sync(0xffffffffu, rs0, 2);
        rs1 += __shfl_xor_sync(0xffffffffu, rs1, 1);
        rs1 += __shfl_xor_sync(0xffffffffu, rs1, 2);
        l0 = l0 * a0 + rs0;
        l1 = l1 * a1 + rs1;

        __syncthreads();
        if (tid == 0) {
            if (ch + 1 < 16) issue_v(ch + 1);
            if (ch + 2 < 16) issue_k(ch + 2);
        }
    }

    // Epilogue: bf16 hi/lo attention output -> g_ab blocked
    const float i0 = 1.f / l0, i1 = 1.f / l1;
    const int b = bh >> 4, h = bh & (HH - 1);
    const int mg = b * NN + r0;
    const int mT = mg >> 7;
    const int rr = mg & 127;
#pragma unroll
    for (int j = 0; j < 8; ++j) {
        const int w = h * 32 + j * 4 + cc;
        uint32_t hp0, lp0, hp1, lp1;
        split_pair(o[j][0] * i0, o[j][1] * i0, hp0, lp0);
        split_pair(o[j][2] * i1, o[j][3] * i1, hp1, lp1);
        char* blk = g_ab + ((size_t)mT * 64 + (w >> 3)) * XBLK;
        const int off = (w & 7) * 4;
        *(uint32_t*)(blk + rr * 48 + off) = hp0;
        *(uint32_t*)(blk + 6144 + rr * 48 + off) = lp0;
        *(uint32_t*)(blk + (rr + 8) * 48 + off) = hp1;
        *(uint32_t*)(blk + 6144 + (rr + 8) * 48 + off) = lp1;
    }
}

// ---------------------------------------------------------------------------
extern "C" void kernel_launch(void* const* d_in, const int* in_sizes, int n_in,
                              void* d_out, int out_size)
{
    const float* x     = (const float*)d_in[0];
    const float* w_qkv = (const float*)d_in[1];
    const float* w_out = (const float*)d_in[2];
    float* out = (float*)d_out;

    cudaFuncSetAttribute(attn_hmma,
                         cudaFuncAttributeMaxDynamicSharedMemorySize, ATTN_SMEM);
    cudaFuncSetAttribute(qkv_gemm_hmma,
                         cudaFuncAttributeMaxDynamicSharedMemorySize, GEMM_SMEM);
    cudaFuncSetAttribute(out_gemm_hmma,
                         cudaFuncAttributeMaxDynamicSharedMemorySize, GEMM_SMEM);

    split_x_blocked<<<dim3(64, 64), 256>>>(x);
    split_wq_blocked<<<dim3(12, 64), 512>>>(w_qkv);
    split_wo_blocked<<<dim3(4, 64), 512>>>(w_out);

    {
        dim3 grid(FQKV / 128, MM / 128);   // (24, 64)
        qkv_gemm_hmma<<<grid, 256, GEMM_SMEM>>>();
    }
    {
        dim3 grid(BB * HH, NN / 64);       // (64, 32)
        attn_hmma<<<grid, 128, ATTN_SMEM>>>();
    }
    {
        dim3 grid(EE / 128, MM / 128);     // (8, 64)
        out_gemm_hmma<<<grid, 256, GEMM_SMEM>>>(out);
    }
}

// round 17
// speedup vs baseline: 6.8407x; 1.1985x over previous
#include <cuda_runtime.h>
#include <cuda_bf16.h>
#include <cuda_fp16.h>
#include <cstdint>

// Problem constants
#define BB 4
#define NN 2048
#define EE 1024
#define HH 16
#define DD 64
#define MM (BB * NN)        // 8192
#define FQKV (3 * EE)       // 3072
#define BHND (64 * 2048 * 64)

// Blocked-layout block sizes (bytes)
#define XBLK 12288          // A block: [hi 128x48][lo 128x48]  (fp16 hi + fp16 residual)
#define WBLK 12288          // W block: [fp16 256x48]
#define KVBLK 71680         // attn chunk: [Kf16 18432][unused 18432][Vf16 17408][pad]

// ---------------------------------------------------------------------------
// Scratch (__device__ globals; allocation-free rule)
// ---------------------------------------------------------------------------
__device__ __nv_bfloat16 g_qh[BHND], g_ql[BHND];      // fp16 hi / fp16 residual (bit storage)

__device__ __align__(16) char g_xb[64 * 64 * XBLK];    // X blocked  [mT][kc] fp16 hi/lo
__device__ __align__(16) char g_ab[64 * 64 * XBLK];    // attn-out blocked fp16 hi/lo
__device__ __align__(16) char g_wqb[12 * 64 * WBLK];   // Wqkv blocked [fT256][kc] fp16
__device__ __align__(16) char g_wob[4 * 64 * WBLK];    // Wout blocked fp16
__device__ __align__(16) char g_kvb[64 * 16 * KVBLK];  // K/V blocked  [bh][chunk]

__device__ __forceinline__ float fast_exp2(float x) {
    float y;
    asm("ex2.approx.ftz.f32 %0, %1;" : "=f"(y) : "f"(x));
    return y;
}
__device__ __forceinline__ uint32_t pack_h2(float lo, float hi) {
    __half2 t = __floats2half2_rn(lo, hi);
    uint32_t r; r = *reinterpret_cast<uint32_t*>(&t); return r;
}
__device__ __forceinline__ void split_pair_h(float a, float b, uint32_t& hw, uint32_t& lw) {
    __half2 t = __floats2half2_rn(a, b);
    hw = *reinterpret_cast<uint32_t*>(&t);
    float fa = __half2float(__low2half(t));
    float fb = __half2float(__high2half(t));
    lw = pack_h2(a - fa, b - fb);
}
__device__ __forceinline__ uint32_t smem_u32(const void* p) {
    uint32_t a;
    asm("{ .reg .u64 t; cvta.to.shared.u64 t, %1; cvt.u32.u64 %0, t; }"
        : "=r"(a) : "l"(p));
    return a;
}
__device__ __forceinline__ void mbar_init(uint32_t a, uint32_t cnt) {
    asm volatile("mbarrier.init.shared.b64 [%0], %1;" :: "r"(a), "r"(cnt) : "memory");
}
__device__ __forceinline__ void mbar_expect(uint32_t a, uint32_t bytes) {
    asm volatile("mbarrier.arrive.expect_tx.shared.b64 _, [%0], %1;"
                 :: "r"(a), "r"(bytes) : "memory");
}
__device__ __forceinline__ void mbar_wait(uint32_t addr, uint32_t parity) {
    asm volatile(
        "{\n\t.reg .pred P1;\n\t"
        "WAIT_LOOP_%=:\n\t"
        "mbarrier.try_wait.parity.acquire.cta.shared::cta.b64 P1, [%0], %1, 0x989680;\n\t"
        "@P1 bra.uni WAIT_DONE_%=;\n\t"
        "bra.uni WAIT_LOOP_%=;\n\t"
        "WAIT_DONE_%=:\n\t}"
        :: "r"(addr), "r"(parity) : "memory");
}
__device__ __forceinline__ void bulk_g2s(uint32_t dst, const void* src,
                                         uint32_t bytes, uint32_t mbar) {
    asm volatile(
        "cp.async.bulk.shared::cluster.global.mbarrier::complete_tx::bytes "
        "[%0], [%1], %2, [%3];"
        :: "r"(dst), "l"(src), "r"(bytes), "r"(mbar) : "memory");
}
__device__ __forceinline__ void fence_proxy() {
    asm volatile("fence.proxy.async.shared::cta;" ::: "memory");
}
__device__ __forceinline__ void ldsm_x4(uint32_t* r, uint32_t addr) {
    asm volatile("ldmatrix.sync.aligned.m8n8.x4.shared.b16 {%0,%1,%2,%3}, [%4];"
        : "=r"(r[0]), "=r"(r[1]), "=r"(r[2]), "=r"(r[3]) : "r"(addr));
}
__device__ __forceinline__ void mma16816f(float* c, const uint32_t* a, const uint32_t* b) {
    asm volatile(
        "mma.sync.aligned.m16n8k16.row.col.f32.f16.f16.f32 "
        "{%0,%1,%2,%3}, {%4,%5,%6,%7}, {%8,%9}, {%0,%1,%2,%3};"
        : "+f"(c[0]), "+f"(c[1]), "+f"(c[2]), "+f"(c[3])
        : "r"(a[0]), "r"(a[1]), "r"(a[2]), "r"(a[3]),
          "r"(b[0]), "r"(b[1]));
}

// ---------------------------------------------------------------------------
// Split kernels -> blocked layouts
// ---------------------------------------------------------------------------
__global__ __launch_bounds__(256) void split_x_blocked(const float* __restrict__ x) {
    const int mT = blockIdx.x, kc = blockIdx.y;
    const int t = threadIdx.x;
    const int r = t >> 1, hf = t & 1;
    const float* src = x + ((size_t)(mT * 128 + r)) * EE + kc * 16 + hf * 8;
    float4 v0 = *(const float4*)src;
    float4 v1 = *(const float4*)(src + 4);
    uint32_t h0, h1, h2, h3, l0, l1, l2, l3;
    split_pair_h(v0.x, v0.y, h0, l0);
    split_pair_h(v0.z, v0.w, h1, l1);
    split_pair_h(v1.x, v1.y, h2, l2);
    split_pair_h(v1.z, v1.w, h3, l3);
    char* blk = g_xb + ((size_t)mT * 64 + kc) * XBLK + r * 48 + hf * 16;
    *(uint4*)blk = make_uint4(h0, h1, h2, h3);
    *(uint4*)(blk + 6144) = make_uint4(l0, l1, l2, l3);
}
__global__ __launch_bounds__(512) void split_wq_blocked(const float* __restrict__ w) {
    const int fT = blockIdx.x, kc = blockIdx.y;
    const int t = threadIdx.x;
    const int r = t >> 1, hf = t & 1;
    const float* src = w + ((size_t)(fT * 256 + r)) * EE + kc * 16 + hf * 8;
    float4 v0 = *(const float4*)src;
    float4 v1 = *(const float4*)(src + 4);
    uint32_t a = pack_h2(v0.x, v0.y), b = pack_h2(v0.z, v0.w);
    uint32_t c = pack_h2(v1.x, v1.y), d = pack_h2(v1.z, v1.w);
    char* blk = g_wqb + ((size_t)fT * 64 + kc) * WBLK + r * 48 + hf * 16;
    *(uint4*)blk = make_uint4(a, b, c, d);
}
__global__ __launch_bounds__(512) void split_wo_blocked(const float* __restrict__ w) {
    const int fT = blockIdx.x, kc = blockIdx.y;
    const int t = threadIdx.x;
    const int r = t >> 1, hf = t & 1;
    const float* src = w + ((size_t)(fT * 256 + r)) * EE + kc * 16 + hf * 8;
    float4 v0 = *(const float4*)src;
    float4 v1 = *(const float4*)(src + 4);
    uint32_t a = pack_h2(v0.x, v0.y), b = pack_h2(v0.z, v0.w);
    uint32_t c = pack_h2(v1.x, v1.y), d = pack_h2(v1.z, v1.w);
    char* blk = g_wob + ((size_t)fT * 64 + kc) * WBLK + r * 48 + hf * 16;
    *(uint4*)blk = make_uint4(a, b, c, d);
}

// ---------------------------------------------------------------------------
// 2-pass fp16 HMMA GEMM: CTA 128x128, 8 warps (2x4), warp tile 64x32,
// 4 stages x 1 K-chunk (verified pipeline), 2 CTAs/SM.
// Stage = [Ah 6KB][Al 6KB][W 6KB] = 18KB.
// ---------------------------------------------------------------------------
#define GSTG 18432
#define GSTAGES 4
#define GEMM_SMEM (GSTAGES * GSTG + 64)      // 73792

__device__ __forceinline__ void hmma_mainloop256(
    uint32_t* sm, const char* aBlocks, const char* bBase, float (&acc)[4][4][4])
{
    const int tid = threadIdx.x;
    const int lane = tid & 31;
    const int wid = tid >> 5;
    const int wm = wid >> 2;
    const int wn = wid & 3;
    const uint32_t sb = smem_u32(sm);
    const uint32_t mb = sb + GSTAGES * GSTG;

#pragma unroll
    for (int i = 0; i < 4; ++i)
#pragma unroll
        for (int j = 0; j < 4; ++j)
#pragma unroll
            for (int r = 0; r < 4; ++r) acc[i][j][r] = 0.f;

    const uint32_t aoffb = (uint32_t)((lane & 15) * 48 + (lane >> 4) * 16);
    const uint32_t boffb = (uint32_t)(((lane & 7) + (lane >> 4) * 8) * 48 + ((lane >> 3) & 1) * 16);

    if (tid == 0) {
#pragma unroll
        for (int s = 0; s < GSTAGES; ++s) mbar_init(mb + 8 * s, 1);
    }
    fence_proxy();
    __syncthreads();

    auto issue = [&](int ch) {
        const int s = ch & 3;
        const uint32_t m = mb + 8 * s;
        const uint32_t d = sb + (uint32_t)s * GSTG;
        mbar_expect(m, GSTG);
        bulk_g2s(d, aBlocks + (size_t)ch * XBLK, XBLK, m);          // Ah+Al 12KB
        bulk_g2s(d + XBLK, bBase + (size_t)ch * WBLK, 6144, m);     // W half-tile 6KB
    };

    if (tid == 0) { issue(0); issue(1); issue(2); }

    for (int ch = 0; ch < 64; ++ch) {
        const int s = ch & 3;
        __syncthreads();
        if (tid == 0 && ch + 3 < 64) issue(ch + 3);
        mbar_wait(mb + 8 * s, (ch >> 2) & 1);

        const uint32_t stb = sb + (uint32_t)s * GSTG;
        const uint32_t aHb = stb;
        const uint32_t aLb = stb + 6144;
        const uint32_t bWb = stb + 12288;

        uint32_t bw_[4][2];
#pragma unroll
        for (int jp = 0; jp < 2; ++jp) {
            const uint32_t ar = (uint32_t)((wn * 32 + jp * 16) * 48) + boffb;
            uint32_t r4[4];
            ldsm_x4(r4, bWb + ar);
            bw_[jp * 2][0] = r4[0]; bw_[jp * 2][1] = r4[1];
            bw_[jp * 2 + 1][0] = r4[2]; bw_[jp * 2 + 1][1] = r4[3];
        }
#pragma unroll
        for (int i = 0; i < 4; ++i) {
            const uint32_t ao = (uint32_t)((wm * 64 + i * 16) * 48) + aoffb;
            uint32_t ah4[4], al4[4];
            ldsm_x4(ah4, aHb + ao);
            ldsm_x4(al4, aLb + ao);
#pragma unroll
            for (int j = 0; j < 4; ++j) mma16816f(acc[i][j], ah4, bw_[j]);
#pragma unroll
            for (int j = 0; j < 4; ++j) mma16816f(acc[i][j], al4, bw_[j]);
        }
    }
}

// ---------------------------------------------------------------------------
// QKV GEMM: epilogue writes Q (fp16 hi + fp16 residual, linear),
// K (fp16 blocked), V (fp16 blocked).
// ---------------------------------------------------------------------------
__global__ __launch_bounds__(256, 2) void qkv_gemm_hmma() {
    extern __shared__ __align__(16) uint32_t smg[];
    const int mBase = blockIdx.y * 128;
    const int fBase = blockIdx.x * 128;
    float acc[4][4][4];
    const char* aBlocks = g_xb + (size_t)blockIdx.y * 64 * XBLK;
    const char* bBase = g_wqb + (size_t)(blockIdx.x >> 1) * 64 * WBLK
                      + (size_t)(blockIdx.x & 1) * 6144;
    hmma_mainloop256(smg, aBlocks, bBase, acc);

    const int tid = threadIdx.x;
    const int lane = tid & 31;
    const int wid = tid >> 5;
    const int wm = wid >> 2, wn = wid & 3;
    const int g = lane >> 2, cc = lane & 3;
    const int which = fBase >> 10;

    if (which == 2) {
#pragma unroll
        for (int i = 0; i < 4; ++i) {
            const int m0 = mBase + wm * 64 + i * 16 + g;
            const int b = m0 >> 11;
            const int n0 = m0 & (NN - 1);
#pragma unroll
            for (int j = 0; j < 4; ++j) {
                const int col = fBase + wn * 32 + j * 8 + cc * 2;
                const int h = (col >> 6) & (HH - 1);
                const int d0 = col & (DD - 1);
                char* blk = g_kvb + ((size_t)((b * HH + h) * 16) + (n0 >> 7)) * KVBLK + 36864;
#pragma unroll
                for (int r = 0; r < 4; ++r) {
                    const int dd = d0 + (r & 1);
                    const int nn = (n0 & 127) + (r >> 1) * 8;
                    *(__half*)(blk + dd * 272 + nn * 2) = __float2half_rn(acc[i][j][r]);
                }
            }
        }
    } else if (which == 1) {
#pragma unroll
        for (int i = 0; i < 4; ++i) {
            const int m0 = mBase + wm * 64 + i * 16 + g;
            const int b = m0 >> 11;
            const int n0 = m0 & (NN - 1);
#pragma unroll
            for (int j = 0; j < 4; ++j) {
                const int col = fBase + wn * 32 + j * 8 + cc * 2;
                const int h = (col >> 6) & (HH - 1);
                const int d0 = col & (DD - 1);
                char* blk = g_kvb + ((size_t)((b * HH + h) * 16) + (n0 >> 7)) * KVBLK;
                const int rr = n0 & 127;
                *(uint32_t*)(blk + rr * 144 + d0 * 2) = pack_h2(acc[i][j][0], acc[i][j][1]);
                *(uint32_t*)(blk + (rr + 8) * 144 + d0 * 2) = pack_h2(acc[i][j][2], acc[i][j][3]);
            }
        }
    } else {
        const float qs = 0.125f * 1.44269504f;
        uint32_t* ph_ = (uint32_t*)g_qh;
        uint32_t* pl_ = (uint32_t*)g_ql;
#pragma unroll
        for (int i = 0; i < 4; ++i) {
            const int m0 = mBase + wm * 64 + i * 16 + g;
            const int b = m0 >> 11;
            const int n0 = m0 & (NN - 1);
#pragma unroll
            for (int j = 0; j < 4; ++j) {
                const int col = fBase + wn * 32 + j * 8 + cc * 2;
                const int h = (col >> 6) & (HH - 1);
                const int d0 = col & (DD - 1);
                const size_t rowbase = (size_t)(b * HH + h) * NN;
                uint32_t hp0, lp0, hp1, lp1;
                split_pair_h(acc[i][j][0] * qs, acc[i][j][1] * qs, hp0, lp0);
                split_pair_h(acc[i][j][2] * qs, acc[i][j][3] * qs, hp1, lp1);
                ph_[(rowbase + n0) * 32 + (d0 >> 1)] = hp0;
                pl_[(rowbase + n0) * 32 + (d0 >> 1)] = lp0;
                ph_[(rowbase + n0 + 8) * 32 + (d0 >> 1)] = hp1;
                pl_[(rowbase + n0 + 8) * 32 + (d0 >> 1)] = lp1;
            }
        }
    }
}

// ---------------------------------------------------------------------------
// Output projection GEMM
// ---------------------------------------------------------------------------
__global__ __launch_bounds__(256, 2) void out_gemm_hmma(float* __restrict__ Cout) {
    extern __shared__ __align__(16) uint32_t smg[];
    const int mBase = blockIdx.y * 128;
    const int fBase = blockIdx.x * 128;
    float acc[4][4][4];
    const char* aBlocks = g_ab + (size_t)blockIdx.y * 64 * XBLK;
    const char* bBase = g_wob + (size_t)(blockIdx.x >> 1) * 64 * WBLK
                      + (size_t)(blockIdx.x & 1) * 6144;
    hmma_mainloop256(smg, aBlocks, bBase, acc);

    const int tid = threadIdx.x;
    const int lane = tid & 31;
    const int wid = tid >> 5;
    const int wm = wid >> 2, wn = wid & 3;
    const int g = lane >> 2, cc = lane & 3;

#pragma unroll
    for (int i = 0; i < 4; ++i) {
        const int m0 = mBase + wm * 64 + i * 16 + g;
#pragma unroll
        for (int j = 0; j < 4; ++j) {
            const int col = fBase + wn * 32 + j * 8 + cc * 2;
            float* d1 = Cout + (size_t)m0 * EE + col;
            float* d2 = Cout + (size_t)(m0 + 8) * EE + col;
            *(float2*)d1 = make_float2(acc[i][j][0], acc[i][j][1]);
            *(float2*)d2 = make_float2(acc[i][j][2], acc[i][j][3]);
        }
    }
}

// ---------------------------------------------------------------------------
// Flash attention (VERBATIM round 16, verified): 128 threads, q-tile 64.
// K fp16 double-buffered, V fp16 single-buffered. QK^T 2 fp16 passes; PV 1.
// Epilogue now emits fp16 hi/lo (for fp16 out-proj A operand).
// ---------------------------------------------------------------------------
#define KROW 36
#define VROW 68
#define KWORDS (128 * KROW)
#define VWORDS (64 * VROW)
#define KBYTES (KWORDS * 4)                 // 18432
#define VBYTES (VWORDS * 4)                 // 17408
#define ATTN_SMEM (2 * KBYTES + VBYTES + 64)  // 54336

__global__ __launch_bounds__(128) void attn_hmma() {
    extern __shared__ __align__(16) uint32_t smdyn[];

    const int bh = blockIdx.x;
    const int qt = blockIdx.y;
    const int tid = threadIdx.x;
    const int lane = tid & 31, wid = tid >> 5;
    const int g = lane >> 2, cc = lane & 3;

    const size_t qoff = (size_t)bh * NN * DD;
    const uint32_t* qhw = (const uint32_t*)g_qh + (qoff >> 1);
    const uint32_t* qlw = (const uint32_t*)g_ql + (qoff >> 1);
    const char* kvsrc = g_kvb + (size_t)bh * 16 * KVBLK;
    const uint32_t sb = smem_u32(smdyn);
    const uint32_t mb = sb + 2 * KBYTES + VBYTES;

    const int r0 = qt * 64 + wid * 16 + g;
    uint32_t qa[4][4], qb[4][4];
#pragma unroll
    for (int kc = 0; kc < 4; ++kc) {
        const int w0 = r0 * 32 + kc * 8 + cc;
        qa[kc][0] = qhw[w0];       qa[kc][1] = qhw[w0 + 256];
        qa[kc][2] = qhw[w0 + 4];   qa[kc][3] = qhw[w0 + 260];
        qb[kc][0] = qlw[w0];       qb[kc][1] = qlw[w0 + 256];
        qb[kc][2] = qlw[w0 + 4];   qb[kc][3] = qlw[w0 + 260];
    }

    float o[8][4];
#pragma unroll
    for (int j = 0; j < 8; ++j) { o[j][0] = o[j][1] = o[j][2] = o[j][3] = 0.f; }
    float m0 = -30000.f, m1 = -30000.f, l0 = 0.f, l1 = 0.f;

    if (tid == 0) { mbar_init(mb, 1); mbar_init(mb + 8, 1); mbar_init(mb + 16, 1); }
    fence_proxy();
    __syncthreads();

    auto issue_k = [&](int kt) {
        const int s = kt & 1;
        const uint32_t m = mb + 8 * s;
        const uint32_t d = sb + (uint32_t)s * KBYTES;
        const char* src = kvsrc + (size_t)kt * KVBLK;
        mbar_expect(m, KBYTES);
        bulk_g2s(d, src, KBYTES, m);
    };
    auto issue_v = [&](int kt) {
        const uint32_t m = mb + 16;
        const uint32_t d = sb + 2 * KBYTES;
        const char* src = kvsrc + (size_t)kt * KVBLK + 2 * KBYTES;
        mbar_expect(m, VBYTES);
        bulk_g2s(d, src, VBYTES, m);
    };

    if (tid == 0) { issue_k(0); issue_v(0); issue_k(1); }

    for (int ch = 0; ch < 16; ++ch) {
        const int s = ch & 1;
        mbar_wait(mb + 8 * s, (ch >> 1) & 1);

        const uint32_t* sK = smdyn + (size_t)s * (KBYTES / 4);
        const uint32_t* sVh = smdyn + 2 * (KBYTES / 4);

        float sc[16][4];
#pragma unroll
        for (int j = 0; j < 16; ++j) { sc[j][0] = sc[j][1] = sc[j][2] = sc[j][3] = 0.f; }
#pragma unroll
        for (int kc = 0; kc < 4; ++kc) {
            uint32_t kb[16][2];
#pragma unroll
            for (int j = 0; j < 16; ++j) {
                const int bw = (j * 8 + g) * KROW + kc * 8 + cc;
                kb[j][0] = sK[bw]; kb[j][1] = sK[bw + 4];
            }
#pragma unroll
            for (int j = 0; j < 16; ++j) mma16816f(sc[j], qa[kc], kb[j]);
#pragma unroll
            for (int j = 0; j < 16; ++j) mma16816f(sc[j], qb[kc], kb[j]);
        }

        float cm0 = -30000.f, cm1 = -30000.f;
#pragma unroll
        for (int j = 0; j < 16; ++j) {
            cm0 = fmaxf(cm0, fmaxf(sc[j][0], sc[j][1]));
            cm1 = fmaxf(cm1, fmaxf(sc[j][2], sc[j][3]));
        }
        cm0 = fmaxf(cm0, __shfl_xor_sync(0xffffffffu, cm0, 1));
        cm0 = fmaxf(cm0, __shfl_xor_sync(0xffffffffu, cm0, 2));
        cm1 = fmaxf(cm1, __shfl_xor_sync(0xffffffffu, cm1, 1));
        cm1 = fmaxf(cm1, __shfl_xor_sync(0xffffffffu, cm1, 2));
        const float mn0 = fmaxf(m0, cm0), mn1 = fmaxf(m1, cm1);
        const float a0 = fast_exp2(m0 - mn0), a1 = fast_exp2(m1 - mn1);
        m0 = mn0; m1 = mn1;
#pragma unroll
        for (int j = 0; j < 8; ++j) {
            o[j][0] *= a0; o[j][1] *= a0; o[j][2] *= a1; o[j][3] *= a1;
        }

        mbar_wait(mb + 16, ch & 1);

        float rs0 = 0.f, rs1 = 0.f;
#pragma unroll
        for (int kc2 = 0; kc2 < 8; ++kc2) {
            uint32_t pah[4];
#pragma unroll
            for (int t = 0; t < 2; ++t) {
                const int j = kc2 * 2 + t;
                float p0 = fast_exp2(sc[j][0] - m0);
                float p1 = fast_exp2(sc[j][1] - m0);
                float p2 = fast_exp2(sc[j][2] - m1);
                float p3 = fast_exp2(sc[j][3] - m1);
                rs0 += p0 + p1; rs1 += p2 + p3;
                pah[2 * t] = pack_h2(p0, p1);
                pah[2 * t + 1] = pack_h2(p2, p3);
            }
            uint32_t vbh[8][2];
#pragma unroll
            for (int j = 0; j < 8; ++j) {
                const int bw = (j * 8 + g) * VROW + kc2 * 8 + cc;
                vbh[j][0] = sVh[bw]; vbh[j][1] = sVh[bw + 4];
            }
#pragma unroll
            for (int j = 0; j < 8; ++j) mma16816f(o[j], pah, vbh[j]);
        }
        rs0 += __shfl_xor_sync(0xffffffffu, rs0, 1);
        rs0 += __shfl_xor_sync(0xffffffffu, rs0, 2);
        rs1 += __shfl_xor_sync(0xffffffffu, rs1, 1);
        rs1 += __shfl_xor_sync(0xffffffffu, rs1, 2);
        l0 = l0 * a0 + rs0;
        l1 = l1 * a1 + rs1;

        __syncthreads();
        if (tid == 0) {
            if (ch + 1 < 16) issue_v(ch + 1);
            if (ch + 2 < 16) issue_k(ch + 2);
        }
    }

    // Epilogue: fp16 hi/lo attention output -> g_ab blocked (fp16 A operand)
    const float i0 = 1.f / l0, i1 = 1.f / l1;
    const int b = bh >> 4, h = bh & (HH - 1);
    const int mg = b * NN + r0;
    const int mT = mg >> 7;
    const int rr = mg & 127;
#pragma unroll
    for (int j = 0; j < 8; ++j) {
        const int w = h * 32 + j * 4 + cc;
        uint32_t hp0, lp0, hp1, lp1;
        split_pair_h(o[j][0] * i0, o[j][1] * i0, hp0, lp0);
        split_pair_h(o[j][2] * i1, o[j][3] * i1, hp1, lp1);
        char* blk = g_ab + ((size_t)mT * 64 + (w >> 3)) * XBLK;
        const int off = (w & 7) * 4;
        *(uint32_t*)(blk + rr * 48 + off) = hp0;
        *(uint32_t*)(blk + 6144 + rr * 48 + off) = lp0;
        *(uint32_t*)(blk + (rr + 8) * 48 + off) = hp1;
        *(uint32_t*)(blk + 6144 + (rr + 8) * 48 + off) = lp1;
    }
}

// ---------------------------------------------------------------------------
extern "C" void kernel_launch(void* const* d_in, const int* in_sizes, int n_in,
                              void* d_out, int out_size)
{
    const float* x     = (const float*)d_in[0];
    const float* w_qkv = (const float*)d_in[1];
    const float* w_out = (const float*)d_in[2];
    float* out = (float*)d_out;

    cudaFuncSetAttribute(attn_hmma,
                         cudaFuncAttributeMaxDynamicSharedMemorySize, ATTN_SMEM);
    cudaFuncSetAttribute(qkv_gemm_hmma,
                         cudaFuncAttributeMaxDynamicSharedMemorySize, GEMM_SMEM);
    cudaFuncSetAttribute(out_gemm_hmma,
                         cudaFuncAttributeMaxDynamicSharedMemorySize, GEMM_SMEM);

    split_x_blocked<<<dim3(64, 64), 256>>>(x);
    split_wq_blocked<<<dim3(12, 64), 512>>>(w_qkv);
    split_wo_blocked<<<dim3(4, 64), 512>>>(w_out);

    {
        dim3 grid(FQKV / 128, MM / 128);   // (24, 64)
        qkv_gemm_hmma<<<grid, 256, GEMM_SMEM>>>();
    }
    {
        dim3 grid(BB * HH, NN / 64);       // (64, 32)
        attn_hmma<<<grid, 128, ATTN_SMEM>>>();
    }
    {
        dim3 grid(EE / 128, MM / 128);     // (8, 64)
        out_gemm_hmma<<<grid, 256, GEMM_SMEM>>>(out);
    }
}